// round 7
// baseline (speedup 1.0000x reference)
#include <cuda_runtime.h>
#include <cuda_bf16.h>
#include <math.h>
#include <stdint.h>

// Problem constants
#define B_SZ   4
#define T_SEQ  2048
#define DM     1024
#define NH     16
#define DH     64
#define WIN    256
#define M_ROWS (B_SZ * T_SEQ)        // 8192
#define N_QKV  (3 * DM)              // 3072

// GEMM tiling: 128x256 CTA tile, 8 warps of 64x64, 4-stage cp.async ring
#define BM 128
#define BN 256
#define BKK 32
#define NSTAGE 4
#define A_TILE_B (BM * 64)                    // 8192 B per split
#define B_TILE_B (BN * 64)                    // 16384 B per split
#define STG_B (2 * A_TILE_B + 2 * B_TILE_B)   // 49152 B
#define AH_OFF 0
#define AL_OFF A_TILE_B
#define BH_OFF (2 * A_TILE_B)
#define BL_OFF (2 * A_TILE_B + B_TILE_B)
#define GEMM_SMEM (NSTAGE * STG_B + 128)

// ---------------------------------------------------------------------------
// Device scratch (allocation-free per harness rules)
// ---------------------------------------------------------------------------
__device__ __align__(16) __nv_bfloat16 g_x_hi[M_ROWS * (size_t)DM];
__device__ __align__(16) __nv_bfloat16 g_x_lo[M_ROWS * (size_t)DM];
__device__ __align__(16) __nv_bfloat16 g_wqkvT_hi[N_QKV * (size_t)DM];   // [N][K]
__device__ __align__(16) __nv_bfloat16 g_wqkvT_lo[N_QKV * (size_t)DM];
__device__ __align__(16) __nv_bfloat16 g_woutT_hi[DM * (size_t)DM];      // [N][K]
__device__ __align__(16) __nv_bfloat16 g_woutT_lo[DM * (size_t)DM];
__device__ __align__(16) float g_qkv[M_ROWS * (size_t)N_QKV];            // [8192,3072]
__device__ __align__(16) __nv_bfloat16 g_att_hi[M_ROWS * (size_t)DM];
__device__ __align__(16) __nv_bfloat16 g_att_lo[M_ROWS * (size_t)DM];

// ---------------------------------------------------------------------------
// Helpers
// ---------------------------------------------------------------------------
__device__ __forceinline__ uint32_t smem_u32(const void* p) {
    return (uint32_t)__cvta_generic_to_shared(p);
}

#define CP16(saddr, gptr) \
    asm volatile("cp.async.cg.shared.global [%0], [%1], 16;" :: "r"(saddr), "l"(gptr))
#define CP_COMMIT() asm volatile("cp.async.commit_group;")
#define CP_WAIT(n)  asm volatile("cp.async.wait_group %0;" :: "n"(n))

#define LDM4(r, addr) \
    asm volatile("ldmatrix.sync.aligned.m8n8.x4.shared.b16 {%0,%1,%2,%3}, [%4];" \
        : "=r"((r)[0]), "=r"((r)[1]), "=r"((r)[2]), "=r"((r)[3]) : "r"(addr))

#define LDM4T(r, addr) \
    asm volatile("ldmatrix.sync.aligned.m8n8.x4.trans.shared.b16 {%0,%1,%2,%3}, [%4];" \
        : "=r"((r)[0]), "=r"((r)[1]), "=r"((r)[2]), "=r"((r)[3]) : "r"(addr))

#define MMA16816(d, a, b0, b1) \
    asm volatile("mma.sync.aligned.m16n8k16.row.col.f32.bf16.bf16.f32 " \
        "{%0,%1,%2,%3}, {%4,%5,%6,%7}, {%8,%9}, {%0,%1,%2,%3};" \
        : "+f"((d)[0]), "+f"((d)[1]), "+f"((d)[2]), "+f"((d)[3]) \
        : "r"((a)[0]), "r"((a)[1]), "r"((a)[2]), "r"((a)[3]), "r"(b0), "r"(b1))

// 64B-row swizzle: chunk' = chunk ^ ((row>>1)&3)
#define SWZ2(off) ((off) ^ ((((off) >> 7) & 3u) << 4))

__device__ __forceinline__ void split_f32(float f, __nv_bfloat16& hi, __nv_bfloat16& lo) {
    hi = __float2bfloat16_rn(f);
    lo = __float2bfloat16_rn(f - __bfloat162float(hi));
}

__device__ __forceinline__ void pack2_hilo(float x, float y, uint32_t& h, uint32_t& l) {
    __nv_bfloat162 hv, lv;
    split_f32(x, hv.x, lv.x);
    split_f32(y, hv.y, lv.y);
    h = *reinterpret_cast<uint32_t*>(&hv);
    l = *reinterpret_cast<uint32_t*>(&lv);
}

__device__ __forceinline__ void split_store4(float4 f, __nv_bfloat16* hp, __nv_bfloat16* lp) {
    __nv_bfloat162 h01, l01, h23, l23;
    split_f32(f.x, h01.x, l01.x);
    split_f32(f.y, h01.y, l01.y);
    split_f32(f.z, h23.x, l23.x);
    split_f32(f.w, h23.y, l23.y);
    *reinterpret_cast<__nv_bfloat162*>(hp)     = h01;
    *reinterpret_cast<__nv_bfloat162*>(hp + 2) = h23;
    *reinterpret_cast<__nv_bfloat162*>(lp)     = l01;
    *reinterpret_cast<__nv_bfloat162*>(lp + 2) = l23;
}

// ---------------------------------------------------------------------------
// prep kernels
// ---------------------------------------------------------------------------
__global__ void split_kernel(const float* __restrict__ src,
                             __nv_bfloat16* __restrict__ hi,
                             __nv_bfloat16* __restrict__ lo, int n4) {
    int i = blockIdx.x * blockDim.x + threadIdx.x;
    if (i >= n4) return;
    float4 f = reinterpret_cast<const float4*>(src)[i];
    split_store4(f, hi + i * 4, lo + i * 4);
}

__global__ void transpose_split_kernel(const float* __restrict__ src,
                                       __nv_bfloat16* __restrict__ hi,
                                       __nv_bfloat16* __restrict__ lo,
                                       int K, int N) {
    __shared__ float t[32][33];
    const int n0 = blockIdx.x * 32;
    const int k0 = blockIdx.y * 32;
    const int tx = threadIdx.x & 31;
    const int ty = threadIdx.x >> 5;
    #pragma unroll
    for (int i = 0; i < 32; i += 8)
        t[ty + i][tx] = src[(size_t)(k0 + ty + i) * N + n0 + tx];
    __syncthreads();
    #pragma unroll
    for (int i = 0; i < 32; i += 8) {
        float f = t[tx][ty + i];
        __nv_bfloat16 h, l;
        split_f32(f, h, l);
        size_t o = (size_t)(n0 + ty + i) * K + k0 + tx;
        hi[o] = h;
        lo[o] = l;
    }
}

// ---------------------------------------------------------------------------
// bf16x3 GEMM: C[M][N] fp32 = A @ B^T (Bt is [N][K]).
// 128x256 CTA tile, 8 warps (2M x 4N) of 64x64, 4-stage ring, one sync/K-tile.
// ---------------------------------------------------------------------------
__global__ __launch_bounds__(256, 1)
void gemm_bf16x3(const __nv_bfloat16* __restrict__ Ah, const __nv_bfloat16* __restrict__ Al,
                 const __nv_bfloat16* __restrict__ Bh, const __nv_bfloat16* __restrict__ Bl,
                 float* __restrict__ C, int M, int N, int K) {
    extern __shared__ char smraw[];
    const uint32_t sbase = (smem_u32(smraw) + 127) & ~127u;

    const int tid  = threadIdx.x;
    const int lane = tid & 31;
    const int warp = tid >> 5;
    const int wm   = warp & 1;        // 0..1 (64 rows each)
    const int wn   = warp >> 1;       // 0..3 (64 cols each)
    const int m0   = blockIdx.y * BM;
    const int n0   = blockIdx.x * BN;

    float acc[4][8][4];               // [mt][nt][frag]
    #pragma unroll
    for (int a = 0; a < 4; a++)
        #pragma unroll
        for (int b = 0; b < 8; b++)
            #pragma unroll
            for (int c = 0; c < 4; c++) acc[a][b][c] = 0.f;

    const int NK = K / BKK;

    // loader: A 512 chunks/split (2/thread), B 1024 chunks/split (4/thread)
    auto load_stage = [&](int buf, int kt) {
        const uint32_t s = sbase + buf * STG_B;
        const int kg = kt * BKK;
        #pragma unroll
        for (int i = 0; i < 2; ++i) {
            int cg  = tid + i * 256;
            int row = cg >> 2;
            int ck  = cg & 3;
            uint32_t so = SWZ2((uint32_t)(row * 64 + ck * 16));
            size_t ga = (size_t)(m0 + row) * K + kg + ck * 8;
            CP16(s + AH_OFF + so, Ah + ga);
            CP16(s + AL_OFF + so, Al + ga);
        }
        #pragma unroll
        for (int i = 0; i < 4; ++i) {
            int cg  = tid + i * 256;
            int row = cg >> 2;
            int ck  = cg & 3;
            uint32_t so = SWZ2((uint32_t)(row * 64 + ck * 16));
            size_t gb = (size_t)(n0 + row) * K + kg + ck * 8;
            CP16(s + BH_OFF + so, Bh + gb);
            CP16(s + BL_OFF + so, Bl + gb);
        }
    };

    load_stage(0, 0); CP_COMMIT();
    load_stage(1, 1); CP_COMMIT();
    load_stage(2, 2); CP_COMMIT();

    const int a_r  = wm * 64 + (lane & 15);
    const int a_c0 = lane >> 4;
    const int b_r  = wn * 64 + (lane & 7) + ((lane >> 4) << 3);
    const int b_c0 = (lane >> 3) & 1;

    for (int kt = 0; kt < NK; ++kt) {
        CP_WAIT(2);
        __syncthreads();
        if (kt + 3 < NK) load_stage((kt + 3) % NSTAGE, kt + 3);
        CP_COMMIT();   // always commit (possibly empty) -> uniform group count

        const uint32_t s = sbase + (kt % NSTAGE) * STG_B;
        #pragma unroll
        for (int ks = 0; ks < 2; ++ks) {
            uint32_t ah[4][4], al[4][4];
            #pragma unroll
            for (int mt = 0; mt < 4; ++mt) {
                uint32_t ro = SWZ2((uint32_t)((a_r + mt * 16) * 64 + (2 * ks + a_c0) * 16));
                LDM4(ah[mt], s + AH_OFF + ro);
                LDM4(al[mt], s + AL_OFF + ro);
            }
            #pragma unroll
            for (int np = 0; np < 4; ++np) {
                uint32_t ro = SWZ2((uint32_t)((b_r + np * 16) * 64 + (2 * ks + b_c0) * 16));
                uint32_t bh[4], bl[4];
                LDM4(bh, s + BH_OFF + ro);
                LDM4(bl, s + BL_OFF + ro);
                // 24 MMAs per np; same-acc reuse distance = 8
                #pragma unroll
                for (int mt = 0; mt < 4; ++mt) {
                    MMA16816(acc[mt][2 * np],     ah[mt], bh[0], bh[1]);
                    MMA16816(acc[mt][2 * np + 1], ah[mt], bh[2], bh[3]);
                }
                #pragma unroll
                for (int mt = 0; mt < 4; ++mt) {
                    MMA16816(acc[mt][2 * np],     ah[mt], bl[0], bl[1]);
                    MMA16816(acc[mt][2 * np + 1], ah[mt], bl[2], bl[3]);
                }
                #pragma unroll
                for (int mt = 0; mt < 4; ++mt) {
                    MMA16816(acc[mt][2 * np],     al[mt], bh[0], bh[1]);
                    MMA16816(acc[mt][2 * np + 1], al[mt], bh[2], bh[3]);
                }
            }
        }
    }

    #pragma unroll
    for (int mt = 0; mt < 4; ++mt) {
        #pragma unroll
        for (int nt = 0; nt < 8; ++nt) {
            int row = m0 + wm * 64 + mt * 16 + (lane >> 2);
            int col = n0 + wn * 64 + nt * 8 + (lane & 3) * 2;
            float2 v0 = make_float2(acc[mt][nt][0], acc[mt][nt][1]);
            float2 v1 = make_float2(acc[mt][nt][2], acc[mt][nt][3]);
            *reinterpret_cast<float2*>(&C[(size_t)row * N + col]) = v0;
            *reinterpret_cast<float2*>(&C[(size_t)(row + 8) * N + col]) = v1;
        }
    }
}

// ---------------------------------------------------------------------------
// Tensor-core sliding-window attention (bf16x3, mma.sync) — unchanged (at
// the HMMA roofline already).
// ---------------------------------------------------------------------------
#define AST 72

__global__ __launch_bounds__(128, 4)
void attn_tc_kernel(const float* __restrict__ qkv,
                    __nv_bfloat16* __restrict__ out_hi,
                    __nv_bfloat16* __restrict__ out_lo) {
    extern __shared__ __nv_bfloat16 smb[];
    const int REG = 64 * AST;
    __nv_bfloat16* Qh = smb;
    __nv_bfloat16* Ql = smb + REG;
    __nv_bfloat16* Kh = smb + 2 * REG;
    __nv_bfloat16* Kl = smb + 3 * REG;
    __nv_bfloat16* Vh = smb + 4 * REG;
    __nv_bfloat16* Vl = smb + 5 * REG;

    const int tid  = threadIdx.x;
    const int lane = tid & 31;
    const int warp = tid >> 5;
    const int q0 = blockIdx.x * 64;
    const int h  = blockIdx.y;
    const int b  = blockIdx.z;
    const size_t base = (size_t)b * T_SEQ * N_QKV;
    const int hoff = h * DH;

    const uint32_t sQh = smem_u32(Qh), sQl = smem_u32(Ql);
    const uint32_t sKh = smem_u32(Kh), sKl = smem_u32(Kl);
    const uint32_t sVh = smem_u32(Vh), sVl = smem_u32(Vl);

    #pragma unroll
    for (int it = 0; it < 8; it++) {
        int idx = it * 128 + tid;
        int r = idx >> 4, d4 = (idx & 15) << 2;
        float4 f = *reinterpret_cast<const float4*>(
            &qkv[base + (size_t)(q0 + r) * N_QKV + hoff + d4]);
        split_store4(f, &Qh[r * AST + d4], &Ql[r * AST + d4]);
    }

    float sa[8][4];
    float o[8][4];
    #pragma unroll
    for (int t = 0; t < 8; t++)
        #pragma unroll
        for (int j = 0; j < 4; j++) o[t][j] = 0.f;
    float m0 = -1e20f, m1 = -1e20f, l0 = 0.f, l1 = 0.f;

    const int lane2 = (lane & 3) * 2;
    const int qrow  = warp * 16 + (lane >> 2);
    const int qg0   = q0 + qrow;

    const uint32_t a_off = (uint32_t)((warp * 16 + (lane & 15)) * AST + ((lane >> 4) << 3)) * 2;
    const uint32_t b_off = (uint32_t)(((lane & 7) + ((lane >> 4) << 3)) * AST + (((lane >> 3) & 1) << 3)) * 2;
    const uint32_t v_off = (uint32_t)((lane & 15) * AST + ((lane >> 4) << 3)) * 2;

    for (int c = 0; c < 5; c++) {
        const int kb = q0 - WIN + c * 64;
        __syncthreads();
        #pragma unroll
        for (int it = 0; it < 8; it++) {
            int idx = it * 128 + tid;
            int r = idx >> 4, d4 = (idx & 15) << 2;
            int kg = kb + r;
            float4 kf = make_float4(0.f, 0.f, 0.f, 0.f);
            float4 vf = kf;
            if (kg >= 0) {
                const float* p = &qkv[base + (size_t)kg * N_QKV + hoff + d4];
                kf = *reinterpret_cast<const float4*>(p + DM);
                vf = *reinterpret_cast<const float4*>(p + 2 * DM);
            }
            split_store4(kf, &Kh[r * AST + d4], &Kl[r * AST + d4]);
            split_store4(vf, &Vh[r * AST + d4], &Vl[r * AST + d4]);
        }
        __syncthreads();

        #pragma unroll
        for (int t = 0; t < 8; t++)
            #pragma unroll
            for (int j = 0; j < 4; j++) sa[t][j] = 0.f;

        #pragma unroll
        for (int ks = 0; ks < 4; ks++) {
            uint32_t ah[4], al[4];
            LDM4(ah, sQh + a_off + ks * 32);
            LDM4(al, sQl + a_off + ks * 32);
            #pragma unroll
            for (int np = 0; np < 4; np++) {
                uint32_t bh[4], bl[4];
                uint32_t ko = b_off + (uint32_t)(np * 16 * AST) * 2 + ks * 32;
                LDM4(bh, sKh + ko);
                LDM4(bl, sKl + ko);
                MMA16816(sa[2 * np],     ah, bh[0], bh[1]);
                MMA16816(sa[2 * np + 1], ah, bh[2], bh[3]);
                MMA16816(sa[2 * np],     ah, bl[0], bl[1]);
                MMA16816(sa[2 * np + 1], ah, bl[2], bl[3]);
                MMA16816(sa[2 * np],     al, bh[0], bh[1]);
                MMA16816(sa[2 * np + 1], al, bh[2], bh[3]);
            }
        }

        float mx0 = -1e30f, mx1 = -1e30f;
        #pragma unroll
        for (int t = 0; t < 8; t++) {
            #pragma unroll
            for (int j = 0; j < 4; j++) {
                int col = t * 8 + lane2 + (j & 1);
                int kg  = kb + col;
                int qg  = qg0 + ((j >> 1) << 3);
                bool valid = (kg >= 0) && (kg <= qg) && (kg >= qg - WIN);
                float s = valid ? sa[t][j] * 0.125f : -1e30f;
                sa[t][j] = s;
                if (j < 2) mx0 = fmaxf(mx0, s); else mx1 = fmaxf(mx1, s);
            }
        }
        mx0 = fmaxf(mx0, __shfl_xor_sync(0xffffffffu, mx0, 1));
        mx0 = fmaxf(mx0, __shfl_xor_sync(0xffffffffu, mx0, 2));
        mx1 = fmaxf(mx1, __shfl_xor_sync(0xffffffffu, mx1, 1));
        mx1 = fmaxf(mx1, __shfl_xor_sync(0xffffffffu, mx1, 2));

        const float mn0 = fmaxf(m0, mx0);
        const float mn1 = fmaxf(m1, mx1);
        const float sc0 = __expf(m0 - mn0);
        const float sc1 = __expf(m1 - mn1);
        m0 = mn0; m1 = mn1;

        float ps0 = 0.f, ps1 = 0.f;
        #pragma unroll
        for (int t = 0; t < 8; t++) {
            float p0 = __expf(sa[t][0] - mn0);
            float p1 = __expf(sa[t][1] - mn0);
            float p2 = __expf(sa[t][2] - mn1);
            float p3 = __expf(sa[t][3] - mn1);
            sa[t][0] = p0; sa[t][1] = p1; sa[t][2] = p2; sa[t][3] = p3;
            ps0 += p0 + p1; ps1 += p2 + p3;
        }
        ps0 += __shfl_xor_sync(0xffffffffu, ps0, 1);
        ps0 += __shfl_xor_sync(0xffffffffu, ps0, 2);
        ps1 += __shfl_xor_sync(0xffffffffu, ps1, 1);
        ps1 += __shfl_xor_sync(0xffffffffu, ps1, 2);
        l0 = l0 * sc0 + ps0;
        l1 = l1 * sc1 + ps1;

        #pragma unroll
        for (int t = 0; t < 8; t++) {
            o[t][0] *= sc0; o[t][1] *= sc0;
            o[t][2] *= sc1; o[t][3] *= sc1;
        }

        #pragma unroll
        for (int s = 0; s < 4; s++) {
            uint32_t aph[4], apl[4];
            pack2_hilo(sa[2 * s][0],     sa[2 * s][1],     aph[0], apl[0]);
            pack2_hilo(sa[2 * s][2],     sa[2 * s][3],     aph[1], apl[1]);
            pack2_hilo(sa[2 * s + 1][0], sa[2 * s + 1][1], aph[2], apl[2]);
            pack2_hilo(sa[2 * s + 1][2], sa[2 * s + 1][3], aph[3], apl[3]);
            #pragma unroll
            for (int nd = 0; nd < 4; nd++) {
                uint32_t vh[4], vl[4];
                uint32_t vo = v_off + (uint32_t)(s * 16 * AST) * 2 + nd * 32;
                LDM4T(vh, sVh + vo);
                LDM4T(vl, sVl + vo);
                MMA16816(o[2 * nd],     aph, vh[0], vh[1]);
                MMA16816(o[2 * nd + 1], aph, vh[2], vh[3]);
                MMA16816(o[2 * nd],     aph, vl[0], vl[1]);
                MMA16816(o[2 * nd + 1], aph, vl[2], vl[3]);
                MMA16816(o[2 * nd],     apl, vh[0], vh[1]);
                MMA16816(o[2 * nd + 1], apl, vh[2], vh[3]);
            }
        }
    }

    const float il0 = 1.f / l0;
    const float il1 = 1.f / l1;
    const size_t row0 = (size_t)(b * T_SEQ + qg0);
    #pragma unroll
    for (int t = 0; t < 8; t++) {
        int col = hoff + t * 8 + lane2;
        uint32_t h0, lo0, h1, lo1;
        pack2_hilo(o[t][0] * il0, o[t][1] * il0, h0, lo0);
        pack2_hilo(o[t][2] * il1, o[t][3] * il1, h1, lo1);
        *reinterpret_cast<uint32_t*>(&out_hi[row0 * DM + col])       = h0;
        *reinterpret_cast<uint32_t*>(&out_lo[row0 * DM + col])       = lo0;
        *reinterpret_cast<uint32_t*>(&out_hi[(row0 + 8) * DM + col]) = h1;
        *reinterpret_cast<uint32_t*>(&out_lo[(row0 + 8) * DM + col]) = lo1;
    }
}

// ---------------------------------------------------------------------------
extern "C" void kernel_launch(void* const* d_in, const int* in_sizes, int n_in,
                              void* d_out, int out_size) {
    const float* x     = (const float*)d_in[0];
    const float* w_qkv = (const float*)d_in[1];
    const float* w_out = (const float*)d_in[2];
    float* out = (float*)d_out;

    __nv_bfloat16 *x_hi, *x_lo, *wq_hi, *wq_lo, *wo_hi, *wo_lo, *at_hi, *at_lo;
    float *qkv_buf;
    cudaGetSymbolAddress((void**)&x_hi,  g_x_hi);
    cudaGetSymbolAddress((void**)&x_lo,  g_x_lo);
    cudaGetSymbolAddress((void**)&wq_hi, g_wqkvT_hi);
    cudaGetSymbolAddress((void**)&wq_lo, g_wqkvT_lo);
    cudaGetSymbolAddress((void**)&wo_hi, g_woutT_hi);
    cudaGetSymbolAddress((void**)&wo_lo, g_woutT_lo);
    cudaGetSymbolAddress((void**)&at_hi, g_att_hi);
    cudaGetSymbolAddress((void**)&at_lo, g_att_lo);
    cudaGetSymbolAddress((void**)&qkv_buf, g_qkv);

    cudaFuncSetAttribute(gemm_bf16x3, cudaFuncAttributeMaxDynamicSharedMemorySize, GEMM_SMEM);
    const int ATTN_SMEM = 6 * 64 * AST * (int)sizeof(__nv_bfloat16);        // 55296
    cudaFuncSetAttribute(attn_tc_kernel, cudaFuncAttributeMaxDynamicSharedMemorySize, ATTN_SMEM);

    // 0) precision splits / weight transposes
    {
        int n4 = M_ROWS * DM / 4;
        split_kernel<<<(n4 + 255) / 256, 256>>>(x, x_hi, x_lo, n4);
        dim3 g1(N_QKV / 32, DM / 32);
        transpose_split_kernel<<<g1, 256>>>(w_qkv, wq_hi, wq_lo, DM, N_QKV);
        dim3 g2(DM / 32, DM / 32);
        transpose_split_kernel<<<g2, 256>>>(w_out, wo_hi, wo_lo, DM, DM);
    }
    // 1) QKV projection
    {
        dim3 grid(N_QKV / BN, M_ROWS / BM);
        gemm_bf16x3<<<grid, 256, GEMM_SMEM>>>(x_hi, x_lo, wq_hi, wq_lo,
                                              qkv_buf, M_ROWS, N_QKV, DM);
    }
    // 2) attention
    {
        dim3 grid(T_SEQ / 64, NH, B_SZ);
        attn_tc_kernel<<<grid, 128, ATTN_SMEM>>>(qkv_buf, at_hi, at_lo);
    }
    // 3) output projection
    {
        dim3 grid(DM / BN, M_ROWS / BM);
        gemm_bf16x3<<<grid, 256, GEMM_SMEM>>>(at_hi, at_lo, wo_hi, wo_lo,
                                              out, M_ROWS, DM, DM);
    }
}

// round 8
// speedup vs baseline: 1.1054x; 1.1054x over previous
#include <cuda_runtime.h>
#include <cuda_bf16.h>
#include <math.h>
#include <stdint.h>

// Problem constants
#define B_SZ   4
#define T_SEQ  2048
#define DM     1024
#define NH     16
#define DH     64
#define WIN    256
#define M_ROWS (B_SZ * T_SEQ)        // 8192
#define N_QKV  (3 * DM)              // 3072

// GEMM tiling (Round-6 proven config)
#define BM 128
#define BN 128
#define BKK 32
#define NSTAGE 3
#define TILE_B (BM * 64)              // 8192 B per split tile
#define STG_B  (4 * TILE_B)           // 32768 B
#define GEMM_SMEM (NSTAGE * STG_B + 128)

// ---------------------------------------------------------------------------
// Device scratch (allocation-free per harness rules)
// ---------------------------------------------------------------------------
__device__ __align__(16) __nv_bfloat16 g_x_hi[M_ROWS * (size_t)DM];
__device__ __align__(16) __nv_bfloat16 g_x_lo[M_ROWS * (size_t)DM];
__device__ __align__(16) __nv_bfloat16 g_wqkvT_hi[N_QKV * (size_t)DM];   // [N][K]
__device__ __align__(16) __nv_bfloat16 g_wqkvT_lo[N_QKV * (size_t)DM];
__device__ __align__(16) __nv_bfloat16 g_woutT_hi[DM * (size_t)DM];      // [N][K]
__device__ __align__(16) __nv_bfloat16 g_woutT_lo[DM * (size_t)DM];
__device__ __align__(16) __nv_bfloat16 g_qkv_hi[M_ROWS * (size_t)N_QKV]; // pre-split QKV
__device__ __align__(16) __nv_bfloat16 g_qkv_lo[M_ROWS * (size_t)N_QKV];
__device__ __align__(16) __nv_bfloat16 g_att_hi[M_ROWS * (size_t)DM];
__device__ __align__(16) __nv_bfloat16 g_att_lo[M_ROWS * (size_t)DM];

// ---------------------------------------------------------------------------
// Helpers
// ---------------------------------------------------------------------------
__device__ __forceinline__ uint32_t smem_u32(const void* p) {
    return (uint32_t)__cvta_generic_to_shared(p);
}

#define CP16(saddr, gptr) \
    asm volatile("cp.async.cg.shared.global [%0], [%1], 16;" :: "r"(saddr), "l"(gptr))
#define CP16Z(saddr, gptr, sz) \
    asm volatile("cp.async.cg.shared.global [%0], [%1], 16, %2;" \
        :: "r"(saddr), "l"(gptr), "r"(sz))
#define CP_COMMIT() asm volatile("cp.async.commit_group;")
#define CP_WAIT(n)  asm volatile("cp.async.wait_group %0;" :: "n"(n))

#define LDM4(r, addr) \
    asm volatile("ldmatrix.sync.aligned.m8n8.x4.shared.b16 {%0,%1,%2,%3}, [%4];" \
        : "=r"((r)[0]), "=r"((r)[1]), "=r"((r)[2]), "=r"((r)[3]) : "r"(addr))

#define LDM4T(r, addr) \
    asm volatile("ldmatrix.sync.aligned.m8n8.x4.trans.shared.b16 {%0,%1,%2,%3}, [%4];" \
        : "=r"((r)[0]), "=r"((r)[1]), "=r"((r)[2]), "=r"((r)[3]) : "r"(addr))

#define MMA16816(d, a, b0, b1) \
    asm volatile("mma.sync.aligned.m16n8k16.row.col.f32.bf16.bf16.f32 " \
        "{%0,%1,%2,%3}, {%4,%5,%6,%7}, {%8,%9}, {%0,%1,%2,%3};" \
        : "+f"((d)[0]), "+f"((d)[1]), "+f"((d)[2]), "+f"((d)[3]) \
        : "r"((a)[0]), "r"((a)[1]), "r"((a)[2]), "r"((a)[3]), "r"(b0), "r"(b1))

// 64B-row swizzle (GEMM tiles): chunk' = chunk ^ ((row>>1)&3)
#define SWZ2(off) ((off) ^ ((((off) >> 7) & 3u) << 4))
// 128B-row swizzle (attention tiles): chunk' = chunk ^ (row&7)
#define SWZ128(off) ((off) ^ ((((off) >> 7) & 7u) << 4))

__device__ __forceinline__ void split_f32(float f, __nv_bfloat16& hi, __nv_bfloat16& lo) {
    hi = __float2bfloat16_rn(f);
    lo = __float2bfloat16_rn(f - __bfloat162float(hi));
}

__device__ __forceinline__ void pack2_hilo(float x, float y, uint32_t& h, uint32_t& l) {
    __nv_bfloat162 hv, lv;
    split_f32(x, hv.x, lv.x);
    split_f32(y, hv.y, lv.y);
    h = *reinterpret_cast<uint32_t*>(&hv);
    l = *reinterpret_cast<uint32_t*>(&lv);
}

__device__ __forceinline__ void split_store4(float4 f, __nv_bfloat16* hp, __nv_bfloat16* lp) {
    __nv_bfloat162 h01, l01, h23, l23;
    split_f32(f.x, h01.x, l01.x);
    split_f32(f.y, h01.y, l01.y);
    split_f32(f.z, h23.x, l23.x);
    split_f32(f.w, h23.y, l23.y);
    *reinterpret_cast<__nv_bfloat162*>(hp)     = h01;
    *reinterpret_cast<__nv_bfloat162*>(hp + 2) = h23;
    *reinterpret_cast<__nv_bfloat162*>(lp)     = l01;
    *reinterpret_cast<__nv_bfloat162*>(lp + 2) = l23;
}

// ---------------------------------------------------------------------------
// prep kernels
// ---------------------------------------------------------------------------
__global__ void split_kernel(const float* __restrict__ src,
                             __nv_bfloat16* __restrict__ hi,
                             __nv_bfloat16* __restrict__ lo, int n4) {
    int i = blockIdx.x * blockDim.x + threadIdx.x;
    if (i >= n4) return;
    float4 f = reinterpret_cast<const float4*>(src)[i];
    split_store4(f, hi + i * 4, lo + i * 4);
}

__global__ void transpose_split_kernel(const float* __restrict__ src,
                                       __nv_bfloat16* __restrict__ hi,
                                       __nv_bfloat16* __restrict__ lo,
                                       int K, int N) {
    __shared__ float t[32][33];
    const int n0 = blockIdx.x * 32;
    const int k0 = blockIdx.y * 32;
    const int tx = threadIdx.x & 31;
    const int ty = threadIdx.x >> 5;
    #pragma unroll
    for (int i = 0; i < 32; i += 8)
        t[ty + i][tx] = src[(size_t)(k0 + ty + i) * N + n0 + tx];
    __syncthreads();
    #pragma unroll
    for (int i = 0; i < 32; i += 8) {
        float f = t[tx][ty + i];
        __nv_bfloat16 h, l;
        split_f32(f, h, l);
        size_t o = (size_t)(n0 + ty + i) * K + k0 + tx;
        hi[o] = h;
        lo[o] = l;
    }
}

// ---------------------------------------------------------------------------
// bf16x3 GEMM (Round-6 mainloop): C = A @ B^T (Bt is [N][K]).
// Epilogue: if Chi!=null write hi/lo bf16 splits, else fp32 C.
// ---------------------------------------------------------------------------
__global__ __launch_bounds__(256, 2)
void gemm_bf16x3(const __nv_bfloat16* __restrict__ Ah, const __nv_bfloat16* __restrict__ Al,
                 const __nv_bfloat16* __restrict__ Bh, const __nv_bfloat16* __restrict__ Bl,
                 float* __restrict__ C,
                 __nv_bfloat16* __restrict__ Chi, __nv_bfloat16* __restrict__ Clo,
                 int M, int N, int K) {
    extern __shared__ char smraw[];
    const uint32_t sbase = (smem_u32(smraw) + 127) & ~127u;

    const int tid  = threadIdx.x;
    const int lane = tid & 31;
    const int warp = tid >> 5;
    const int wm   = warp & 3;
    const int wn   = warp >> 2;
    const int m0   = blockIdx.y * BM;
    const int n0   = blockIdx.x * BN;

    float acc[2][8][4];
    #pragma unroll
    for (int a = 0; a < 2; a++)
        #pragma unroll
        for (int b = 0; b < 8; b++)
            #pragma unroll
            for (int c = 0; c < 4; c++) acc[a][b][c] = 0.f;

    const int NK = K / BKK;

    auto load_stage = [&](int buf, int kt) {
        const uint32_t s = sbase + buf * STG_B;
        const int kg = kt * BKK;
        #pragma unroll
        for (int i = 0; i < 2; ++i) {
            int cg  = tid + i * 256;
            int row = cg >> 2;
            int ck  = cg & 3;
            uint32_t so = SWZ2((uint32_t)(row * 64 + ck * 16));
            size_t ka = (size_t)kg + ck * 8;
            size_t ga = (size_t)(m0 + row) * K + ka;
            size_t gb = (size_t)(n0 + row) * K + ka;
            CP16(s + so,              Ah + ga);
            CP16(s + TILE_B + so,     Al + ga);
            CP16(s + 2 * TILE_B + so, Bh + gb);
            CP16(s + 3 * TILE_B + so, Bl + gb);
        }
    };

    load_stage(0, 0); CP_COMMIT();
    load_stage(1, 1); CP_COMMIT();

    const int a_r  = wm * 32 + (lane & 15);
    const int a_c0 = lane >> 4;
    const int b_r  = wn * 64 + (lane & 7) + ((lane >> 4) << 3);
    const int b_c0 = (lane >> 3) & 1;

    for (int kt = 0; kt < NK; ++kt) {
        if (kt + 1 < NK) { CP_WAIT(1); } else { CP_WAIT(0); }
        __syncthreads();
        if (kt + 2 < NK) {
            load_stage((kt + 2) % NSTAGE, kt + 2);
            CP_COMMIT();
        }

        const uint32_t s = sbase + (kt % NSTAGE) * STG_B;
        #pragma unroll
        for (int ks = 0; ks < 2; ++ks) {
            uint32_t ah[2][4], al[2][4];
            #pragma unroll
            for (int mt = 0; mt < 2; ++mt) {
                uint32_t ro = SWZ2((uint32_t)((a_r + mt * 16) * 64 + (2 * ks + a_c0) * 16));
                LDM4(ah[mt], s + ro);
                LDM4(al[mt], s + TILE_B + ro);
            }
            #pragma unroll
            for (int np = 0; np < 4; ++np) {
                uint32_t ro = SWZ2((uint32_t)((b_r + np * 16) * 64 + (2 * ks + b_c0) * 16));
                uint32_t bh[4], bl[4];
                LDM4(bh, s + 2 * TILE_B + ro);
                LDM4(bl, s + 3 * TILE_B + ro);
                MMA16816(acc[0][2 * np],     ah[0], bh[0], bh[1]);
                MMA16816(acc[1][2 * np],     ah[1], bh[0], bh[1]);
                MMA16816(acc[0][2 * np + 1], ah[0], bh[2], bh[3]);
                MMA16816(acc[1][2 * np + 1], ah[1], bh[2], bh[3]);
                MMA16816(acc[0][2 * np],     ah[0], bl[0], bl[1]);
                MMA16816(acc[1][2 * np],     ah[1], bl[0], bl[1]);
                MMA16816(acc[0][2 * np + 1], ah[0], bl[2], bl[3]);
                MMA16816(acc[1][2 * np + 1], ah[1], bl[2], bl[3]);
                MMA16816(acc[0][2 * np],     al[0], bh[0], bh[1]);
                MMA16816(acc[1][2 * np],     al[1], bh[0], bh[1]);
                MMA16816(acc[0][2 * np + 1], al[0], bh[2], bh[3]);
                MMA16816(acc[1][2 * np + 1], al[1], bh[2], bh[3]);
            }
        }
    }

    if (Chi != nullptr) {
        #pragma unroll
        for (int mt = 0; mt < 2; ++mt) {
            #pragma unroll
            for (int nt = 0; nt < 8; ++nt) {
                int row = m0 + wm * 32 + mt * 16 + (lane >> 2);
                int col = n0 + wn * 64 + nt * 8 + (lane & 3) * 2;
                uint32_t h0, l0, h1, l1;
                pack2_hilo(acc[mt][nt][0], acc[mt][nt][1], h0, l0);
                pack2_hilo(acc[mt][nt][2], acc[mt][nt][3], h1, l1);
                *reinterpret_cast<uint32_t*>(&Chi[(size_t)row * N + col])       = h0;
                *reinterpret_cast<uint32_t*>(&Clo[(size_t)row * N + col])       = l0;
                *reinterpret_cast<uint32_t*>(&Chi[(size_t)(row + 8) * N + col]) = h1;
                *reinterpret_cast<uint32_t*>(&Clo[(size_t)(row + 8) * N + col]) = l1;
            }
        }
    } else {
        #pragma unroll
        for (int mt = 0; mt < 2; ++mt) {
            #pragma unroll
            for (int nt = 0; nt < 8; ++nt) {
                int row = m0 + wm * 32 + mt * 16 + (lane >> 2);
                int col = n0 + wn * 64 + nt * 8 + (lane & 3) * 2;
                float2 v0 = make_float2(acc[mt][nt][0], acc[mt][nt][1]);
                float2 v1 = make_float2(acc[mt][nt][2], acc[mt][nt][3]);
                *reinterpret_cast<float2*>(&C[(size_t)row * N + col]) = v0;
                *reinterpret_cast<float2*>(&C[(size_t)(row + 8) * N + col]) = v1;
            }
        }
    }
}

// ---------------------------------------------------------------------------
// Attention: consumes pre-split hi/lo QKV via cp.async (zero-fill for kg<0).
// 128B smem rows, SW128 swizzle, no split math in-kernel.
// smem: Qh,Ql,Kh,Kl,Vh,Vl each 64x128B = 8 KB -> 48 KB total.
// ---------------------------------------------------------------------------
#define ATT_T 8192   // bytes per tensor-split tile

__global__ __launch_bounds__(128, 4)
void attn_tc_kernel(const __nv_bfloat16* __restrict__ qh,
                    const __nv_bfloat16* __restrict__ ql,
                    __nv_bfloat16* __restrict__ out_hi,
                    __nv_bfloat16* __restrict__ out_lo) {
    extern __shared__ char smb[];
    const uint32_t sb  = smem_u32(smb);
    const uint32_t sQH = sb,            sQL = sb + ATT_T;
    const uint32_t sKH = sb + 2 * ATT_T, sKL = sb + 3 * ATT_T;
    const uint32_t sVH = sb + 4 * ATT_T, sVL = sb + 5 * ATT_T;

    const int tid  = threadIdx.x;
    const int lane = tid & 31;
    const int warp = tid >> 5;
    const int q0 = blockIdx.x * 64;
    const int h  = blockIdx.y;
    const int b  = blockIdx.z;
    const int hoff = h * DH;
    const size_t rbase = (size_t)b * T_SEQ;

    // ---- load Q tile (512 16B-chunks per split) ----
    #pragma unroll
    for (int i = 0; i < 4; i++) {
        int cg  = tid + i * 128;
        int row = cg >> 3;
        int ck  = cg & 7;
        uint32_t so = SWZ128((uint32_t)(row * 128 + ck * 16));
        size_t g = (rbase + q0 + row) * N_QKV + hoff + ck * 8;
        CP16(sQH + so, qh + g);
        CP16(sQL + so, ql + g);
    }
    CP_COMMIT();

    float sa[8][4];
    float o[8][4];
    #pragma unroll
    for (int t = 0; t < 8; t++)
        #pragma unroll
        for (int j = 0; j < 4; j++) o[t][j] = 0.f;
    float m0 = -1e20f, m1 = -1e20f, l0 = 0.f, l1 = 0.f;

    const int lane2 = (lane & 3) * 2;
    const int qrow  = warp * 16 + (lane >> 2);
    const int qg0   = q0 + qrow;

    const int a_r = warp * 16 + (lane & 15);
    const int a_c = (lane >> 4) << 4;                    // byte offset 0/16
    const int b_r = (lane & 7) + ((lane >> 4) << 3);
    const int b_c = ((lane >> 3) & 1) << 4;
    const int v_r = lane & 15;
    const int v_c = (lane >> 4) << 4;

    for (int c = 0; c < 5; c++) {
        const int kb = q0 - WIN + c * 64;
        __syncthreads();   // previous chunk's K/V reads complete
        // ---- cp.async K/V chunk (zero-fill rows with kg<0) ----
        #pragma unroll
        for (int i = 0; i < 4; i++) {
            int cg  = tid + i * 128;
            int row = cg >> 3;
            int ck  = cg & 7;
            int kg  = kb + row;
            uint32_t sz = (kg >= 0) ? 16u : 0u;
            int kgc = kg >= 0 ? kg : 0;
            uint32_t so = SWZ128((uint32_t)(row * 128 + ck * 16));
            size_t gk = (rbase + kgc) * N_QKV + DM + hoff + ck * 8;
            size_t gv = gk + DM;
            CP16Z(sKH + so, qh + gk, sz);
            CP16Z(sKL + so, ql + gk, sz);
            CP16Z(sVH + so, qh + gv, sz);
            CP16Z(sVL + so, ql + gv, sz);
        }
        CP_COMMIT();
        CP_WAIT(0);
        __syncthreads();

        // ---- S = Q K^T (3-term) ----
        #pragma unroll
        for (int t = 0; t < 8; t++)
            #pragma unroll
            for (int j = 0; j < 4; j++) sa[t][j] = 0.f;

        #pragma unroll
        for (int ks = 0; ks < 4; ks++) {
            uint32_t ah[4], al[4];
            uint32_t ao = SWZ128((uint32_t)(a_r * 128 + ks * 32 + a_c));
            LDM4(ah, sQH + ao);
            LDM4(al, sQL + ao);
            #pragma unroll
            for (int np = 0; np < 4; np++) {
                uint32_t bo = SWZ128((uint32_t)((np * 16 + b_r) * 128 + ks * 32 + b_c));
                uint32_t bh[4], bl[4];
                LDM4(bh, sKH + bo);
                LDM4(bl, sKL + bo);
                MMA16816(sa[2 * np],     ah, bh[0], bh[1]);
                MMA16816(sa[2 * np + 1], ah, bh[2], bh[3]);
                MMA16816(sa[2 * np],     ah, bl[0], bl[1]);
                MMA16816(sa[2 * np + 1], ah, bl[2], bl[3]);
                MMA16816(sa[2 * np],     al, bh[0], bh[1]);
                MMA16816(sa[2 * np + 1], al, bh[2], bh[3]);
            }
        }

        // ---- mask + online softmax ----
        float mx0 = -1e30f, mx1 = -1e30f;
        #pragma unroll
        for (int t = 0; t < 8; t++) {
            #pragma unroll
            for (int j = 0; j < 4; j++) {
                int col = t * 8 + lane2 + (j & 1);
                int kg  = kb + col;
                int qg  = qg0 + ((j >> 1) << 3);
                bool valid = (kg >= 0) && (kg <= qg) && (kg >= qg - WIN);
                float s = valid ? sa[t][j] * 0.125f : -1e30f;
                sa[t][j] = s;
                if (j < 2) mx0 = fmaxf(mx0, s); else mx1 = fmaxf(mx1, s);
            }
        }
        mx0 = fmaxf(mx0, __shfl_xor_sync(0xffffffffu, mx0, 1));
        mx0 = fmaxf(mx0, __shfl_xor_sync(0xffffffffu, mx0, 2));
        mx1 = fmaxf(mx1, __shfl_xor_sync(0xffffffffu, mx1, 1));
        mx1 = fmaxf(mx1, __shfl_xor_sync(0xffffffffu, mx1, 2));

        const float mn0 = fmaxf(m0, mx0);
        const float mn1 = fmaxf(m1, mx1);
        const float sc0 = __expf(m0 - mn0);
        const float sc1 = __expf(m1 - mn1);
        m0 = mn0; m1 = mn1;

        float ps0 = 0.f, ps1 = 0.f;
        #pragma unroll
        for (int t = 0; t < 8; t++) {
            float p0 = __expf(sa[t][0] - mn0);
            float p1 = __expf(sa[t][1] - mn0);
            float p2 = __expf(sa[t][2] - mn1);
            float p3 = __expf(sa[t][3] - mn1);
            sa[t][0] = p0; sa[t][1] = p1; sa[t][2] = p2; sa[t][3] = p3;
            ps0 += p0 + p1; ps1 += p2 + p3;
        }
        ps0 += __shfl_xor_sync(0xffffffffu, ps0, 1);
        ps0 += __shfl_xor_sync(0xffffffffu, ps0, 2);
        ps1 += __shfl_xor_sync(0xffffffffu, ps1, 1);
        ps1 += __shfl_xor_sync(0xffffffffu, ps1, 2);
        l0 = l0 * sc0 + ps0;
        l1 = l1 * sc1 + ps1;

        #pragma unroll
        for (int t = 0; t < 8; t++) {
            o[t][0] *= sc0; o[t][1] *= sc0;
            o[t][2] *= sc1; o[t][3] *= sc1;
        }

        // ---- O += P V (3-term) ----
        #pragma unroll
        for (int s = 0; s < 4; s++) {
            uint32_t aph[4], apl[4];
            pack2_hilo(sa[2 * s][0],     sa[2 * s][1],     aph[0], apl[0]);
            pack2_hilo(sa[2 * s][2],     sa[2 * s][3],     aph[1], apl[1]);
            pack2_hilo(sa[2 * s + 1][0], sa[2 * s + 1][1], aph[2], apl[2]);
            pack2_hilo(sa[2 * s + 1][2], sa[2 * s + 1][3], aph[3], apl[3]);
            #pragma unroll
            for (int nd = 0; nd < 4; nd++) {
                uint32_t vo = SWZ128((uint32_t)((s * 16 + v_r) * 128 + nd * 32 + v_c));
                uint32_t vh[4], vl[4];
                LDM4T(vh, sVH + vo);
                LDM4T(vl, sVL + vo);
                MMA16816(o[2 * nd],     aph, vh[0], vh[1]);
                MMA16816(o[2 * nd + 1], aph, vh[2], vh[3]);
                MMA16816(o[2 * nd],     aph, vl[0], vl[1]);
                MMA16816(o[2 * nd + 1], aph, vl[2], vl[3]);
                MMA16816(o[2 * nd],     apl, vh[0], vh[1]);
                MMA16816(o[2 * nd + 1], apl, vh[2], vh[3]);
            }
        }
    }

    // ---- epilogue: normalize, split, store hi/lo ----
    const float il0 = 1.f / l0;
    const float il1 = 1.f / l1;
    const size_t row0 = rbase + qg0;
    #pragma unroll
    for (int t = 0; t < 8; t++) {
        int col = hoff + t * 8 + lane2;
        uint32_t h0, lo0, h1, lo1;
        pack2_hilo(o[t][0] * il0, o[t][1] * il0, h0, lo0);
        pack2_hilo(o[t][2] * il1, o[t][3] * il1, h1, lo1);
        *reinterpret_cast<uint32_t*>(&out_hi[row0 * DM + col])       = h0;
        *reinterpret_cast<uint32_t*>(&out_lo[row0 * DM + col])       = lo0;
        *reinterpret_cast<uint32_t*>(&out_hi[(row0 + 8) * DM + col]) = h1;
        *reinterpret_cast<uint32_t*>(&out_lo[(row0 + 8) * DM + col]) = lo1;
    }
}

// ---------------------------------------------------------------------------
extern "C" void kernel_launch(void* const* d_in, const int* in_sizes, int n_in,
                              void* d_out, int out_size) {
    const float* x     = (const float*)d_in[0];
    const float* w_qkv = (const float*)d_in[1];
    const float* w_out = (const float*)d_in[2];
    float* out = (float*)d_out;

    __nv_bfloat16 *x_hi, *x_lo, *wq_hi, *wq_lo, *wo_hi, *wo_lo;
    __nv_bfloat16 *qkv_hi, *qkv_lo, *at_hi, *at_lo;
    cudaGetSymbolAddress((void**)&x_hi,  g_x_hi);
    cudaGetSymbolAddress((void**)&x_lo,  g_x_lo);
    cudaGetSymbolAddress((void**)&wq_hi, g_wqkvT_hi);
    cudaGetSymbolAddress((void**)&wq_lo, g_wqkvT_lo);
    cudaGetSymbolAddress((void**)&wo_hi, g_woutT_hi);
    cudaGetSymbolAddress((void**)&wo_lo, g_woutT_lo);
    cudaGetSymbolAddress((void**)&qkv_hi, g_qkv_hi);
    cudaGetSymbolAddress((void**)&qkv_lo, g_qkv_lo);
    cudaGetSymbolAddress((void**)&at_hi, g_att_hi);
    cudaGetSymbolAddress((void**)&at_lo, g_att_lo);

    cudaFuncSetAttribute(gemm_bf16x3, cudaFuncAttributeMaxDynamicSharedMemorySize, GEMM_SMEM);
    const int ATTN_SMEM = 6 * ATT_T;   // 49152
    cudaFuncSetAttribute(attn_tc_kernel, cudaFuncAttributeMaxDynamicSharedMemorySize, ATTN_SMEM);

    // 0) precision splits / weight transposes
    {
        int n4 = M_ROWS * DM / 4;
        split_kernel<<<(n4 + 255) / 256, 256>>>(x, x_hi, x_lo, n4);
        dim3 g1(N_QKV / 32, DM / 32);
        transpose_split_kernel<<<g1, 256>>>(w_qkv, wq_hi, wq_lo, DM, N_QKV);
        dim3 g2(DM / 32, DM / 32);
        transpose_split_kernel<<<g2, 256>>>(w_out, wo_hi, wo_lo, DM, DM);
    }
    // 1) QKV projection -> pre-split hi/lo outputs
    {
        dim3 grid(N_QKV / BN, M_ROWS / BM);
        gemm_bf16x3<<<grid, 256, GEMM_SMEM>>>(x_hi, x_lo, wq_hi, wq_lo,
                                              nullptr, qkv_hi, qkv_lo,
                                              M_ROWS, N_QKV, DM);
    }
    // 2) attention (cp.async pre-split consumption)
    {
        dim3 grid(T_SEQ / 64, NH, B_SZ);
        attn_tc_kernel<<<grid, 128, ATTN_SMEM>>>(qkv_hi, qkv_lo, at_hi, at_lo);
    }
    // 3) output projection -> fp32
    {
        dim3 grid(DM / BN, M_ROWS / BM);
        gemm_bf16x3<<<grid, 256, GEMM_SMEM>>>(at_hi, at_lo, wo_hi, wo_lo,
                                              out, nullptr, nullptr,
                                              M_ROWS, DM, DM);
    }
}

// round 9
// speedup vs baseline: 1.3135x; 1.1883x over previous
#include <cuda_runtime.h>
#include <cuda_bf16.h>
#include <cuda_fp16.h>
#include <math.h>
#include <stdint.h>

// Problem constants
#define B_SZ   4
#define T_SEQ  2048
#define DM     1024
#define NH     16
#define DH     64
#define WIN    256
#define M_ROWS (B_SZ * T_SEQ)        // 8192
#define N_QKV  (3 * DM)              // 3072

// bf16x3 GEMM tiling (GEMM2, Round-6 proven config)
#define BM 128
#define BN 128
#define BKK 32
#define NSTAGE 3
#define TILE_B (BM * 64)              // 8192 B per split tile
#define STG_B  (4 * TILE_B)           // 32768 B
#define GEMM_SMEM (NSTAGE * STG_B + 128)

// fp16x2 GEMM tiling (GEMM1): stage = Ah + Al + B = 3 tiles, 4-stage ring
#define NSTAGE2 4
#define STG2_B (3 * TILE_B)           // 24576 B
#define GEMM2_SMEM (NSTAGE2 * STG2_B + 128)

// ---------------------------------------------------------------------------
// Device scratch (allocation-free per harness rules)
// ---------------------------------------------------------------------------
__device__ __align__(16) __half g_x16_hi[M_ROWS * (size_t)DM];
__device__ __align__(16) __half g_x16_lo[M_ROWS * (size_t)DM];
__device__ __align__(16) __half g_wqkvT16[N_QKV * (size_t)DM];           // [N][K]
__device__ __align__(16) __nv_bfloat16 g_woutT_hi[DM * (size_t)DM];      // [N][K]
__device__ __align__(16) __nv_bfloat16 g_woutT_lo[DM * (size_t)DM];
__device__ __align__(16) __nv_bfloat16 g_qkv_hi[M_ROWS * (size_t)N_QKV]; // pre-split QKV
__device__ __align__(16) __nv_bfloat16 g_qkv_lo[M_ROWS * (size_t)N_QKV];
__device__ __align__(16) __nv_bfloat16 g_att_hi[M_ROWS * (size_t)DM];
__device__ __align__(16) __nv_bfloat16 g_att_lo[M_ROWS * (size_t)DM];

// ---------------------------------------------------------------------------
// Helpers
// ---------------------------------------------------------------------------
__device__ __forceinline__ uint32_t smem_u32(const void* p) {
    return (uint32_t)__cvta_generic_to_shared(p);
}

#define CP16(saddr, gptr) \
    asm volatile("cp.async.cg.shared.global [%0], [%1], 16;" :: "r"(saddr), "l"(gptr))
#define CP16Z(saddr, gptr, sz) \
    asm volatile("cp.async.cg.shared.global [%0], [%1], 16, %2;" \
        :: "r"(saddr), "l"(gptr), "r"(sz))
#define CP_COMMIT() asm volatile("cp.async.commit_group;")
#define CP_WAIT(n)  asm volatile("cp.async.wait_group %0;" :: "n"(n))

#define LDM4(r, addr) \
    asm volatile("ldmatrix.sync.aligned.m8n8.x4.shared.b16 {%0,%1,%2,%3}, [%4];" \
        : "=r"((r)[0]), "=r"((r)[1]), "=r"((r)[2]), "=r"((r)[3]) : "r"(addr))

#define LDM4T(r, addr) \
    asm volatile("ldmatrix.sync.aligned.m8n8.x4.trans.shared.b16 {%0,%1,%2,%3}, [%4];" \
        : "=r"((r)[0]), "=r"((r)[1]), "=r"((r)[2]), "=r"((r)[3]) : "r"(addr))

#define MMA16816(d, a, b0, b1) \
    asm volatile("mma.sync.aligned.m16n8k16.row.col.f32.bf16.bf16.f32 " \
        "{%0,%1,%2,%3}, {%4,%5,%6,%7}, {%8,%9}, {%0,%1,%2,%3};" \
        : "+f"((d)[0]), "+f"((d)[1]), "+f"((d)[2]), "+f"((d)[3]) \
        : "r"((a)[0]), "r"((a)[1]), "r"((a)[2]), "r"((a)[3]), "r"(b0), "r"(b1))

#define MMA16816H(d, a, b0, b1) \
    asm volatile("mma.sync.aligned.m16n8k16.row.col.f32.f16.f16.f32 " \
        "{%0,%1,%2,%3}, {%4,%5,%6,%7}, {%8,%9}, {%0,%1,%2,%3};" \
        : "+f"((d)[0]), "+f"((d)[1]), "+f"((d)[2]), "+f"((d)[3]) \
        : "r"((a)[0]), "r"((a)[1]), "r"((a)[2]), "r"((a)[3]), "r"(b0), "r"(b1))

// 64B-row swizzle (GEMM tiles)
#define SWZ2(off) ((off) ^ ((((off) >> 7) & 3u) << 4))
// 128B-row swizzle (attention tiles)
#define SWZ128(off) ((off) ^ ((((off) >> 7) & 7u) << 4))

__device__ __forceinline__ void split_f32(float f, __nv_bfloat16& hi, __nv_bfloat16& lo) {
    hi = __float2bfloat16_rn(f);
    lo = __float2bfloat16_rn(f - __bfloat162float(hi));
}
__device__ __forceinline__ void split_f32h(float f, __half& hi, __half& lo) {
    hi = __float2half_rn(f);
    lo = __float2half_rn(f - __half2float(hi));
}

__device__ __forceinline__ void pack2_hilo(float x, float y, uint32_t& h, uint32_t& l) {
    __nv_bfloat162 hv, lv;
    split_f32(x, hv.x, lv.x);
    split_f32(y, hv.y, lv.y);
    h = *reinterpret_cast<uint32_t*>(&hv);
    l = *reinterpret_cast<uint32_t*>(&lv);
}

// ---------------------------------------------------------------------------
// prep kernels
// ---------------------------------------------------------------------------
__global__ void split_f16_kernel(const float* __restrict__ src,
                                 __half* __restrict__ hi,
                                 __half* __restrict__ lo, int n4) {
    int i = blockIdx.x * blockDim.x + threadIdx.x;
    if (i >= n4) return;
    float4 f = reinterpret_cast<const float4*>(src)[i];
    __half2 h01, l01, h23, l23;
    split_f32h(f.x, h01.x, l01.x);
    split_f32h(f.y, h01.y, l01.y);
    split_f32h(f.z, h23.x, l23.x);
    split_f32h(f.w, h23.y, l23.y);
    __half2* hp = reinterpret_cast<__half2*>(hi) + i * 2;
    __half2* lp = reinterpret_cast<__half2*>(lo) + i * 2;
    hp[0] = h01; hp[1] = h23;
    lp[0] = l01; lp[1] = l23;
}

// transpose + round to single fp16: src [K][N] fp32 -> dst [N][K] half
__global__ void transpose_f16_kernel(const float* __restrict__ src,
                                     __half* __restrict__ dst, int K, int N) {
    __shared__ float t[32][33];
    const int n0 = blockIdx.x * 32;
    const int k0 = blockIdx.y * 32;
    const int tx = threadIdx.x & 31;
    const int ty = threadIdx.x >> 5;
    #pragma unroll
    for (int i = 0; i < 32; i += 8)
        t[ty + i][tx] = src[(size_t)(k0 + ty + i) * N + n0 + tx];
    __syncthreads();
    #pragma unroll
    for (int i = 0; i < 32; i += 8)
        dst[(size_t)(n0 + ty + i) * K + k0 + tx] = __float2half_rn(t[tx][ty + i]);
}

// transpose + bf16 hi/lo split (w_out)
__global__ void transpose_split_kernel(const float* __restrict__ src,
                                       __nv_bfloat16* __restrict__ hi,
                                       __nv_bfloat16* __restrict__ lo,
                                       int K, int N) {
    __shared__ float t[32][33];
    const int n0 = blockIdx.x * 32;
    const int k0 = blockIdx.y * 32;
    const int tx = threadIdx.x & 31;
    const int ty = threadIdx.x >> 5;
    #pragma unroll
    for (int i = 0; i < 32; i += 8)
        t[ty + i][tx] = src[(size_t)(k0 + ty + i) * N + n0 + tx];
    __syncthreads();
    #pragma unroll
    for (int i = 0; i < 32; i += 8) {
        float f = t[tx][ty + i];
        __nv_bfloat16 h, l;
        split_f32(f, h, l);
        size_t o = (size_t)(n0 + ty + i) * K + k0 + tx;
        hi[o] = h;
        lo[o] = l;
    }
}

// ---------------------------------------------------------------------------
// fp16x2 GEMM (GEMM1): C = (Ah+Al) @ B^T, A split fp16, B single fp16.
// 128x128x32 tiles, 8 warps, 4-stage ring, one sync/K-tile.
// Epilogue writes bf16 hi/lo splits of the fp32 accumulator.
// ---------------------------------------------------------------------------
__global__ __launch_bounds__(256, 2)
void gemm_f16x2(const __half* __restrict__ Ah, const __half* __restrict__ Al,
                const __half* __restrict__ Bq,
                __nv_bfloat16* __restrict__ Chi, __nv_bfloat16* __restrict__ Clo,
                int M, int N, int K) {
    extern __shared__ char smraw[];
    const uint32_t sbase = (smem_u32(smraw) + 127) & ~127u;

    const int tid  = threadIdx.x;
    const int lane = tid & 31;
    const int warp = tid >> 5;
    const int wm   = warp & 3;
    const int wn   = warp >> 2;
    const int m0   = blockIdx.y * BM;
    const int n0   = blockIdx.x * BN;

    float acc[2][8][4];
    #pragma unroll
    for (int a = 0; a < 2; a++)
        #pragma unroll
        for (int b = 0; b < 8; b++)
            #pragma unroll
            for (int c = 0; c < 4; c++) acc[a][b][c] = 0.f;

    const int NK = K / BKK;

    auto load_stage = [&](int buf, int kt) {
        const uint32_t s = sbase + buf * STG2_B;
        const int kg = kt * BKK;
        #pragma unroll
        for (int i = 0; i < 2; ++i) {
            int cg  = tid + i * 256;
            int row = cg >> 2;
            int ck  = cg & 3;
            uint32_t so = SWZ2((uint32_t)(row * 64 + ck * 16));
            size_t ka = (size_t)kg + ck * 8;
            size_t ga = (size_t)(m0 + row) * K + ka;
            size_t gb = (size_t)(n0 + row) * K + ka;
            CP16(s + so,              Ah + ga);
            CP16(s + TILE_B + so,     Al + ga);
            CP16(s + 2 * TILE_B + so, Bq + gb);
        }
    };

    load_stage(0, 0); CP_COMMIT();
    load_stage(1, 1); CP_COMMIT();
    load_stage(2, 2); CP_COMMIT();

    const int a_r  = wm * 32 + (lane & 15);
    const int a_c0 = lane >> 4;
    const int b_r  = wn * 64 + (lane & 7) + ((lane >> 4) << 3);
    const int b_c0 = (lane >> 3) & 1;

    for (int kt = 0; kt < NK; ++kt) {
        if (kt + 1 < NK) { CP_WAIT(2); } else { CP_WAIT(0); }
        __syncthreads();
        if (kt + 3 < NK) {
            load_stage((kt + 3) % NSTAGE2, kt + 3);
            CP_COMMIT();
        }

        const uint32_t s = sbase + (kt % NSTAGE2) * STG2_B;
        #pragma unroll
        for (int ks = 0; ks < 2; ++ks) {
            uint32_t ah[2][4], al[2][4];
            #pragma unroll
            for (int mt = 0; mt < 2; ++mt) {
                uint32_t ro = SWZ2((uint32_t)((a_r + mt * 16) * 64 + (2 * ks + a_c0) * 16));
                LDM4(ah[mt], s + ro);
                LDM4(al[mt], s + TILE_B + ro);
            }
            #pragma unroll
            for (int np = 0; np < 4; ++np) {
                uint32_t ro = SWZ2((uint32_t)((b_r + np * 16) * 64 + (2 * ks + b_c0) * 16));
                uint32_t bq[4];
                LDM4(bq, s + 2 * TILE_B + ro);
                // 8 MMAs per np; same-acc reuse distance = 4
                MMA16816H(acc[0][2 * np],     ah[0], bq[0], bq[1]);
                MMA16816H(acc[1][2 * np],     ah[1], bq[0], bq[1]);
                MMA16816H(acc[0][2 * np + 1], ah[0], bq[2], bq[3]);
                MMA16816H(acc[1][2 * np + 1], ah[1], bq[2], bq[3]);
                MMA16816H(acc[0][2 * np],     al[0], bq[0], bq[1]);
                MMA16816H(acc[1][2 * np],     al[1], bq[0], bq[1]);
                MMA16816H(acc[0][2 * np + 1], al[0], bq[2], bq[3]);
                MMA16816H(acc[1][2 * np + 1], al[1], bq[2], bq[3]);
            }
        }
    }

    #pragma unroll
    for (int mt = 0; mt < 2; ++mt) {
        #pragma unroll
        for (int nt = 0; nt < 8; ++nt) {
            int row = m0 + wm * 32 + mt * 16 + (lane >> 2);
            int col = n0 + wn * 64 + nt * 8 + (lane & 3) * 2;
            uint32_t h0, l0, h1, l1;
            pack2_hilo(acc[mt][nt][0], acc[mt][nt][1], h0, l0);
            pack2_hilo(acc[mt][nt][2], acc[mt][nt][3], h1, l1);
            *reinterpret_cast<uint32_t*>(&Chi[(size_t)row * N + col])       = h0;
            *reinterpret_cast<uint32_t*>(&Clo[(size_t)row * N + col])       = l0;
            *reinterpret_cast<uint32_t*>(&Chi[(size_t)(row + 8) * N + col]) = h1;
            *reinterpret_cast<uint32_t*>(&Clo[(size_t)(row + 8) * N + col]) = l1;
        }
    }
}

// ---------------------------------------------------------------------------
// bf16x3 GEMM (GEMM2, Round-6 mainloop): C fp32 = A @ B^T.
// ---------------------------------------------------------------------------
__global__ __launch_bounds__(256, 2)
void gemm_bf16x3(const __nv_bfloat16* __restrict__ Ah, const __nv_bfloat16* __restrict__ Al,
                 const __nv_bfloat16* __restrict__ Bh, const __nv_bfloat16* __restrict__ Bl,
                 float* __restrict__ C, int M, int N, int K) {
    extern __shared__ char smraw[];
    const uint32_t sbase = (smem_u32(smraw) + 127) & ~127u;

    const int tid  = threadIdx.x;
    const int lane = tid & 31;
    const int warp = tid >> 5;
    const int wm   = warp & 3;
    const int wn   = warp >> 2;
    const int m0   = blockIdx.y * BM;
    const int n0   = blockIdx.x * BN;

    float acc[2][8][4];
    #pragma unroll
    for (int a = 0; a < 2; a++)
        #pragma unroll
        for (int b = 0; b < 8; b++)
            #pragma unroll
            for (int c = 0; c < 4; c++) acc[a][b][c] = 0.f;

    const int NK = K / BKK;

    auto load_stage = [&](int buf, int kt) {
        const uint32_t s = sbase + buf * STG_B;
        const int kg = kt * BKK;
        #pragma unroll
        for (int i = 0; i < 2; ++i) {
            int cg  = tid + i * 256;
            int row = cg >> 2;
            int ck  = cg & 3;
            uint32_t so = SWZ2((uint32_t)(row * 64 + ck * 16));
            size_t ka = (size_t)kg + ck * 8;
            size_t ga = (size_t)(m0 + row) * K + ka;
            size_t gb = (size_t)(n0 + row) * K + ka;
            CP16(s + so,              Ah + ga);
            CP16(s + TILE_B + so,     Al + ga);
            CP16(s + 2 * TILE_B + so, Bh + gb);
            CP16(s + 3 * TILE_B + so, Bl + gb);
        }
    };

    load_stage(0, 0); CP_COMMIT();
    load_stage(1, 1); CP_COMMIT();

    const int a_r  = wm * 32 + (lane & 15);
    const int a_c0 = lane >> 4;
    const int b_r  = wn * 64 + (lane & 7) + ((lane >> 4) << 3);
    const int b_c0 = (lane >> 3) & 1;

    for (int kt = 0; kt < NK; ++kt) {
        if (kt + 1 < NK) { CP_WAIT(1); } else { CP_WAIT(0); }
        __syncthreads();
        if (kt + 2 < NK) {
            load_stage((kt + 2) % NSTAGE, kt + 2);
            CP_COMMIT();
        }

        const uint32_t s = sbase + (kt % NSTAGE) * STG_B;
        #pragma unroll
        for (int ks = 0; ks < 2; ++ks) {
            uint32_t ah[2][4], al[2][4];
            #pragma unroll
            for (int mt = 0; mt < 2; ++mt) {
                uint32_t ro = SWZ2((uint32_t)((a_r + mt * 16) * 64 + (2 * ks + a_c0) * 16));
                LDM4(ah[mt], s + ro);
                LDM4(al[mt], s + TILE_B + ro);
            }
            #pragma unroll
            for (int np = 0; np < 4; ++np) {
                uint32_t ro = SWZ2((uint32_t)((b_r + np * 16) * 64 + (2 * ks + b_c0) * 16));
                uint32_t bh[4], bl[4];
                LDM4(bh, s + 2 * TILE_B + ro);
                LDM4(bl, s + 3 * TILE_B + ro);
                MMA16816(acc[0][2 * np],     ah[0], bh[0], bh[1]);
                MMA16816(acc[1][2 * np],     ah[1], bh[0], bh[1]);
                MMA16816(acc[0][2 * np + 1], ah[0], bh[2], bh[3]);
                MMA16816(acc[1][2 * np + 1], ah[1], bh[2], bh[3]);
                MMA16816(acc[0][2 * np],     ah[0], bl[0], bl[1]);
                MMA16816(acc[1][2 * np],     ah[1], bl[0], bl[1]);
                MMA16816(acc[0][2 * np + 1], ah[0], bl[2], bl[3]);
                MMA16816(acc[1][2 * np + 1], ah[1], bl[2], bl[3]);
                MMA16816(acc[0][2 * np],     al[0], bh[0], bh[1]);
                MMA16816(acc[1][2 * np],     al[1], bh[0], bh[1]);
                MMA16816(acc[0][2 * np + 1], al[0], bh[2], bh[3]);
                MMA16816(acc[1][2 * np + 1], al[1], bh[2], bh[3]);
            }
        }
    }

    #pragma unroll
    for (int mt = 0; mt < 2; ++mt) {
        #pragma unroll
        for (int nt = 0; nt < 8; ++nt) {
            int row = m0 + wm * 32 + mt * 16 + (lane >> 2);
            int col = n0 + wn * 64 + nt * 8 + (lane & 3) * 2;
            float2 v0 = make_float2(acc[mt][nt][0], acc[mt][nt][1]);
            float2 v1 = make_float2(acc[mt][nt][2], acc[mt][nt][3]);
            *reinterpret_cast<float2*>(&C[(size_t)row * N + col]) = v0;
            *reinterpret_cast<float2*>(&C[(size_t)(row + 8) * N + col]) = v1;
        }
    }
}

// ---------------------------------------------------------------------------
// Attention (Round-8 version, unchanged): pre-split hi/lo QKV via cp.async.
// ---------------------------------------------------------------------------
#define ATT_T 8192

__global__ __launch_bounds__(128, 4)
void attn_tc_kernel(const __nv_bfloat16* __restrict__ qh,
                    const __nv_bfloat16* __restrict__ ql,
                    __nv_bfloat16* __restrict__ out_hi,
                    __nv_bfloat16* __restrict__ out_lo) {
    extern __shared__ char smb[];
    const uint32_t sb  = smem_u32(smb);
    const uint32_t sQH = sb,            sQL = sb + ATT_T;
    const uint32_t sKH = sb + 2 * ATT_T, sKL = sb + 3 * ATT_T;
    const uint32_t sVH = sb + 4 * ATT_T, sVL = sb + 5 * ATT_T;

    const int tid  = threadIdx.x;
    const int lane = tid & 31;
    const int warp = tid >> 5;
    const int q0 = blockIdx.x * 64;
    const int h  = blockIdx.y;
    const int b  = blockIdx.z;
    const int hoff = h * DH;
    const size_t rbase = (size_t)b * T_SEQ;

    #pragma unroll
    for (int i = 0; i < 4; i++) {
        int cg  = tid + i * 128;
        int row = cg >> 3;
        int ck  = cg & 7;
        uint32_t so = SWZ128((uint32_t)(row * 128 + ck * 16));
        size_t g = (rbase + q0 + row) * N_QKV + hoff + ck * 8;
        CP16(sQH + so, qh + g);
        CP16(sQL + so, ql + g);
    }
    CP_COMMIT();

    float sa[8][4];
    float o[8][4];
    #pragma unroll
    for (int t = 0; t < 8; t++)
        #pragma unroll
        for (int j = 0; j < 4; j++) o[t][j] = 0.f;
    float m0 = -1e20f, m1 = -1e20f, l0 = 0.f, l1 = 0.f;

    const int lane2 = (lane & 3) * 2;
    const int qrow  = warp * 16 + (lane >> 2);
    const int qg0   = q0 + qrow;

    const int a_r = warp * 16 + (lane & 15);
    const int a_c = (lane >> 4) << 4;
    const int b_r = (lane & 7) + ((lane >> 4) << 3);
    const int b_c = ((lane >> 3) & 1) << 4;
    const int v_r = lane & 15;
    const int v_c = (lane >> 4) << 4;

    for (int c = 0; c < 5; c++) {
        const int kb = q0 - WIN + c * 64;
        __syncthreads();
        #pragma unroll
        for (int i = 0; i < 4; i++) {
            int cg  = tid + i * 128;
            int row = cg >> 3;
            int ck  = cg & 7;
            int kg  = kb + row;
            uint32_t sz = (kg >= 0) ? 16u : 0u;
            int kgc = kg >= 0 ? kg : 0;
            uint32_t so = SWZ128((uint32_t)(row * 128 + ck * 16));
            size_t gk = (rbase + kgc) * N_QKV + DM + hoff + ck * 8;
            size_t gv = gk + DM;
            CP16Z(sKH + so, qh + gk, sz);
            CP16Z(sKL + so, ql + gk, sz);
            CP16Z(sVH + so, qh + gv, sz);
            CP16Z(sVL + so, ql + gv, sz);
        }
        CP_COMMIT();
        CP_WAIT(0);
        __syncthreads();

        #pragma unroll
        for (int t = 0; t < 8; t++)
            #pragma unroll
            for (int j = 0; j < 4; j++) sa[t][j] = 0.f;

        #pragma unroll
        for (int ks = 0; ks < 4; ks++) {
            uint32_t ah[4], al[4];
            uint32_t ao = SWZ128((uint32_t)(a_r * 128 + ks * 32 + a_c));
            LDM4(ah, sQH + ao);
            LDM4(al, sQL + ao);
            #pragma unroll
            for (int np = 0; np < 4; np++) {
                uint32_t bo = SWZ128((uint32_t)((np * 16 + b_r) * 128 + ks * 32 + b_c));
                uint32_t bh[4], bl[4];
                LDM4(bh, sKH + bo);
                LDM4(bl, sKL + bo);
                MMA16816(sa[2 * np],     ah, bh[0], bh[1]);
                MMA16816(sa[2 * np + 1], ah, bh[2], bh[3]);
                MMA16816(sa[2 * np],     ah, bl[0], bl[1]);
                MMA16816(sa[2 * np + 1], ah, bl[2], bl[3]);
                MMA16816(sa[2 * np],     al, bh[0], bh[1]);
                MMA16816(sa[2 * np + 1], al, bh[2], bh[3]);
            }
        }

        float mx0 = -1e30f, mx1 = -1e30f;
        #pragma unroll
        for (int t = 0; t < 8; t++) {
            #pragma unroll
            for (int j = 0; j < 4; j++) {
                int col = t * 8 + lane2 + (j & 1);
                int kg  = kb + col;
                int qg  = qg0 + ((j >> 1) << 3);
                bool valid = (kg >= 0) && (kg <= qg) && (kg >= qg - WIN);
                float s = valid ? sa[t][j] * 0.125f : -1e30f;
                sa[t][j] = s;
                if (j < 2) mx0 = fmaxf(mx0, s); else mx1 = fmaxf(mx1, s);
            }
        }
        mx0 = fmaxf(mx0, __shfl_xor_sync(0xffffffffu, mx0, 1));
        mx0 = fmaxf(mx0, __shfl_xor_sync(0xffffffffu, mx0, 2));
        mx1 = fmaxf(mx1, __shfl_xor_sync(0xffffffffu, mx1, 1));
        mx1 = fmaxf(mx1, __shfl_xor_sync(0xffffffffu, mx1, 2));

        const float mn0 = fmaxf(m0, mx0);
        const float mn1 = fmaxf(m1, mx1);
        const float sc0 = __expf(m0 - mn0);
        const float sc1 = __expf(m1 - mn1);
        m0 = mn0; m1 = mn1;

        float ps0 = 0.f, ps1 = 0.f;
        #pragma unroll
        for (int t = 0; t < 8; t++) {
            float p0 = __expf(sa[t][0] - mn0);
            float p1 = __expf(sa[t][1] - mn0);
            float p2 = __expf(sa[t][2] - mn1);
            float p3 = __expf(sa[t][3] - mn1);
            sa[t][0] = p0; sa[t][1] = p1; sa[t][2] = p2; sa[t][3] = p3;
            ps0 += p0 + p1; ps1 += p2 + p3;
        }
        ps0 += __shfl_xor_sync(0xffffffffu, ps0, 1);
        ps0 += __shfl_xor_sync(0xffffffffu, ps0, 2);
        ps1 += __shfl_xor_sync(0xffffffffu, ps1, 1);
        ps1 += __shfl_xor_sync(0xffffffffu, ps1, 2);
        l0 = l0 * sc0 + ps0;
        l1 = l1 * sc1 + ps1;

        #pragma unroll
        for (int t = 0; t < 8; t++) {
            o[t][0] *= sc0; o[t][1] *= sc0;
            o[t][2] *= sc1; o[t][3] *= sc1;
        }

        #pragma unroll
        for (int s = 0; s < 4; s++) {
            uint32_t aph[4], apl[4];
            pack2_hilo(sa[2 * s][0],     sa[2 * s][1],     aph[0], apl[0]);
            pack2_hilo(sa[2 * s][2],     sa[2 * s][3],     aph[1], apl[1]);
            pack2_hilo(sa[2 * s + 1][0], sa[2 * s + 1][1], aph[2], apl[2]);
            pack2_hilo(sa[2 * s + 1][2], sa[2 * s + 1][3], aph[3], apl[3]);
            #pragma unroll
            for (int nd = 0; nd < 4; nd++) {
                uint32_t vo = SWZ128((uint32_t)((s * 16 + v_r) * 128 + nd * 32 + v_c));
                uint32_t vh[4], vl[4];
                LDM4T(vh, sVH + vo);
                LDM4T(vl, sVL + vo);
                MMA16816(o[2 * nd],     aph, vh[0], vh[1]);
                MMA16816(o[2 * nd + 1], aph, vh[2], vh[3]);
                MMA16816(o[2 * nd],     aph, vl[0], vl[1]);
                MMA16816(o[2 * nd + 1], aph, vl[2], vl[3]);
                MMA16816(o[2 * nd],     apl, vh[0], vh[1]);
                MMA16816(o[2 * nd + 1], apl, vh[2], vh[3]);
            }
        }
    }

    const float il0 = 1.f / l0;
    const float il1 = 1.f / l1;
    const size_t row0 = rbase + qg0;
    #pragma unroll
    for (int t = 0; t < 8; t++) {
        int col = hoff + t * 8 + lane2;
        uint32_t h0, lo0, h1, lo1;
        pack2_hilo(o[t][0] * il0, o[t][1] * il0, h0, lo0);
        pack2_hilo(o[t][2] * il1, o[t][3] * il1, h1, lo1);
        *reinterpret_cast<uint32_t*>(&out_hi[row0 * DM + col])       = h0;
        *reinterpret_cast<uint32_t*>(&out_lo[row0 * DM + col])       = lo0;
        *reinterpret_cast<uint32_t*>(&out_hi[(row0 + 8) * DM + col]) = h1;
        *reinterpret_cast<uint32_t*>(&out_lo[(row0 + 8) * DM + col]) = lo1;
    }
}

// ---------------------------------------------------------------------------
extern "C" void kernel_launch(void* const* d_in, const int* in_sizes, int n_in,
                              void* d_out, int out_size) {
    const float* x     = (const float*)d_in[0];
    const float* w_qkv = (const float*)d_in[1];
    const float* w_out = (const float*)d_in[2];
    float* out = (float*)d_out;

    __half *x16_hi, *x16_lo, *wq16;
    __nv_bfloat16 *wo_hi, *wo_lo, *qkv_hi, *qkv_lo, *at_hi, *at_lo;
    cudaGetSymbolAddress((void**)&x16_hi, g_x16_hi);
    cudaGetSymbolAddress((void**)&x16_lo, g_x16_lo);
    cudaGetSymbolAddress((void**)&wq16,   g_wqkvT16);
    cudaGetSymbolAddress((void**)&wo_hi,  g_woutT_hi);
    cudaGetSymbolAddress((void**)&wo_lo,  g_woutT_lo);
    cudaGetSymbolAddress((void**)&qkv_hi, g_qkv_hi);
    cudaGetSymbolAddress((void**)&qkv_lo, g_qkv_lo);
    cudaGetSymbolAddress((void**)&at_hi,  g_att_hi);
    cudaGetSymbolAddress((void**)&at_lo,  g_att_lo);

    cudaFuncSetAttribute(gemm_f16x2,  cudaFuncAttributeMaxDynamicSharedMemorySize, GEMM2_SMEM);
    cudaFuncSetAttribute(gemm_bf16x3, cudaFuncAttributeMaxDynamicSharedMemorySize, GEMM_SMEM);
    const int ATTN_SMEM = 6 * ATT_T;
    cudaFuncSetAttribute(attn_tc_kernel, cudaFuncAttributeMaxDynamicSharedMemorySize, ATTN_SMEM);

    // 0) prep: x -> fp16 hi/lo; w_qkv -> [N][K] fp16; w_out -> bf16 hi/lo [N][K]
    {
        int n4 = M_ROWS * DM / 4;
        split_f16_kernel<<<(n4 + 255) / 256, 256>>>(x, x16_hi, x16_lo, n4);
        dim3 g1(N_QKV / 32, DM / 32);
        transpose_f16_kernel<<<g1, 256>>>(w_qkv, wq16, DM, N_QKV);
        dim3 g2(DM / 32, DM / 32);
        transpose_split_kernel<<<g2, 256>>>(w_out, wo_hi, wo_lo, DM, DM);
    }
    // 1) QKV projection (fp16x2) -> pre-split bf16 hi/lo
    {
        dim3 grid(N_QKV / BN, M_ROWS / BM);
        gemm_f16x2<<<grid, 256, GEMM2_SMEM>>>(x16_hi, x16_lo, wq16,
                                              qkv_hi, qkv_lo,
                                              M_ROWS, N_QKV, DM);
    }
    // 2) attention
    {
        dim3 grid(T_SEQ / 64, NH, B_SZ);
        attn_tc_kernel<<<grid, 128, ATTN_SMEM>>>(qkv_hi, qkv_lo, at_hi, at_lo);
    }
    // 3) output projection (bf16x3) -> fp32
    {
        dim3 grid(DM / BN, M_ROWS / BM);
        gemm_bf16x3<<<grid, 256, GEMM_SMEM>>>(at_hi, at_lo, wo_hi, wo_lo,
                                              out, M_ROWS, DM, DM);
    }
}

// round 10
// speedup vs baseline: 1.3977x; 1.0641x over previous
#include <cuda_runtime.h>
#include <cuda_bf16.h>
#include <cuda_fp16.h>
#include <math.h>
#include <stdint.h>

// Problem constants
#define B_SZ   4
#define T_SEQ  2048
#define DM     1024
#define NH     16
#define DH     64
#define WIN    256
#define M_ROWS (B_SZ * T_SEQ)        // 8192
#define N_QKV  (3 * DM)              // 3072

// fp16x2 GEMM tiling: 128x128x32, stage = Ah + Al + B = 3 tiles, 4-stage ring
#define BM 128
#define BN 128
#define BKK 32
#define TILE_B (BM * 64)              // 8192 B per split tile
#define NSTAGE2 4
#define STG2_B (3 * TILE_B)           // 24576 B
#define GEMM2_SMEM (NSTAGE2 * STG2_B + 128)

// ---------------------------------------------------------------------------
// Device scratch (allocation-free per harness rules)
// ---------------------------------------------------------------------------
__device__ __align__(16) __half g_x16_hi[M_ROWS * (size_t)DM];
__device__ __align__(16) __half g_x16_lo[M_ROWS * (size_t)DM];
__device__ __align__(16) __half g_wqkvT16[N_QKV * (size_t)DM];           // [N][K]
__device__ __align__(16) __half g_woutT16[DM * (size_t)DM];              // [N][K]
__device__ __align__(16) __nv_bfloat16 g_qkv_hi[M_ROWS * (size_t)N_QKV]; // pre-split QKV
__device__ __align__(16) __nv_bfloat16 g_qkv_lo[M_ROWS * (size_t)N_QKV];
__device__ __align__(16) __half g_att16_hi[M_ROWS * (size_t)DM];
__device__ __align__(16) __half g_att16_lo[M_ROWS * (size_t)DM];

// ---------------------------------------------------------------------------
// Helpers
// ---------------------------------------------------------------------------
__device__ __forceinline__ uint32_t smem_u32(const void* p) {
    return (uint32_t)__cvta_generic_to_shared(p);
}

#define CP16(saddr, gptr) \
    asm volatile("cp.async.cg.shared.global [%0], [%1], 16;" :: "r"(saddr), "l"(gptr))
#define CP16Z(saddr, gptr, sz) \
    asm volatile("cp.async.cg.shared.global [%0], [%1], 16, %2;" \
        :: "r"(saddr), "l"(gptr), "r"(sz))
#define CP_COMMIT() asm volatile("cp.async.commit_group;")
#define CP_WAIT(n)  asm volatile("cp.async.wait_group %0;" :: "n"(n))

#define LDM4(r, addr) \
    asm volatile("ldmatrix.sync.aligned.m8n8.x4.shared.b16 {%0,%1,%2,%3}, [%4];" \
        : "=r"((r)[0]), "=r"((r)[1]), "=r"((r)[2]), "=r"((r)[3]) : "r"(addr))

#define LDM4T(r, addr) \
    asm volatile("ldmatrix.sync.aligned.m8n8.x4.trans.shared.b16 {%0,%1,%2,%3}, [%4];" \
        : "=r"((r)[0]), "=r"((r)[1]), "=r"((r)[2]), "=r"((r)[3]) : "r"(addr))

#define MMA16816(d, a, b0, b1) \
    asm volatile("mma.sync.aligned.m16n8k16.row.col.f32.bf16.bf16.f32 " \
        "{%0,%1,%2,%3}, {%4,%5,%6,%7}, {%8,%9}, {%0,%1,%2,%3};" \
        : "+f"((d)[0]), "+f"((d)[1]), "+f"((d)[2]), "+f"((d)[3]) \
        : "r"((a)[0]), "r"((a)[1]), "r"((a)[2]), "r"((a)[3]), "r"(b0), "r"(b1))

#define MMA16816H(d, a, b0, b1) \
    asm volatile("mma.sync.aligned.m16n8k16.row.col.f32.f16.f16.f32 " \
        "{%0,%1,%2,%3}, {%4,%5,%6,%7}, {%8,%9}, {%0,%1,%2,%3};" \
        : "+f"((d)[0]), "+f"((d)[1]), "+f"((d)[2]), "+f"((d)[3]) \
        : "r"((a)[0]), "r"((a)[1]), "r"((a)[2]), "r"((a)[3]), "r"(b0), "r"(b1))

// 64B-row swizzle (GEMM tiles)
#define SWZ2(off) ((off) ^ ((((off) >> 7) & 3u) << 4))
// 128B-row swizzle (attention tiles)
#define SWZ128(off) ((off) ^ ((((off) >> 7) & 7u) << 4))

__device__ __forceinline__ void split_f32(float f, __nv_bfloat16& hi, __nv_bfloat16& lo) {
    hi = __float2bfloat16_rn(f);
    lo = __float2bfloat16_rn(f - __bfloat162float(hi));
}
__device__ __forceinline__ void split_f32h(float f, __half& hi, __half& lo) {
    hi = __float2half_rn(f);
    lo = __float2half_rn(f - __half2float(hi));
}

__device__ __forceinline__ void pack2_hilo(float x, float y, uint32_t& h, uint32_t& l) {
    __nv_bfloat162 hv, lv;
    split_f32(x, hv.x, lv.x);
    split_f32(y, hv.y, lv.y);
    h = *reinterpret_cast<uint32_t*>(&hv);
    l = *reinterpret_cast<uint32_t*>(&lv);
}
__device__ __forceinline__ void pack2_hilo_h(float x, float y, uint32_t& h, uint32_t& l) {
    __half2 hv, lv;
    split_f32h(x, hv.x, lv.x);
    split_f32h(y, hv.y, lv.y);
    h = *reinterpret_cast<uint32_t*>(&hv);
    l = *reinterpret_cast<uint32_t*>(&lv);
}

// ---------------------------------------------------------------------------
// prep kernels
// ---------------------------------------------------------------------------
__global__ void split_f16_kernel(const float* __restrict__ src,
                                 __half* __restrict__ hi,
                                 __half* __restrict__ lo, int n4) {
    int i = blockIdx.x * blockDim.x + threadIdx.x;
    if (i >= n4) return;
    float4 f = reinterpret_cast<const float4*>(src)[i];
    __half2 h01, l01, h23, l23;
    split_f32h(f.x, h01.x, l01.x);
    split_f32h(f.y, h01.y, l01.y);
    split_f32h(f.z, h23.x, l23.x);
    split_f32h(f.w, h23.y, l23.y);
    __half2* hp = reinterpret_cast<__half2*>(hi) + i * 2;
    __half2* lp = reinterpret_cast<__half2*>(lo) + i * 2;
    hp[0] = h01; hp[1] = h23;
    lp[0] = l01; lp[1] = l23;
}

// transpose + round to single fp16: src [K][N] fp32 -> dst [N][K] half
__global__ void transpose_f16_kernel(const float* __restrict__ src,
                                     __half* __restrict__ dst, int K, int N) {
    __shared__ float t[32][33];
    const int n0 = blockIdx.x * 32;
    const int k0 = blockIdx.y * 32;
    const int tx = threadIdx.x & 31;
    const int ty = threadIdx.x >> 5;
    #pragma unroll
    for (int i = 0; i < 32; i += 8)
        t[ty + i][tx] = src[(size_t)(k0 + ty + i) * N + n0 + tx];
    __syncthreads();
    #pragma unroll
    for (int i = 0; i < 32; i += 8)
        dst[(size_t)(n0 + ty + i) * K + k0 + tx] = __float2half_rn(t[tx][ty + i]);
}

// ---------------------------------------------------------------------------
// fp16x2 GEMM: C = (Ah+Al) @ B^T, A split fp16, B single fp16.
// 128x128x32 tiles, 8 warps, 4-stage ring, one sync/K-tile.
// Epilogue: Chi!=null -> bf16 hi/lo splits; else fp32 C.
// ---------------------------------------------------------------------------
__global__ __launch_bounds__(256, 2)
void gemm_f16x2(const __half* __restrict__ Ah, const __half* __restrict__ Al,
                const __half* __restrict__ Bq,
                float* __restrict__ C,
                __nv_bfloat16* __restrict__ Chi, __nv_bfloat16* __restrict__ Clo,
                int M, int N, int K) {
    extern __shared__ char smraw[];
    const uint32_t sbase = (smem_u32(smraw) + 127) & ~127u;

    const int tid  = threadIdx.x;
    const int lane = tid & 31;
    const int warp = tid >> 5;
    const int wm   = warp & 3;
    const int wn   = warp >> 2;
    const int m0   = blockIdx.y * BM;
    const int n0   = blockIdx.x * BN;

    float acc[2][8][4];
    #pragma unroll
    for (int a = 0; a < 2; a++)
        #pragma unroll
        for (int b = 0; b < 8; b++)
            #pragma unroll
            for (int c = 0; c < 4; c++) acc[a][b][c] = 0.f;

    const int NK = K / BKK;

    auto load_stage = [&](int buf, int kt) {
        const uint32_t s = sbase + buf * STG2_B;
        const int kg = kt * BKK;
        #pragma unroll
        for (int i = 0; i < 2; ++i) {
            int cg  = tid + i * 256;
            int row = cg >> 2;
            int ck  = cg & 3;
            uint32_t so = SWZ2((uint32_t)(row * 64 + ck * 16));
            size_t ka = (size_t)kg + ck * 8;
            size_t ga = (size_t)(m0 + row) * K + ka;
            size_t gb = (size_t)(n0 + row) * K + ka;
            CP16(s + so,              Ah + ga);
            CP16(s + TILE_B + so,     Al + ga);
            CP16(s + 2 * TILE_B + so, Bq + gb);
        }
    };

    load_stage(0, 0); CP_COMMIT();
    load_stage(1, 1); CP_COMMIT();
    load_stage(2, 2); CP_COMMIT();

    const int a_r  = wm * 32 + (lane & 15);
    const int a_c0 = lane >> 4;
    const int b_r  = wn * 64 + (lane & 7) + ((lane >> 4) << 3);
    const int b_c0 = (lane >> 3) & 1;

    for (int kt = 0; kt < NK; ++kt) {
        if (kt + 1 < NK) { CP_WAIT(2); } else { CP_WAIT(0); }
        __syncthreads();
        if (kt + 3 < NK) {
            load_stage((kt + 3) % NSTAGE2, kt + 3);
            CP_COMMIT();
        }

        const uint32_t s = sbase + (kt % NSTAGE2) * STG2_B;
        #pragma unroll
        for (int ks = 0; ks < 2; ++ks) {
            uint32_t ah[2][4], al[2][4];
            #pragma unroll
            for (int mt = 0; mt < 2; ++mt) {
                uint32_t ro = SWZ2((uint32_t)((a_r + mt * 16) * 64 + (2 * ks + a_c0) * 16));
                LDM4(ah[mt], s + ro);
                LDM4(al[mt], s + TILE_B + ro);
            }
            #pragma unroll
            for (int np = 0; np < 4; ++np) {
                uint32_t ro = SWZ2((uint32_t)((b_r + np * 16) * 64 + (2 * ks + b_c0) * 16));
                uint32_t bq[4];
                LDM4(bq, s + 2 * TILE_B + ro);
                MMA16816H(acc[0][2 * np],     ah[0], bq[0], bq[1]);
                MMA16816H(acc[1][2 * np],     ah[1], bq[0], bq[1]);
                MMA16816H(acc[0][2 * np + 1], ah[0], bq[2], bq[3]);
                MMA16816H(acc[1][2 * np + 1], ah[1], bq[2], bq[3]);
                MMA16816H(acc[0][2 * np],     al[0], bq[0], bq[1]);
                MMA16816H(acc[1][2 * np],     al[1], bq[0], bq[1]);
                MMA16816H(acc[0][2 * np + 1], al[0], bq[2], bq[3]);
                MMA16816H(acc[1][2 * np + 1], al[1], bq[2], bq[3]);
            }
        }
    }

    if (Chi != nullptr) {
        #pragma unroll
        for (int mt = 0; mt < 2; ++mt) {
            #pragma unroll
            for (int nt = 0; nt < 8; ++nt) {
                int row = m0 + wm * 32 + mt * 16 + (lane >> 2);
                int col = n0 + wn * 64 + nt * 8 + (lane & 3) * 2;
                uint32_t h0, l0, h1, l1;
                pack2_hilo(acc[mt][nt][0], acc[mt][nt][1], h0, l0);
                pack2_hilo(acc[mt][nt][2], acc[mt][nt][3], h1, l1);
                *reinterpret_cast<uint32_t*>(&Chi[(size_t)row * N + col])       = h0;
                *reinterpret_cast<uint32_t*>(&Clo[(size_t)row * N + col])       = l0;
                *reinterpret_cast<uint32_t*>(&Chi[(size_t)(row + 8) * N + col]) = h1;
                *reinterpret_cast<uint32_t*>(&Clo[(size_t)(row + 8) * N + col]) = l1;
            }
        }
    } else {
        #pragma unroll
        for (int mt = 0; mt < 2; ++mt) {
            #pragma unroll
            for (int nt = 0; nt < 8; ++nt) {
                int row = m0 + wm * 32 + mt * 16 + (lane >> 2);
                int col = n0 + wn * 64 + nt * 8 + (lane & 3) * 2;
                float2 v0 = make_float2(acc[mt][nt][0], acc[mt][nt][1]);
                float2 v1 = make_float2(acc[mt][nt][2], acc[mt][nt][3]);
                *reinterpret_cast<float2*>(&C[(size_t)row * N + col]) = v0;
                *reinterpret_cast<float2*>(&C[(size_t)(row + 8) * N + col]) = v1;
            }
        }
    }
}

// ---------------------------------------------------------------------------
// Attention (Round-8 math, unchanged): pre-split bf16 hi/lo QKV via cp.async;
// epilogue now writes fp16 hi/lo for the fp16x2 output projection.
// ---------------------------------------------------------------------------
#define ATT_T 8192

__global__ __launch_bounds__(128, 4)
void attn_tc_kernel(const __nv_bfloat16* __restrict__ qh,
                    const __nv_bfloat16* __restrict__ ql,
                    __half* __restrict__ out_hi,
                    __half* __restrict__ out_lo) {
    extern __shared__ char smb[];
    const uint32_t sb  = smem_u32(smb);
    const uint32_t sQH = sb,            sQL = sb + ATT_T;
    const uint32_t sKH = sb + 2 * ATT_T, sKL = sb + 3 * ATT_T;
    const uint32_t sVH = sb + 4 * ATT_T, sVL = sb + 5 * ATT_T;

    const int tid  = threadIdx.x;
    const int lane = tid & 31;
    const int warp = tid >> 5;
    const int q0 = blockIdx.x * 64;
    const int h  = blockIdx.y;
    const int b  = blockIdx.z;
    const int hoff = h * DH;
    const size_t rbase = (size_t)b * T_SEQ;

    #pragma unroll
    for (int i = 0; i < 4; i++) {
        int cg  = tid + i * 128;
        int row = cg >> 3;
        int ck  = cg & 7;
        uint32_t so = SWZ128((uint32_t)(row * 128 + ck * 16));
        size_t g = (rbase + q0 + row) * N_QKV + hoff + ck * 8;
        CP16(sQH + so, qh + g);
        CP16(sQL + so, ql + g);
    }
    CP_COMMIT();

    float sa[8][4];
    float o[8][4];
    #pragma unroll
    for (int t = 0; t < 8; t++)
        #pragma unroll
        for (int j = 0; j < 4; j++) o[t][j] = 0.f;
    float m0 = -1e20f, m1 = -1e20f, l0 = 0.f, l1 = 0.f;

    const int lane2 = (lane & 3) * 2;
    const int qrow  = warp * 16 + (lane >> 2);
    const int qg0   = q0 + qrow;

    const int a_r = warp * 16 + (lane & 15);
    const int a_c = (lane >> 4) << 4;
    const int b_r = (lane & 7) + ((lane >> 4) << 3);
    const int b_c = ((lane >> 3) & 1) << 4;
    const int v_r = lane & 15;
    const int v_c = (lane >> 4) << 4;

    for (int c = 0; c < 5; c++) {
        const int kb = q0 - WIN + c * 64;
        __syncthreads();
        #pragma unroll
        for (int i = 0; i < 4; i++) {
            int cg  = tid + i * 128;
            int row = cg >> 3;
            int ck  = cg & 7;
            int kg  = kb + row;
            uint32_t sz = (kg >= 0) ? 16u : 0u;
            int kgc = kg >= 0 ? kg : 0;
            uint32_t so = SWZ128((uint32_t)(row * 128 + ck * 16));
            size_t gk = (rbase + kgc) * N_QKV + DM + hoff + ck * 8;
            size_t gv = gk + DM;
            CP16Z(sKH + so, qh + gk, sz);
            CP16Z(sKL + so, ql + gk, sz);
            CP16Z(sVH + so, qh + gv, sz);
            CP16Z(sVL + so, ql + gv, sz);
        }
        CP_COMMIT();
        CP_WAIT(0);
        __syncthreads();

        #pragma unroll
        for (int t = 0; t < 8; t++)
            #pragma unroll
            for (int j = 0; j < 4; j++) sa[t][j] = 0.f;

        #pragma unroll
        for (int ks = 0; ks < 4; ks++) {
            uint32_t ah[4], al[4];
            uint32_t ao = SWZ128((uint32_t)(a_r * 128 + ks * 32 + a_c));
            LDM4(ah, sQH + ao);
            LDM4(al, sQL + ao);
            #pragma unroll
            for (int np = 0; np < 4; np++) {
                uint32_t bo = SWZ128((uint32_t)((np * 16 + b_r) * 128 + ks * 32 + b_c));
                uint32_t bh[4], bl[4];
                LDM4(bh, sKH + bo);
                LDM4(bl, sKL + bo);
                MMA16816(sa[2 * np],     ah, bh[0], bh[1]);
                MMA16816(sa[2 * np + 1], ah, bh[2], bh[3]);
                MMA16816(sa[2 * np],     ah, bl[0], bl[1]);
                MMA16816(sa[2 * np + 1], ah, bl[2], bl[3]);
                MMA16816(sa[2 * np],     al, bh[0], bh[1]);
                MMA16816(sa[2 * np + 1], al, bh[2], bh[3]);
            }
        }

        float mx0 = -1e30f, mx1 = -1e30f;
        #pragma unroll
        for (int t = 0; t < 8; t++) {
            #pragma unroll
            for (int j = 0; j < 4; j++) {
                int col = t * 8 + lane2 + (j & 1);
                int kg  = kb + col;
                int qg  = qg0 + ((j >> 1) << 3);
                bool valid = (kg >= 0) && (kg <= qg) && (kg >= qg - WIN);
                float s = valid ? sa[t][j] * 0.125f : -1e30f;
                sa[t][j] = s;
                if (j < 2) mx0 = fmaxf(mx0, s); else mx1 = fmaxf(mx1, s);
            }
        }
        mx0 = fmaxf(mx0, __shfl_xor_sync(0xffffffffu, mx0, 1));
        mx0 = fmaxf(mx0, __shfl_xor_sync(0xffffffffu, mx0, 2));
        mx1 = fmaxf(mx1, __shfl_xor_sync(0xffffffffu, mx1, 1));
        mx1 = fmaxf(mx1, __shfl_xor_sync(0xffffffffu, mx1, 2));

        const float mn0 = fmaxf(m0, mx0);
        const float mn1 = fmaxf(m1, mx1);
        const float sc0 = __expf(m0 - mn0);
        const float sc1 = __expf(m1 - mn1);
        m0 = mn0; m1 = mn1;

        float ps0 = 0.f, ps1 = 0.f;
        #pragma unroll
        for (int t = 0; t < 8; t++) {
            float p0 = __expf(sa[t][0] - mn0);
            float p1 = __expf(sa[t][1] - mn0);
            float p2 = __expf(sa[t][2] - mn1);
            float p3 = __expf(sa[t][3] - mn1);
            sa[t][0] = p0; sa[t][1] = p1; sa[t][2] = p2; sa[t][3] = p3;
            ps0 += p0 + p1; ps1 += p2 + p3;
        }
        ps0 += __shfl_xor_sync(0xffffffffu, ps0, 1);
        ps0 += __shfl_xor_sync(0xffffffffu, ps0, 2);
        ps1 += __shfl_xor_sync(0xffffffffu, ps1, 1);
        ps1 += __shfl_xor_sync(0xffffffffu, ps1, 2);
        l0 = l0 * sc0 + ps0;
        l1 = l1 * sc1 + ps1;

        #pragma unroll
        for (int t = 0; t < 8; t++) {
            o[t][0] *= sc0; o[t][1] *= sc0;
            o[t][2] *= sc1; o[t][3] *= sc1;
        }

        #pragma unroll
        for (int s = 0; s < 4; s++) {
            uint32_t aph[4], apl[4];
            pack2_hilo(sa[2 * s][0],     sa[2 * s][1],     aph[0], apl[0]);
            pack2_hilo(sa[2 * s][2],     sa[2 * s][3],     aph[1], apl[1]);
            pack2_hilo(sa[2 * s + 1][0], sa[2 * s + 1][1], aph[2], apl[2]);
            pack2_hilo(sa[2 * s + 1][2], sa[2 * s + 1][3], aph[3], apl[3]);
            #pragma unroll
            for (int nd = 0; nd < 4; nd++) {
                uint32_t vo = SWZ128((uint32_t)((s * 16 + v_r) * 128 + nd * 32 + v_c));
                uint32_t vh[4], vl[4];
                LDM4T(vh, sVH + vo);
                LDM4T(vl, sVL + vo);
                MMA16816(o[2 * nd],     aph, vh[0], vh[1]);
                MMA16816(o[2 * nd + 1], aph, vh[2], vh[3]);
                MMA16816(o[2 * nd],     aph, vl[0], vl[1]);
                MMA16816(o[2 * nd + 1], aph, vl[2], vl[3]);
                MMA16816(o[2 * nd],     apl, vh[0], vh[1]);
                MMA16816(o[2 * nd + 1], apl, vh[2], vh[3]);
            }
        }
    }

    // epilogue: normalize, split to fp16 hi/lo for the fp16x2 out-projection
    const float il0 = 1.f / l0;
    const float il1 = 1.f / l1;
    const size_t row0 = rbase + qg0;
    #pragma unroll
    for (int t = 0; t < 8; t++) {
        int col = hoff + t * 8 + lane2;
        uint32_t h0, lo0, h1, lo1;
        pack2_hilo_h(o[t][0] * il0, o[t][1] * il0, h0, lo0);
        pack2_hilo_h(o[t][2] * il1, o[t][3] * il1, h1, lo1);
        *reinterpret_cast<uint32_t*>(&out_hi[row0 * DM + col])       = h0;
        *reinterpret_cast<uint32_t*>(&out_lo[row0 * DM + col])       = lo0;
        *reinterpret_cast<uint32_t*>(&out_hi[(row0 + 8) * DM + col]) = h1;
        *reinterpret_cast<uint32_t*>(&out_lo[(row0 + 8) * DM + col]) = lo1;
    }
}

// ---------------------------------------------------------------------------
extern "C" void kernel_launch(void* const* d_in, const int* in_sizes, int n_in,
                              void* d_out, int out_size) {
    const float* x     = (const float*)d_in[0];
    const float* w_qkv = (const float*)d_in[1];
    const float* w_out = (const float*)d_in[2];
    float* out = (float*)d_out;

    __half *x16_hi, *x16_lo, *wq16, *wo16, *at16_hi, *at16_lo;
    __nv_bfloat16 *qkv_hi, *qkv_lo;
    cudaGetSymbolAddress((void**)&x16_hi,  g_x16_hi);
    cudaGetSymbolAddress((void**)&x16_lo,  g_x16_lo);
    cudaGetSymbolAddress((void**)&wq16,    g_wqkvT16);
    cudaGetSymbolAddress((void**)&wo16,    g_woutT16);
    cudaGetSymbolAddress((void**)&qkv_hi,  g_qkv_hi);
    cudaGetSymbolAddress((void**)&qkv_lo,  g_qkv_lo);
    cudaGetSymbolAddress((void**)&at16_hi, g_att16_hi);
    cudaGetSymbolAddress((void**)&at16_lo, g_att16_lo);

    cudaFuncSetAttribute(gemm_f16x2, cudaFuncAttributeMaxDynamicSharedMemorySize, GEMM2_SMEM);
    const int ATTN_SMEM = 6 * ATT_T;
    cudaFuncSetAttribute(attn_tc_kernel, cudaFuncAttributeMaxDynamicSharedMemorySize, ATTN_SMEM);

    // 0) prep: x -> fp16 hi/lo; w_qkv, w_out -> [N][K] fp16
    {
        int n4 = M_ROWS * DM / 4;
        split_f16_kernel<<<(n4 + 255) / 256, 256>>>(x, x16_hi, x16_lo, n4);
        dim3 g1(N_QKV / 32, DM / 32);
        transpose_f16_kernel<<<g1, 256>>>(w_qkv, wq16, DM, N_QKV);
        dim3 g2(DM / 32, DM / 32);
        transpose_f16_kernel<<<g2, 256>>>(w_out, wo16, DM, DM);
    }
    // 1) QKV projection (fp16x2) -> pre-split bf16 hi/lo
    {
        dim3 grid(N_QKV / BN, M_ROWS / BM);
        gemm_f16x2<<<grid, 256, GEMM2_SMEM>>>(x16_hi, x16_lo, wq16,
                                              nullptr, qkv_hi, qkv_lo,
                                              M_ROWS, N_QKV, DM);
    }
    // 2) attention -> fp16 hi/lo
    {
        dim3 grid(T_SEQ / 64, NH, B_SZ);
        attn_tc_kernel<<<grid, 128, ATTN_SMEM>>>(qkv_hi, qkv_lo, at16_hi, at16_lo);
    }
    // 3) output projection (fp16x2) -> fp32
    {
        dim3 grid(DM / BN, M_ROWS / BM);
        gemm_f16x2<<<grid, 256, GEMM2_SMEM>>>(at16_hi, at16_lo, wo16,
                                              out, nullptr, nullptr,
                                              M_ROWS, DM, DM);
    }
}

// round 11
// speedup vs baseline: 1.8128x; 1.2970x over previous
#include <cuda_runtime.h>
#include <cuda_bf16.h>
#include <cuda_fp16.h>
#include <math.h>
#include <stdint.h>

// Problem constants
#define B_SZ   4
#define T_SEQ  2048
#define DM     1024
#define NH     16
#define DH     64
#define WIN    256
#define M_ROWS (B_SZ * T_SEQ)        // 8192
#define N_QKV  (3 * DM)              // 3072

// GEMM tiling: 128x128x32, one sync per K-tile
#define BM 128
#define BN 128
#define BKK 32
#define TILE_B (BM * 64)              // 8192 B per tile
// fp16x1 (GEMM1): stage = A + B = 2 tiles, 4-stage ring
#define NSTAGE1 4
#define STG1_B (2 * TILE_B)           // 16384 B
#define GEMM1_SMEM (NSTAGE1 * STG1_B + 128)
// fp16x2 (GEMM2): stage = Ah + Al + B = 3 tiles, 4-stage ring
#define NSTAGE2 4
#define STG2_B (3 * TILE_B)           // 24576 B
#define GEMM2_SMEM (NSTAGE2 * STG2_B + 128)

// ---------------------------------------------------------------------------
// Device scratch (allocation-free per harness rules)
// ---------------------------------------------------------------------------
__device__ __align__(16) __half g_x16[M_ROWS * (size_t)DM];
__device__ __align__(16) __half g_wqkvT16[N_QKV * (size_t)DM];           // [N][K]
__device__ __align__(16) __half g_woutT16[DM * (size_t)DM];              // [N][K]
__device__ __align__(16) __nv_bfloat16 g_qkv_hi[M_ROWS * (size_t)N_QKV]; // pre-split QKV
__device__ __align__(16) __nv_bfloat16 g_qkv_lo[M_ROWS * (size_t)N_QKV];
__device__ __align__(16) __half g_att16_hi[M_ROWS * (size_t)DM];
__device__ __align__(16) __half g_att16_lo[M_ROWS * (size_t)DM];

// ---------------------------------------------------------------------------
// Helpers
// ---------------------------------------------------------------------------
__device__ __forceinline__ uint32_t smem_u32(const void* p) {
    return (uint32_t)__cvta_generic_to_shared(p);
}

#define CP16(saddr, gptr) \
    asm volatile("cp.async.cg.shared.global [%0], [%1], 16;" :: "r"(saddr), "l"(gptr))
#define CP16Z(saddr, gptr, sz) \
    asm volatile("cp.async.cg.shared.global [%0], [%1], 16, %2;" \
        :: "r"(saddr), "l"(gptr), "r"(sz))
#define CP_COMMIT() asm volatile("cp.async.commit_group;")
#define CP_WAIT(n)  asm volatile("cp.async.wait_group %0;" :: "n"(n))

#define LDM4(r, addr) \
    asm volatile("ldmatrix.sync.aligned.m8n8.x4.shared.b16 {%0,%1,%2,%3}, [%4];" \
        : "=r"((r)[0]), "=r"((r)[1]), "=r"((r)[2]), "=r"((r)[3]) : "r"(addr))

#define LDM4T(r, addr) \
    asm volatile("ldmatrix.sync.aligned.m8n8.x4.trans.shared.b16 {%0,%1,%2,%3}, [%4];" \
        : "=r"((r)[0]), "=r"((r)[1]), "=r"((r)[2]), "=r"((r)[3]) : "r"(addr))

#define MMA16816(d, a, b0, b1) \
    asm volatile("mma.sync.aligned.m16n8k16.row.col.f32.bf16.bf16.f32 " \
        "{%0,%1,%2,%3}, {%4,%5,%6,%7}, {%8,%9}, {%0,%1,%2,%3};" \
        : "+f"((d)[0]), "+f"((d)[1]), "+f"((d)[2]), "+f"((d)[3]) \
        : "r"((a)[0]), "r"((a)[1]), "r"((a)[2]), "r"((a)[3]), "r"(b0), "r"(b1))

#define MMA16816H(d, a, b0, b1) \
    asm volatile("mma.sync.aligned.m16n8k16.row.col.f32.f16.f16.f32 " \
        "{%0,%1,%2,%3}, {%4,%5,%6,%7}, {%8,%9}, {%0,%1,%2,%3};" \
        : "+f"((d)[0]), "+f"((d)[1]), "+f"((d)[2]), "+f"((d)[3]) \
        : "r"((a)[0]), "r"((a)[1]), "r"((a)[2]), "r"((a)[3]), "r"(b0), "r"(b1))

// 64B-row swizzle (GEMM tiles)
#define SWZ2(off) ((off) ^ ((((off) >> 7) & 3u) << 4))
// 128B-row swizzle (attention tiles)
#define SWZ128(off) ((off) ^ ((((off) >> 7) & 7u) << 4))

__device__ __forceinline__ void split_f32(float f, __nv_bfloat16& hi, __nv_bfloat16& lo) {
    hi = __float2bfloat16_rn(f);
    lo = __float2bfloat16_rn(f - __bfloat162float(hi));
}
__device__ __forceinline__ void split_f32h(float f, __half& hi, __half& lo) {
    hi = __float2half_rn(f);
    lo = __float2half_rn(f - __half2float(hi));
}

__device__ __forceinline__ void pack2_hilo(float x, float y, uint32_t& h, uint32_t& l) {
    __nv_bfloat162 hv, lv;
    split_f32(x, hv.x, lv.x);
    split_f32(y, hv.y, lv.y);
    h = *reinterpret_cast<uint32_t*>(&hv);
    l = *reinterpret_cast<uint32_t*>(&lv);
}
__device__ __forceinline__ void pack2_hilo_h(float x, float y, uint32_t& h, uint32_t& l) {
    __half2 hv, lv;
    split_f32h(x, hv.x, lv.x);
    split_f32h(y, hv.y, lv.y);
    h = *reinterpret_cast<uint32_t*>(&hv);
    l = *reinterpret_cast<uint32_t*>(&lv);
}

// ---------------------------------------------------------------------------
// prep kernels
// ---------------------------------------------------------------------------
__global__ void cvt_f16_kernel(const float* __restrict__ src,
                               __half* __restrict__ dst, int n4) {
    int i = blockIdx.x * blockDim.x + threadIdx.x;
    if (i >= n4) return;
    float4 f = reinterpret_cast<const float4*>(src)[i];
    __half2 a = __half2(__float2half_rn(f.x), __float2half_rn(f.y));
    __half2 b = __half2(__float2half_rn(f.z), __float2half_rn(f.w));
    __half2* dp = reinterpret_cast<__half2*>(dst) + i * 2;
    dp[0] = a; dp[1] = b;
}

// transpose + round to single fp16: src [K][N] fp32 -> dst [N][K] half
__global__ void transpose_f16_kernel(const float* __restrict__ src,
                                     __half* __restrict__ dst, int K, int N) {
    __shared__ float t[32][33];
    const int n0 = blockIdx.x * 32;
    const int k0 = blockIdx.y * 32;
    const int tx = threadIdx.x & 31;
    const int ty = threadIdx.x >> 5;
    #pragma unroll
    for (int i = 0; i < 32; i += 8)
        t[ty + i][tx] = src[(size_t)(k0 + ty + i) * N + n0 + tx];
    __syncthreads();
    #pragma unroll
    for (int i = 0; i < 32; i += 8)
        dst[(size_t)(n0 + ty + i) * K + k0 + tx] = __float2half_rn(t[tx][ty + i]);
}

// ---------------------------------------------------------------------------
// fp16x1 GEMM (GEMM1): C = A16 @ B16^T, both single-rounded fp16.
// 128x128x32 tiles, 8 warps, 4-stage ring, one sync/K-tile.
// Epilogue writes bf16 hi/lo splits of the fp32 accumulator.
// ---------------------------------------------------------------------------
__global__ __launch_bounds__(256, 2)
void gemm_f16x1(const __half* __restrict__ A16, const __half* __restrict__ Bq,
                __nv_bfloat16* __restrict__ Chi, __nv_bfloat16* __restrict__ Clo,
                int M, int N, int K) {
    extern __shared__ char smraw[];
    const uint32_t sbase = (smem_u32(smraw) + 127) & ~127u;

    const int tid  = threadIdx.x;
    const int lane = tid & 31;
    const int warp = tid >> 5;
    const int wm   = warp & 3;
    const int wn   = warp >> 2;
    const int m0   = blockIdx.y * BM;
    const int n0   = blockIdx.x * BN;

    float acc[2][8][4];
    #pragma unroll
    for (int a = 0; a < 2; a++)
        #pragma unroll
        for (int b = 0; b < 8; b++)
            #pragma unroll
            for (int c = 0; c < 4; c++) acc[a][b][c] = 0.f;

    const int NK = K / BKK;

    auto load_stage = [&](int buf, int kt) {
        const uint32_t s = sbase + buf * STG1_B;
        const int kg = kt * BKK;
        #pragma unroll
        for (int i = 0; i < 2; ++i) {
            int cg  = tid + i * 256;
            int row = cg >> 2;
            int ck  = cg & 3;
            uint32_t so = SWZ2((uint32_t)(row * 64 + ck * 16));
            size_t ka = (size_t)kg + ck * 8;
            size_t ga = (size_t)(m0 + row) * K + ka;
            size_t gb = (size_t)(n0 + row) * K + ka;
            CP16(s + so,          A16 + ga);
            CP16(s + TILE_B + so, Bq + gb);
        }
    };

    load_stage(0, 0); CP_COMMIT();
    load_stage(1, 1); CP_COMMIT();
    load_stage(2, 2); CP_COMMIT();

    const int a_r  = wm * 32 + (lane & 15);
    const int a_c0 = lane >> 4;
    const int b_r  = wn * 64 + (lane & 7) + ((lane >> 4) << 3);
    const int b_c0 = (lane >> 3) & 1;

    for (int kt = 0; kt < NK; ++kt) {
        if (kt + 1 < NK) { CP_WAIT(2); } else { CP_WAIT(0); }
        __syncthreads();
        if (kt + 3 < NK) {
            load_stage((kt + 3) % NSTAGE1, kt + 3);
            CP_COMMIT();
        }

        const uint32_t s = sbase + (kt % NSTAGE1) * STG1_B;
        #pragma unroll
        for (int ks = 0; ks < 2; ++ks) {
            uint32_t ah[2][4];
            #pragma unroll
            for (int mt = 0; mt < 2; ++mt) {
                uint32_t ro = SWZ2((uint32_t)((a_r + mt * 16) * 64 + (2 * ks + a_c0) * 16));
                LDM4(ah[mt], s + ro);
            }
            #pragma unroll
            for (int np = 0; np < 4; ++np) {
                uint32_t ro = SWZ2((uint32_t)((b_r + np * 16) * 64 + (2 * ks + b_c0) * 16));
                uint32_t bq[4];
                LDM4(bq, s + TILE_B + ro);
                // 4 MMAs per np; same-acc reuse distance = 4
                MMA16816H(acc[0][2 * np],     ah[0], bq[0], bq[1]);
                MMA16816H(acc[1][2 * np],     ah[1], bq[0], bq[1]);
                MMA16816H(acc[0][2 * np + 1], ah[0], bq[2], bq[3]);
                MMA16816H(acc[1][2 * np + 1], ah[1], bq[2], bq[3]);
            }
        }
    }

    #pragma unroll
    for (int mt = 0; mt < 2; ++mt) {
        #pragma unroll
        for (int nt = 0; nt < 8; ++nt) {
            int row = m0 + wm * 32 + mt * 16 + (lane >> 2);
            int col = n0 + wn * 64 + nt * 8 + (lane & 3) * 2;
            uint32_t h0, l0, h1, l1;
            pack2_hilo(acc[mt][nt][0], acc[mt][nt][1], h0, l0);
            pack2_hilo(acc[mt][nt][2], acc[mt][nt][3], h1, l1);
            *reinterpret_cast<uint32_t*>(&Chi[(size_t)row * N + col])       = h0;
            *reinterpret_cast<uint32_t*>(&Clo[(size_t)row * N + col])       = l0;
            *reinterpret_cast<uint32_t*>(&Chi[(size_t)(row + 8) * N + col]) = h1;
            *reinterpret_cast<uint32_t*>(&Clo[(size_t)(row + 8) * N + col]) = l1;
        }
    }
}

// ---------------------------------------------------------------------------
// fp16x2 GEMM (GEMM2): C fp32 = (Ah+Al) @ B^T, A split fp16, B single fp16.
// ---------------------------------------------------------------------------
__global__ __launch_bounds__(256, 2)
void gemm_f16x2(const __half* __restrict__ Ah, const __half* __restrict__ Al,
                const __half* __restrict__ Bq,
                float* __restrict__ C, int M, int N, int K) {
    extern __shared__ char smraw[];
    const uint32_t sbase = (smem_u32(smraw) + 127) & ~127u;

    const int tid  = threadIdx.x;
    const int lane = tid & 31;
    const int warp = tid >> 5;
    const int wm   = warp & 3;
    const int wn   = warp >> 2;
    const int m0   = blockIdx.y * BM;
    const int n0   = blockIdx.x * BN;

    float acc[2][8][4];
    #pragma unroll
    for (int a = 0; a < 2; a++)
        #pragma unroll
        for (int b = 0; b < 8; b++)
            #pragma unroll
            for (int c = 0; c < 4; c++) acc[a][b][c] = 0.f;

    const int NK = K / BKK;

    auto load_stage = [&](int buf, int kt) {
        const uint32_t s = sbase + buf * STG2_B;
        const int kg = kt * BKK;
        #pragma unroll
        for (int i = 0; i < 2; ++i) {
            int cg  = tid + i * 256;
            int row = cg >> 2;
            int ck  = cg & 3;
            uint32_t so = SWZ2((uint32_t)(row * 64 + ck * 16));
            size_t ka = (size_t)kg + ck * 8;
            size_t ga = (size_t)(m0 + row) * K + ka;
            size_t gb = (size_t)(n0 + row) * K + ka;
            CP16(s + so,              Ah + ga);
            CP16(s + TILE_B + so,     Al + ga);
            CP16(s + 2 * TILE_B + so, Bq + gb);
        }
    };

    load_stage(0, 0); CP_COMMIT();
    load_stage(1, 1); CP_COMMIT();
    load_stage(2, 2); CP_COMMIT();

    const int a_r  = wm * 32 + (lane & 15);
    const int a_c0 = lane >> 4;
    const int b_r  = wn * 64 + (lane & 7) + ((lane >> 4) << 3);
    const int b_c0 = (lane >> 3) & 1;

    for (int kt = 0; kt < NK; ++kt) {
        if (kt + 1 < NK) { CP_WAIT(2); } else { CP_WAIT(0); }
        __syncthreads();
        if (kt + 3 < NK) {
            load_stage((kt + 3) % NSTAGE2, kt + 3);
            CP_COMMIT();
        }

        const uint32_t s = sbase + (kt % NSTAGE2) * STG2_B;
        #pragma unroll
        for (int ks = 0; ks < 2; ++ks) {
            uint32_t ah[2][4], al[2][4];
            #pragma unroll
            for (int mt = 0; mt < 2; ++mt) {
                uint32_t ro = SWZ2((uint32_t)((a_r + mt * 16) * 64 + (2 * ks + a_c0) * 16));
                LDM4(ah[mt], s + ro);
                LDM4(al[mt], s + TILE_B + ro);
            }
            #pragma unroll
            for (int np = 0; np < 4; ++np) {
                uint32_t ro = SWZ2((uint32_t)((b_r + np * 16) * 64 + (2 * ks + b_c0) * 16));
                uint32_t bq[4];
                LDM4(bq, s + 2 * TILE_B + ro);
                MMA16816H(acc[0][2 * np],     ah[0], bq[0], bq[1]);
                MMA16816H(acc[1][2 * np],     ah[1], bq[0], bq[1]);
                MMA16816H(acc[0][2 * np + 1], ah[0], bq[2], bq[3]);
                MMA16816H(acc[1][2 * np + 1], ah[1], bq[2], bq[3]);
                MMA16816H(acc[0][2 * np],     al[0], bq[0], bq[1]);
                MMA16816H(acc[1][2 * np],     al[1], bq[0], bq[1]);
                MMA16816H(acc[0][2 * np + 1], al[0], bq[2], bq[3]);
                MMA16816H(acc[1][2 * np + 1], al[1], bq[2], bq[3]);
            }
        }
    }

    #pragma unroll
    for (int mt = 0; mt < 2; ++mt) {
        #pragma unroll
        for (int nt = 0; nt < 8; ++nt) {
            int row = m0 + wm * 32 + mt * 16 + (lane >> 2);
            int col = n0 + wn * 64 + nt * 8 + (lane & 3) * 2;
            float2 v0 = make_float2(acc[mt][nt][0], acc[mt][nt][1]);
            float2 v1 = make_float2(acc[mt][nt][2], acc[mt][nt][3]);
            *reinterpret_cast<float2*>(&C[(size_t)row * N + col]) = v0;
            *reinterpret_cast<float2*>(&C[(size_t)(row + 8) * N + col]) = v1;
        }
    }
}

// ---------------------------------------------------------------------------
// Attention (unchanged from Round 10): pre-split bf16 hi/lo QKV via cp.async;
// bf16x3 MMA; epilogue writes fp16 hi/lo for the fp16x2 output projection.
// ---------------------------------------------------------------------------
#define ATT_T 8192

__global__ __launch_bounds__(128, 4)
void attn_tc_kernel(const __nv_bfloat16* __restrict__ qh,
                    const __nv_bfloat16* __restrict__ ql,
                    __half* __restrict__ out_hi,
                    __half* __restrict__ out_lo) {
    extern __shared__ char smb[];
    const uint32_t sb  = smem_u32(smb);
    const uint32_t sQH = sb,            sQL = sb + ATT_T;
    const uint32_t sKH = sb + 2 * ATT_T, sKL = sb + 3 * ATT_T;
    const uint32_t sVH = sb + 4 * ATT_T, sVL = sb + 5 * ATT_T;

    const int tid  = threadIdx.x;
    const int lane = tid & 31;
    const int warp = tid >> 5;
    const int q0 = blockIdx.x * 64;
    const int h  = blockIdx.y;
    const int b  = blockIdx.z;
    const int hoff = h * DH;
    const size_t rbase = (size_t)b * T_SEQ;

    #pragma unroll
    for (int i = 0; i < 4; i++) {
        int cg  = tid + i * 128;
        int row = cg >> 3;
        int ck  = cg & 7;
        uint32_t so = SWZ128((uint32_t)(row * 128 + ck * 16));
        size_t g = (rbase + q0 + row) * N_QKV + hoff + ck * 8;
        CP16(sQH + so, qh + g);
        CP16(sQL + so, ql + g);
    }
    CP_COMMIT();

    float sa[8][4];
    float o[8][4];
    #pragma unroll
    for (int t = 0; t < 8; t++)
        #pragma unroll
        for (int j = 0; j < 4; j++) o[t][j] = 0.f;
    float m0 = -1e20f, m1 = -1e20f, l0 = 0.f, l1 = 0.f;

    const int lane2 = (lane & 3) * 2;
    const int qrow  = warp * 16 + (lane >> 2);
    const int qg0   = q0 + qrow;

    const int a_r = warp * 16 + (lane & 15);
    const int a_c = (lane >> 4) << 4;
    const int b_r = (lane & 7) + ((lane >> 4) << 3);
    const int b_c = ((lane >> 3) & 1) << 4;
    const int v_r = lane & 15;
    const int v_c = (lane >> 4) << 4;

    for (int c = 0; c < 5; c++) {
        const int kb = q0 - WIN + c * 64;
        __syncthreads();
        #pragma unroll
        for (int i = 0; i < 4; i++) {
            int cg  = tid + i * 128;
            int row = cg >> 3;
            int ck  = cg & 7;
            int kg  = kb + row;
            uint32_t sz = (kg >= 0) ? 16u : 0u;
            int kgc = kg >= 0 ? kg : 0;
            uint32_t so = SWZ128((uint32_t)(row * 128 + ck * 16));
            size_t gk = (rbase + kgc) * N_QKV + DM + hoff + ck * 8;
            size_t gv = gk + DM;
            CP16Z(sKH + so, qh + gk, sz);
            CP16Z(sKL + so, ql + gk, sz);
            CP16Z(sVH + so, qh + gv, sz);
            CP16Z(sVL + so, ql + gv, sz);
        }
        CP_COMMIT();
        CP_WAIT(0);
        __syncthreads();

        #pragma unroll
        for (int t = 0; t < 8; t++)
            #pragma unroll
            for (int j = 0; j < 4; j++) sa[t][j] = 0.f;

        #pragma unroll
        for (int ks = 0; ks < 4; ks++) {
            uint32_t ah[4], al[4];
            uint32_t ao = SWZ128((uint32_t)(a_r * 128 + ks * 32 + a_c));
            LDM4(ah, sQH + ao);
            LDM4(al, sQL + ao);
            #pragma unroll
            for (int np = 0; np < 4; np++) {
                uint32_t bo = SWZ128((uint32_t)((np * 16 + b_r) * 128 + ks * 32 + b_c));
                uint32_t bh[4], bl[4];
                LDM4(bh, sKH + bo);
                LDM4(bl, sKL + bo);
                MMA16816(sa[2 * np],     ah, bh[0], bh[1]);
                MMA16816(sa[2 * np + 1], ah, bh[2], bh[3]);
                MMA16816(sa[2 * np],     ah, bl[0], bl[1]);
                MMA16816(sa[2 * np + 1], ah, bl[2], bl[3]);
                MMA16816(sa[2 * np],     al, bh[0], bh[1]);
                MMA16816(sa[2 * np + 1], al, bh[2], bh[3]);
            }
        }

        float mx0 = -1e30f, mx1 = -1e30f;
        #pragma unroll
        for (int t = 0; t < 8; t++) {
            #pragma unroll
            for (int j = 0; j < 4; j++) {
                int col = t * 8 + lane2 + (j & 1);
                int kg  = kb + col;
                int qg  = qg0 + ((j >> 1) << 3);
                bool valid = (kg >= 0) && (kg <= qg) && (kg >= qg - WIN);
                float s = valid ? sa[t][j] * 0.125f : -1e30f;
                sa[t][j] = s;
                if (j < 2) mx0 = fmaxf(mx0, s); else mx1 = fmaxf(mx1, s);
            }
        }
        mx0 = fmaxf(mx0, __shfl_xor_sync(0xffffffffu, mx0, 1));
        mx0 = fmaxf(mx0, __shfl_xor_sync(0xffffffffu, mx0, 2));
        mx1 = fmaxf(mx1, __shfl_xor_sync(0xffffffffu, mx1, 1));
        mx1 = fmaxf(mx1, __shfl_xor_sync(0xffffffffu, mx1, 2));

        const float mn0 = fmaxf(m0, mx0);
        const float mn1 = fmaxf(m1, mx1);
        const float sc0 = __expf(m0 - mn0);
        const float sc1 = __expf(m1 - mn1);
        m0 = mn0; m1 = mn1;

        float ps0 = 0.f, ps1 = 0.f;
        #pragma unroll
        for (int t = 0; t < 8; t++) {
            float p0 = __expf(sa[t][0] - mn0);
            float p1 = __expf(sa[t][1] - mn0);
            float p2 = __expf(sa[t][2] - mn1);
            float p3 = __expf(sa[t][3] - mn1);
            sa[t][0] = p0; sa[t][1] = p1; sa[t][2] = p2; sa[t][3] = p3;
            ps0 += p0 + p1; ps1 += p2 + p3;
        }
        ps0 += __shfl_xor_sync(0xffffffffu, ps0, 1);
        ps0 += __shfl_xor_sync(0xffffffffu, ps0, 2);
        ps1 += __shfl_xor_sync(0xffffffffu, ps1, 1);
        ps1 += __shfl_xor_sync(0xffffffffu, ps1, 2);
        l0 = l0 * sc0 + ps0;
        l1 = l1 * sc1 + ps1;

        #pragma unroll
        for (int t = 0; t < 8; t++) {
            o[t][0] *= sc0; o[t][1] *= sc0;
            o[t][2] *= sc1; o[t][3] *= sc1;
        }

        #pragma unroll
        for (int s = 0; s < 4; s++) {
            uint32_t aph[4], apl[4];
            pack2_hilo(sa[2 * s][0],     sa[2 * s][1],     aph[0], apl[0]);
            pack2_hilo(sa[2 * s][2],     sa[2 * s][3],     aph[1], apl[1]);
            pack2_hilo(sa[2 * s + 1][0], sa[2 * s + 1][1], aph[2], apl[2]);
            pack2_hilo(sa[2 * s + 1][2], sa[2 * s + 1][3], aph[3], apl[3]);
            #pragma unroll
            for (int nd = 0; nd < 4; nd++) {
                uint32_t vo = SWZ128((uint32_t)((s * 16 + v_r) * 128 + nd * 32 + v_c));
                uint32_t vh[4], vl[4];
                LDM4T(vh, sVH + vo);
                LDM4T(vl, sVL + vo);
                MMA16816(o[2 * nd],     aph, vh[0], vh[1]);
                MMA16816(o[2 * nd + 1], aph, vh[2], vh[3]);
                MMA16816(o[2 * nd],     aph, vl[0], vl[1]);
                MMA16816(o[2 * nd + 1], aph, vl[2], vl[3]);
                MMA16816(o[2 * nd],     apl, vh[0], vh[1]);
                MMA16816(o[2 * nd + 1], apl, vh[2], vh[3]);
            }
        }
    }

    const float il0 = 1.f / l0;
    const float il1 = 1.f / l1;
    const size_t row0 = rbase + qg0;
    #pragma unroll
    for (int t = 0; t < 8; t++) {
        int col = hoff + t * 8 + lane2;
        uint32_t h0, lo0, h1, lo1;
        pack2_hilo_h(o[t][0] * il0, o[t][1] * il0, h0, lo0);
        pack2_hilo_h(o[t][2] * il1, o[t][3] * il1, h1, lo1);
        *reinterpret_cast<uint32_t*>(&out_hi[row0 * DM + col])       = h0;
        *reinterpret_cast<uint32_t*>(&out_lo[row0 * DM + col])       = lo0;
        *reinterpret_cast<uint32_t*>(&out_hi[(row0 + 8) * DM + col]) = h1;
        *reinterpret_cast<uint32_t*>(&out_lo[(row0 + 8) * DM + col]) = lo1;
    }
}

// ---------------------------------------------------------------------------
extern "C" void kernel_launch(void* const* d_in, const int* in_sizes, int n_in,
                              void* d_out, int out_size) {
    const float* x     = (const float*)d_in[0];
    const float* w_qkv = (const float*)d_in[1];
    const float* w_out = (const float*)d_in[2];
    float* out = (float*)d_out;

    __half *x16, *wq16, *wo16, *at16_hi, *at16_lo;
    __nv_bfloat16 *qkv_hi, *qkv_lo;
    cudaGetSymbolAddress((void**)&x16,     g_x16);
    cudaGetSymbolAddress((void**)&wq16,    g_wqkvT16);
    cudaGetSymbolAddress((void**)&wo16,    g_woutT16);
    cudaGetSymbolAddress((void**)&qkv_hi,  g_qkv_hi);
    cudaGetSymbolAddress((void**)&qkv_lo,  g_qkv_lo);
    cudaGetSymbolAddress((void**)&at16_hi, g_att16_hi);
    cudaGetSymbolAddress((void**)&at16_lo, g_att16_lo);

    cudaFuncSetAttribute(gemm_f16x1, cudaFuncAttributeMaxDynamicSharedMemorySize, GEMM1_SMEM);
    cudaFuncSetAttribute(gemm_f16x2, cudaFuncAttributeMaxDynamicSharedMemorySize, GEMM2_SMEM);
    const int ATTN_SMEM = 6 * ATT_T;
    cudaFuncSetAttribute(attn_tc_kernel, cudaFuncAttributeMaxDynamicSharedMemorySize, ATTN_SMEM);

    // 0) prep: x -> fp16; w_qkv, w_out -> [N][K] fp16
    {
        int n4 = M_ROWS * DM / 4;
        cvt_f16_kernel<<<(n4 + 255) / 256, 256>>>(x, x16, n4);
        dim3 g1(N_QKV / 32, DM / 32);
        transpose_f16_kernel<<<g1, 256>>>(w_qkv, wq16, DM, N_QKV);
        dim3 g2(DM / 32, DM / 32);
        transpose_f16_kernel<<<g2, 256>>>(w_out, wo16, DM, DM);
    }
    // 1) QKV projection (fp16 single-term) -> pre-split bf16 hi/lo
    {
        dim3 grid(N_QKV / BN, M_ROWS / BM);
        gemm_f16x1<<<grid, 256, GEMM1_SMEM>>>(x16, wq16, qkv_hi, qkv_lo,
                                              M_ROWS, N_QKV, DM);
    }
    // 2) attention -> fp16 hi/lo
    {
        dim3 grid(T_SEQ / 64, NH, B_SZ);
        attn_tc_kernel<<<grid, 128, ATTN_SMEM>>>(qkv_hi, qkv_lo, at16_hi, at16_lo);
    }
    // 3) output projection (fp16x2) -> fp32
    {
        dim3 grid(DM / BN, M_ROWS / BM);
        gemm_f16x2<<<grid, 256, GEMM2_SMEM>>>(at16_hi, at16_lo, wo16,
                                              out, M_ROWS, DM, DM);
    }
}

// round 12
// speedup vs baseline: 2.1257x; 1.1726x over previous
#include <cuda_runtime.h>
#include <cuda_bf16.h>
#include <cuda_fp16.h>
#include <math.h>
#include <stdint.h>

// Problem constants
#define B_SZ   4
#define T_SEQ  2048
#define DM     1024
#define NH     16
#define DH     64
#define WIN    256
#define M_ROWS (B_SZ * T_SEQ)        // 8192
#define N_QKV  (3 * DM)              // 3072

// fp16x1 GEMM tiling: 128x128x64 K-tiles, 128B smem rows, 3-stage ring
#define BM 128
#define BN 128
#define BKK 64
#define TILE_B (BM * 128)             // 16384 B per tile (128 rows x 128 B)
#define NSTAGE 3
#define STG_B (2 * TILE_B)            // 32768 B (A + B)
#define GEMM_SMEM (NSTAGE * STG_B + 128)

// ---------------------------------------------------------------------------
// Device scratch (allocation-free per harness rules)
// ---------------------------------------------------------------------------
__device__ __align__(16) __half g_x16[M_ROWS * (size_t)DM];
__device__ __align__(16) __half g_wqkvT16[N_QKV * (size_t)DM];           // [N][K]
__device__ __align__(16) __half g_woutT16[DM * (size_t)DM];              // [N][K]
__device__ __align__(16) __nv_bfloat16 g_qkv_hi[M_ROWS * (size_t)N_QKV]; // pre-split QKV
__device__ __align__(16) __nv_bfloat16 g_qkv_lo[M_ROWS * (size_t)N_QKV];
__device__ __align__(16) __half g_att16[M_ROWS * (size_t)DM];            // attention out (fp16)

// ---------------------------------------------------------------------------
// Helpers
// ---------------------------------------------------------------------------
__device__ __forceinline__ uint32_t smem_u32(const void* p) {
    return (uint32_t)__cvta_generic_to_shared(p);
}

#define CP16(saddr, gptr) \
    asm volatile("cp.async.cg.shared.global [%0], [%1], 16;" :: "r"(saddr), "l"(gptr))
#define CP16Z(saddr, gptr, sz) \
    asm volatile("cp.async.cg.shared.global [%0], [%1], 16, %2;" \
        :: "r"(saddr), "l"(gptr), "r"(sz))
#define CP_COMMIT() asm volatile("cp.async.commit_group;")
#define CP_WAIT(n)  asm volatile("cp.async.wait_group %0;" :: "n"(n))

#define LDM4(r, addr) \
    asm volatile("ldmatrix.sync.aligned.m8n8.x4.shared.b16 {%0,%1,%2,%3}, [%4];" \
        : "=r"((r)[0]), "=r"((r)[1]), "=r"((r)[2]), "=r"((r)[3]) : "r"(addr))

#define LDM4T(r, addr) \
    asm volatile("ldmatrix.sync.aligned.m8n8.x4.trans.shared.b16 {%0,%1,%2,%3}, [%4];" \
        : "=r"((r)[0]), "=r"((r)[1]), "=r"((r)[2]), "=r"((r)[3]) : "r"(addr))

#define MMA16816(d, a, b0, b1) \
    asm volatile("mma.sync.aligned.m16n8k16.row.col.f32.bf16.bf16.f32 " \
        "{%0,%1,%2,%3}, {%4,%5,%6,%7}, {%8,%9}, {%0,%1,%2,%3};" \
        : "+f"((d)[0]), "+f"((d)[1]), "+f"((d)[2]), "+f"((d)[3]) \
        : "r"((a)[0]), "r"((a)[1]), "r"((a)[2]), "r"((a)[3]), "r"(b0), "r"(b1))

#define MMA16816H(d, a, b0, b1) \
    asm volatile("mma.sync.aligned.m16n8k16.row.col.f32.f16.f16.f32 " \
        "{%0,%1,%2,%3}, {%4,%5,%6,%7}, {%8,%9}, {%0,%1,%2,%3};" \
        : "+f"((d)[0]), "+f"((d)[1]), "+f"((d)[2]), "+f"((d)[3]) \
        : "r"((a)[0]), "r"((a)[1]), "r"((a)[2]), "r"((a)[3]), "r"(b0), "r"(b1))

// 128B-row swizzle: 16B-chunk index XORed with (row & 7)
#define SWZ128(off) ((off) ^ ((((off) >> 7) & 7u) << 4))

__device__ __forceinline__ void split_f32(float f, __nv_bfloat16& hi, __nv_bfloat16& lo) {
    hi = __float2bfloat16_rn(f);
    lo = __float2bfloat16_rn(f - __bfloat162float(hi));
}

__device__ __forceinline__ void pack2_hilo(float x, float y, uint32_t& h, uint32_t& l) {
    __nv_bfloat162 hv, lv;
    split_f32(x, hv.x, lv.x);
    split_f32(y, hv.y, lv.y);
    h = *reinterpret_cast<uint32_t*>(&hv);
    l = *reinterpret_cast<uint32_t*>(&lv);
}

// ---------------------------------------------------------------------------
// prep kernels
// ---------------------------------------------------------------------------
__global__ void cvt_f16_kernel(const float* __restrict__ src,
                               __half* __restrict__ dst, int n4) {
    int i = blockIdx.x * blockDim.x + threadIdx.x;
    if (i >= n4) return;
    float4 f = reinterpret_cast<const float4*>(src)[i];
    __half2 a = __half2(__float2half_rn(f.x), __float2half_rn(f.y));
    __half2 b = __half2(__float2half_rn(f.z), __float2half_rn(f.w));
    __half2* dp = reinterpret_cast<__half2*>(dst) + i * 2;
    dp[0] = a; dp[1] = b;
}

__global__ void transpose_f16_kernel(const float* __restrict__ src,
                                     __half* __restrict__ dst, int K, int N) {
    __shared__ float t[32][33];
    const int n0 = blockIdx.x * 32;
    const int k0 = blockIdx.y * 32;
    const int tx = threadIdx.x & 31;
    const int ty = threadIdx.x >> 5;
    #pragma unroll
    for (int i = 0; i < 32; i += 8)
        t[ty + i][tx] = src[(size_t)(k0 + ty + i) * N + n0 + tx];
    __syncthreads();
    #pragma unroll
    for (int i = 0; i < 32; i += 8)
        dst[(size_t)(n0 + ty + i) * K + k0 + tx] = __float2half_rn(t[tx][ty + i]);
}

// ---------------------------------------------------------------------------
// fp16x1 GEMM: C = A16 @ B16^T (Bt is [N][K]), single-rounded fp16 operands.
// 128x128x64 K-tiles, 8 warps (4M x 2N of 32x64), 3-stage ring, one sync/tile.
// Epilogue: Chi!=null -> bf16 hi/lo splits; else fp32 C.
// ---------------------------------------------------------------------------
__global__ __launch_bounds__(256, 2)
void gemm_f16(const __half* __restrict__ A16, const __half* __restrict__ Bq,
              float* __restrict__ C,
              __nv_bfloat16* __restrict__ Chi, __nv_bfloat16* __restrict__ Clo,
              int M, int N, int K) {
    extern __shared__ char smraw[];
    const uint32_t sbase = (smem_u32(smraw) + 127) & ~127u;

    const int tid  = threadIdx.x;
    const int lane = tid & 31;
    const int warp = tid >> 5;
    const int wm   = warp & 3;
    const int wn   = warp >> 2;
    const int m0   = blockIdx.y * BM;
    const int n0   = blockIdx.x * BN;

    float acc[2][8][4];
    #pragma unroll
    for (int a = 0; a < 2; a++)
        #pragma unroll
        for (int b = 0; b < 8; b++)
            #pragma unroll
            for (int c = 0; c < 4; c++) acc[a][b][c] = 0.f;

    const int NK = K / BKK;   // 16

    // loader: A 1024 + B 1024 16B-chunks; 8 per thread
    auto load_stage = [&](int buf, int kt) {
        const uint32_t s = sbase + buf * STG_B;
        const int kg = kt * BKK;
        #pragma unroll
        for (int i = 0; i < 4; ++i) {
            int cg  = tid + i * 256;
            int row = cg >> 3;
            int ck  = cg & 7;
            uint32_t so = SWZ128((uint32_t)(row * 128 + ck * 16));
            size_t ka = (size_t)kg + ck * 8;
            CP16(s + so,          A16 + (size_t)(m0 + row) * K + ka);
            CP16(s + TILE_B + so, Bq  + (size_t)(n0 + row) * K + ka);
        }
    };

    load_stage(0, 0); CP_COMMIT();
    load_stage(1, 1); CP_COMMIT();

    const int a_r = wm * 32 + (lane & 15);
    const int a_c = (lane >> 4) << 4;                 // byte 0/16 within 32B k-step
    const int b_r = wn * 64 + (lane & 7) + ((lane >> 4) << 3);
    const int b_c = ((lane >> 3) & 1) << 4;

    for (int kt = 0; kt < NK; ++kt) {
        if (kt + 1 < NK) { CP_WAIT(1); } else { CP_WAIT(0); }
        __syncthreads();
        if (kt + 2 < NK) {
            load_stage((kt + 2) % NSTAGE, kt + 2);
            CP_COMMIT();
        }

        const uint32_t s = sbase + (kt % NSTAGE) * STG_B;
        #pragma unroll
        for (int ks = 0; ks < 4; ++ks) {              // 4 k-steps of 16
            uint32_t ah[2][4];
            #pragma unroll
            for (int mt = 0; mt < 2; ++mt) {
                uint32_t ro = SWZ128((uint32_t)((a_r + mt * 16) * 128 + ks * 32 + a_c));
                LDM4(ah[mt], s + ro);
            }
            #pragma unroll
            for (int np = 0; np < 4; ++np) {
                uint32_t ro = SWZ128((uint32_t)((b_r + np * 16) * 128 + ks * 32 + b_c));
                uint32_t bq[4];
                LDM4(bq, s + TILE_B + ro);
                MMA16816H(acc[0][2 * np],     ah[0], bq[0], bq[1]);
                MMA16816H(acc[1][2 * np],     ah[1], bq[0], bq[1]);
                MMA16816H(acc[0][2 * np + 1], ah[0], bq[2], bq[3]);
                MMA16816H(acc[1][2 * np + 1], ah[1], bq[2], bq[3]);
            }
        }
    }

    if (Chi != nullptr) {
        #pragma unroll
        for (int mt = 0; mt < 2; ++mt) {
            #pragma unroll
            for (int nt = 0; nt < 8; ++nt) {
                int row = m0 + wm * 32 + mt * 16 + (lane >> 2);
                int col = n0 + wn * 64 + nt * 8 + (lane & 3) * 2;
                uint32_t h0, l0, h1, l1;
                pack2_hilo(acc[mt][nt][0], acc[mt][nt][1], h0, l0);
                pack2_hilo(acc[mt][nt][2], acc[mt][nt][3], h1, l1);
                *reinterpret_cast<uint32_t*>(&Chi[(size_t)row * N + col])       = h0;
                *reinterpret_cast<uint32_t*>(&Clo[(size_t)row * N + col])       = l0;
                *reinterpret_cast<uint32_t*>(&Chi[(size_t)(row + 8) * N + col]) = h1;
                *reinterpret_cast<uint32_t*>(&Clo[(size_t)(row + 8) * N + col]) = l1;
            }
        }
    } else {
        #pragma unroll
        for (int mt = 0; mt < 2; ++mt) {
            #pragma unroll
            for (int nt = 0; nt < 8; ++nt) {
                int row = m0 + wm * 32 + mt * 16 + (lane >> 2);
                int col = n0 + wn * 64 + nt * 8 + (lane & 3) * 2;
                float2 v0 = make_float2(acc[mt][nt][0], acc[mt][nt][1]);
                float2 v1 = make_float2(acc[mt][nt][2], acc[mt][nt][3]);
                *reinterpret_cast<float2*>(&C[(size_t)row * N + col]) = v0;
                *reinterpret_cast<float2*>(&C[(size_t)(row + 8) * N + col]) = v1;
            }
        }
    }
}

// ---------------------------------------------------------------------------
// Attention: pre-split bf16 hi/lo QKV via cp.async; bf16x3 MMA (unchanged);
// epilogue writes SINGLE fp16 (the rounding == GEMM2's A-operand rounding).
// ---------------------------------------------------------------------------
#define ATT_T 8192

__global__ __launch_bounds__(128, 4)
void attn_tc_kernel(const __nv_bfloat16* __restrict__ qh,
                    const __nv_bfloat16* __restrict__ ql,
                    __half* __restrict__ out16) {
    extern __shared__ char smb[];
    const uint32_t sb  = smem_u32(smb);
    const uint32_t sQH = sb,            sQL = sb + ATT_T;
    const uint32_t sKH = sb + 2 * ATT_T, sKL = sb + 3 * ATT_T;
    const uint32_t sVH = sb + 4 * ATT_T, sVL = sb + 5 * ATT_T;

    const int tid  = threadIdx.x;
    const int lane = tid & 31;
    const int warp = tid >> 5;
    const int q0 = blockIdx.x * 64;
    const int h  = blockIdx.y;
    const int b  = blockIdx.z;
    const int hoff = h * DH;
    const size_t rbase = (size_t)b * T_SEQ;

    #pragma unroll
    for (int i = 0; i < 4; i++) {
        int cg  = tid + i * 128;
        int row = cg >> 3;
        int ck  = cg & 7;
        uint32_t so = SWZ128((uint32_t)(row * 128 + ck * 16));
        size_t g = (rbase + q0 + row) * N_QKV + hoff + ck * 8;
        CP16(sQH + so, qh + g);
        CP16(sQL + so, ql + g);
    }
    CP_COMMIT();

    float sa[8][4];
    float o[8][4];
    #pragma unroll
    for (int t = 0; t < 8; t++)
        #pragma unroll
        for (int j = 0; j < 4; j++) o[t][j] = 0.f;
    float m0 = -1e20f, m1 = -1e20f, l0 = 0.f, l1 = 0.f;

    const int lane2 = (lane & 3) * 2;
    const int qrow  = warp * 16 + (lane >> 2);
    const int qg0   = q0 + qrow;

    const int a_r = warp * 16 + (lane & 15);
    const int a_c = (lane >> 4) << 4;
    const int b_r = (lane & 7) + ((lane >> 4) << 3);
    const int b_c = ((lane >> 3) & 1) << 4;
    const int v_r = lane & 15;
    const int v_c = (lane >> 4) << 4;

    for (int c = 0; c < 5; c++) {
        const int kb = q0 - WIN + c * 64;
        __syncthreads();
        #pragma unroll
        for (int i = 0; i < 4; i++) {
            int cg  = tid + i * 128;
            int row = cg >> 3;
            int ck  = cg & 7;
            int kg  = kb + row;
            uint32_t sz = (kg >= 0) ? 16u : 0u;
            int kgc = kg >= 0 ? kg : 0;
            uint32_t so = SWZ128((uint32_t)(row * 128 + ck * 16));
            size_t gk = (rbase + kgc) * N_QKV + DM + hoff + ck * 8;
            size_t gv = gk + DM;
            CP16Z(sKH + so, qh + gk, sz);
            CP16Z(sKL + so, ql + gk, sz);
            CP16Z(sVH + so, qh + gv, sz);
            CP16Z(sVL + so, ql + gv, sz);
        }
        CP_COMMIT();
        CP_WAIT(0);
        __syncthreads();

        #pragma unroll
        for (int t = 0; t < 8; t++)
            #pragma unroll
            for (int j = 0; j < 4; j++) sa[t][j] = 0.f;

        #pragma unroll
        for (int ks = 0; ks < 4; ks++) {
            uint32_t ah[4], al[4];
            uint32_t ao = SWZ128((uint32_t)(a_r * 128 + ks * 32 + a_c));
            LDM4(ah, sQH + ao);
            LDM4(al, sQL + ao);
            #pragma unroll
            for (int np = 0; np < 4; np++) {
                uint32_t bo = SWZ128((uint32_t)((np * 16 + b_r) * 128 + ks * 32 + b_c));
                uint32_t bh[4], bl[4];
                LDM4(bh, sKH + bo);
                LDM4(bl, sKL + bo);
                MMA16816(sa[2 * np],     ah, bh[0], bh[1]);
                MMA16816(sa[2 * np + 1], ah, bh[2], bh[3]);
                MMA16816(sa[2 * np],     ah, bl[0], bl[1]);
                MMA16816(sa[2 * np + 1], ah, bl[2], bl[3]);
                MMA16816(sa[2 * np],     al, bh[0], bh[1]);
                MMA16816(sa[2 * np + 1], al, bh[2], bh[3]);
            }
        }

        float mx0 = -1e30f, mx1 = -1e30f;
        #pragma unroll
        for (int t = 0; t < 8; t++) {
            #pragma unroll
            for (int j = 0; j < 4; j++) {
                int col = t * 8 + lane2 + (j & 1);
                int kg  = kb + col;
                int qg  = qg0 + ((j >> 1) << 3);
                bool valid = (kg >= 0) && (kg <= qg) && (kg >= qg - WIN);
                float s = valid ? sa[t][j] * 0.125f : -1e30f;
                sa[t][j] = s;
                if (j < 2) mx0 = fmaxf(mx0, s); else mx1 = fmaxf(mx1, s);
            }
        }
        mx0 = fmaxf(mx0, __shfl_xor_sync(0xffffffffu, mx0, 1));
        mx0 = fmaxf(mx0, __shfl_xor_sync(0xffffffffu, mx0, 2));
        mx1 = fmaxf(mx1, __shfl_xor_sync(0xffffffffu, mx1, 1));
        mx1 = fmaxf(mx1, __shfl_xor_sync(0xffffffffu, mx1, 2));

        const float mn0 = fmaxf(m0, mx0);
        const float mn1 = fmaxf(m1, mx1);
        const float sc0 = __expf(m0 - mn0);
        const float sc1 = __expf(m1 - mn1);
        m0 = mn0; m1 = mn1;

        float ps0 = 0.f, ps1 = 0.f;
        #pragma unroll
        for (int t = 0; t < 8; t++) {
            float p0 = __expf(sa[t][0] - mn0);
            float p1 = __expf(sa[t][1] - mn0);
            float p2 = __expf(sa[t][2] - mn1);
            float p3 = __expf(sa[t][3] - mn1);
            sa[t][0] = p0; sa[t][1] = p1; sa[t][2] = p2; sa[t][3] = p3;
            ps0 += p0 + p1; ps1 += p2 + p3;
        }
        ps0 += __shfl_xor_sync(0xffffffffu, ps0, 1);
        ps0 += __shfl_xor_sync(0xffffffffu, ps0, 2);
        ps1 += __shfl_xor_sync(0xffffffffu, ps1, 1);
        ps1 += __shfl_xor_sync(0xffffffffu, ps1, 2);
        l0 = l0 * sc0 + ps0;
        l1 = l1 * sc1 + ps1;

        #pragma unroll
        for (int t = 0; t < 8; t++) {
            o[t][0] *= sc0; o[t][1] *= sc0;
            o[t][2] *= sc1; o[t][3] *= sc1;
        }

        #pragma unroll
        for (int s = 0; s < 4; s++) {
            uint32_t aph[4], apl[4];
            pack2_hilo(sa[2 * s][0],     sa[2 * s][1],     aph[0], apl[0]);
            pack2_hilo(sa[2 * s][2],     sa[2 * s][3],     aph[1], apl[1]);
            pack2_hilo(sa[2 * s + 1][0], sa[2 * s + 1][1], aph[2], apl[2]);
            pack2_hilo(sa[2 * s + 1][2], sa[2 * s + 1][3], aph[3], apl[3]);
            #pragma unroll
            for (int nd = 0; nd < 4; nd++) {
                uint32_t vo = SWZ128((uint32_t)((s * 16 + v_r) * 128 + nd * 32 + v_c));
                uint32_t vh[4], vl[4];
                LDM4T(vh, sVH + vo);
                LDM4T(vl, sVL + vo);
                MMA16816(o[2 * nd],     aph, vh[0], vh[1]);
                MMA16816(o[2 * nd + 1], aph, vh[2], vh[3]);
                MMA16816(o[2 * nd],     aph, vl[0], vl[1]);
                MMA16816(o[2 * nd + 1], aph, vl[2], vl[3]);
                MMA16816(o[2 * nd],     apl, vh[0], vh[1]);
                MMA16816(o[2 * nd + 1], apl, vh[2], vh[3]);
            }
        }
    }

    // epilogue: normalize, single fp16 store
    const float il0 = 1.f / l0;
    const float il1 = 1.f / l1;
    const size_t row0 = rbase + qg0;
    #pragma unroll
    for (int t = 0; t < 8; t++) {
        int col = hoff + t * 8 + lane2;
        __half2 h0 = __half2(__float2half_rn(o[t][0] * il0), __float2half_rn(o[t][1] * il0));
        __half2 h1 = __half2(__float2half_rn(o[t][2] * il1), __float2half_rn(o[t][3] * il1));
        *reinterpret_cast<__half2*>(&out16[row0 * DM + col])       = h0;
        *reinterpret_cast<__half2*>(&out16[(row0 + 8) * DM + col]) = h1;
    }
}

// ---------------------------------------------------------------------------
extern "C" void kernel_launch(void* const* d_in, const int* in_sizes, int n_in,
                              void* d_out, int out_size) {
    const float* x     = (const float*)d_in[0];
    const float* w_qkv = (const float*)d_in[1];
    const float* w_out = (const float*)d_in[2];
    float* out = (float*)d_out;

    __half *x16, *wq16, *wo16, *at16;
    __nv_bfloat16 *qkv_hi, *qkv_lo;
    cudaGetSymbolAddress((void**)&x16,    g_x16);
    cudaGetSymbolAddress((void**)&wq16,   g_wqkvT16);
    cudaGetSymbolAddress((void**)&wo16,   g_woutT16);
    cudaGetSymbolAddress((void**)&qkv_hi, g_qkv_hi);
    cudaGetSymbolAddress((void**)&qkv_lo, g_qkv_lo);
    cudaGetSymbolAddress((void**)&at16,   g_att16);

    cudaFuncSetAttribute(gemm_f16, cudaFuncAttributeMaxDynamicSharedMemorySize, GEMM_SMEM);
    const int ATTN_SMEM = 6 * ATT_T;
    cudaFuncSetAttribute(attn_tc_kernel, cudaFuncAttributeMaxDynamicSharedMemorySize, ATTN_SMEM);

    // 0) prep: x -> fp16; w_qkv, w_out -> [N][K] fp16
    {
        int n4 = M_ROWS * DM / 4;
        cvt_f16_kernel<<<(n4 + 255) / 256, 256>>>(x, x16, n4);
        dim3 g1(N_QKV / 32, DM / 32);
        transpose_f16_kernel<<<g1, 256>>>(w_qkv, wq16, DM, N_QKV);
        dim3 g2(DM / 32, DM / 32);
        transpose_f16_kernel<<<g2, 256>>>(w_out, wo16, DM, DM);
    }
    // 1) QKV projection (fp16x1, BKK=64) -> pre-split bf16 hi/lo
    {
        dim3 grid(N_QKV / BN, M_ROWS / BM);
        gemm_f16<<<grid, 256, GEMM_SMEM>>>(x16, wq16, nullptr, qkv_hi, qkv_lo,
                                           M_ROWS, N_QKV, DM);
    }
    // 2) attention -> single fp16
    {
        dim3 grid(T_SEQ / 64, NH, B_SZ);
        attn_tc_kernel<<<grid, 128, ATTN_SMEM>>>(qkv_hi, qkv_lo, at16);
    }
    // 3) output projection (fp16x1, BKK=64) -> fp32
    {
        dim3 grid(DM / BN, M_ROWS / BM);
        gemm_f16<<<grid, 256, GEMM_SMEM>>>(at16, wo16, out, nullptr, nullptr,
                                           M_ROWS, DM, DM);
    }
}

// round 13
// speedup vs baseline: 2.3031x; 1.0834x over previous
#include <cuda_runtime.h>
#include <cuda_bf16.h>
#include <cuda_fp16.h>
#include <math.h>
#include <stdint.h>

// Problem constants
#define B_SZ   4
#define T_SEQ  2048
#define DM     1024
#define NH     16
#define DH     64
#define WIN    256
#define M_ROWS (B_SZ * T_SEQ)        // 8192
#define N_QKV  (3 * DM)              // 3072

// fp16x1 GEMM tiling: 128x128x64 K-tiles, 128B smem rows, 3-stage ring
#define BM 128
#define BN 128
#define BKK 64
#define TILE_B (BM * 128)             // 16384 B per tile
#define NSTAGE 3
#define STG_B (2 * TILE_B)            // 32768 B (A + B)
#define GEMM_SMEM (NSTAGE * STG_B + 128)

// ---------------------------------------------------------------------------
// Device scratch (allocation-free per harness rules)
// ---------------------------------------------------------------------------
__device__ __align__(16) __half g_x16[M_ROWS * (size_t)DM];
__device__ __align__(16) __half g_wqkvT16[N_QKV * (size_t)DM];         // [N][K]
__device__ __align__(16) __half g_woutT16[DM * (size_t)DM];            // [N][K]
__device__ __align__(16) __half g_qkv16_hi[M_ROWS * (size_t)N_QKV];    // fp16 split QKV
__device__ __align__(16) __half g_qkv16_lo[M_ROWS * (size_t)N_QKV];
__device__ __align__(16) __half g_att16[M_ROWS * (size_t)DM];          // attention out

// ---------------------------------------------------------------------------
// Helpers
// ---------------------------------------------------------------------------
__device__ __forceinline__ uint32_t smem_u32(const void* p) {
    return (uint32_t)__cvta_generic_to_shared(p);
}

#define CP16(saddr, gptr) \
    asm volatile("cp.async.cg.shared.global [%0], [%1], 16;" :: "r"(saddr), "l"(gptr))
#define CP16Z(saddr, gptr, sz) \
    asm volatile("cp.async.cg.shared.global [%0], [%1], 16, %2;" \
        :: "r"(saddr), "l"(gptr), "r"(sz))
#define CP_COMMIT() asm volatile("cp.async.commit_group;")
#define CP_WAIT(n)  asm volatile("cp.async.wait_group %0;" :: "n"(n))

#define LDM4(r, addr) \
    asm volatile("ldmatrix.sync.aligned.m8n8.x4.shared.b16 {%0,%1,%2,%3}, [%4];" \
        : "=r"((r)[0]), "=r"((r)[1]), "=r"((r)[2]), "=r"((r)[3]) : "r"(addr))

#define LDM4T(r, addr) \
    asm volatile("ldmatrix.sync.aligned.m8n8.x4.trans.shared.b16 {%0,%1,%2,%3}, [%4];" \
        : "=r"((r)[0]), "=r"((r)[1]), "=r"((r)[2]), "=r"((r)[3]) : "r"(addr))

#define MMA16816H(d, a, b0, b1) \
    asm volatile("mma.sync.aligned.m16n8k16.row.col.f32.f16.f16.f32 " \
        "{%0,%1,%2,%3}, {%4,%5,%6,%7}, {%8,%9}, {%0,%1,%2,%3};" \
        : "+f"((d)[0]), "+f"((d)[1]), "+f"((d)[2]), "+f"((d)[3]) \
        : "r"((a)[0]), "r"((a)[1]), "r"((a)[2]), "r"((a)[3]), "r"(b0), "r"(b1))

// 128B-row swizzle: 16B-chunk index XORed with (row & 7)
#define SWZ128(off) ((off) ^ ((((off) >> 7) & 7u) << 4))

__device__ __forceinline__ void split_f32h(float f, __half& hi, __half& lo) {
    hi = __float2half_rn(f);
    lo = __float2half_rn(f - __half2float(hi));
}
__device__ __forceinline__ void pack2_hilo_h(float x, float y, uint32_t& h, uint32_t& l) {
    __half2 hv, lv;
    split_f32h(x, hv.x, lv.x);
    split_f32h(y, hv.y, lv.y);
    h = *reinterpret_cast<uint32_t*>(&hv);
    l = *reinterpret_cast<uint32_t*>(&lv);
}

// ---------------------------------------------------------------------------
// prep kernels
// ---------------------------------------------------------------------------
__global__ void cvt_f16_kernel(const float* __restrict__ src,
                               __half* __restrict__ dst, int n4) {
    int i = blockIdx.x * blockDim.x + threadIdx.x;
    if (i >= n4) return;
    float4 f = reinterpret_cast<const float4*>(src)[i];
    __half2 a = __half2(__float2half_rn(f.x), __float2half_rn(f.y));
    __half2 b = __half2(__float2half_rn(f.z), __float2half_rn(f.w));
    __half2* dp = reinterpret_cast<__half2*>(dst) + i * 2;
    dp[0] = a; dp[1] = b;
}

__global__ void transpose_f16_kernel(const float* __restrict__ src,
                                     __half* __restrict__ dst, int K, int N) {
    __shared__ float t[32][33];
    const int n0 = blockIdx.x * 32;
    const int k0 = blockIdx.y * 32;
    const int tx = threadIdx.x & 31;
    const int ty = threadIdx.x >> 5;
    #pragma unroll
    for (int i = 0; i < 32; i += 8)
        t[ty + i][tx] = src[(size_t)(k0 + ty + i) * N + n0 + tx];
    __syncthreads();
    #pragma unroll
    for (int i = 0; i < 32; i += 8)
        dst[(size_t)(n0 + ty + i) * K + k0 + tx] = __float2half_rn(t[tx][ty + i]);
}

// ---------------------------------------------------------------------------
// fp16x1 GEMM: C = A16 @ B16^T (Bt is [N][K]).
// 128x128x64 K-tiles, 8 warps (4M x 2N), 3-stage ring, one sync/tile.
// Epilogue: Chi!=null -> fp16 hi/lo splits; else fp32 C.
// ---------------------------------------------------------------------------
__global__ __launch_bounds__(256, 2)
void gemm_f16(const __half* __restrict__ A16, const __half* __restrict__ Bq,
              float* __restrict__ C,
              __half* __restrict__ Chi, __half* __restrict__ Clo,
              int M, int N, int K) {
    extern __shared__ char smraw[];
    const uint32_t sbase = (smem_u32(smraw) + 127) & ~127u;

    const int tid  = threadIdx.x;
    const int lane = tid & 31;
    const int warp = tid >> 5;
    const int wm   = warp & 3;
    const int wn   = warp >> 2;
    const int m0   = blockIdx.y * BM;
    const int n0   = blockIdx.x * BN;

    float acc[2][8][4];
    #pragma unroll
    for (int a = 0; a < 2; a++)
        #pragma unroll
        for (int b = 0; b < 8; b++)
            #pragma unroll
            for (int c = 0; c < 4; c++) acc[a][b][c] = 0.f;

    const int NK = K / BKK;

    auto load_stage = [&](int buf, int kt) {
        const uint32_t s = sbase + buf * STG_B;
        const int kg = kt * BKK;
        #pragma unroll
        for (int i = 0; i < 4; ++i) {
            int cg  = tid + i * 256;
            int row = cg >> 3;
            int ck  = cg & 7;
            uint32_t so = SWZ128((uint32_t)(row * 128 + ck * 16));
            size_t ka = (size_t)kg + ck * 8;
            CP16(s + so,          A16 + (size_t)(m0 + row) * K + ka);
            CP16(s + TILE_B + so, Bq  + (size_t)(n0 + row) * K + ka);
        }
    };

    load_stage(0, 0); CP_COMMIT();
    load_stage(1, 1); CP_COMMIT();

    const int a_r = wm * 32 + (lane & 15);
    const int a_c = (lane >> 4) << 4;
    const int b_r = wn * 64 + (lane & 7) + ((lane >> 4) << 3);
    const int b_c = ((lane >> 3) & 1) << 4;

    for (int kt = 0; kt < NK; ++kt) {
        if (kt + 1 < NK) { CP_WAIT(1); } else { CP_WAIT(0); }
        __syncthreads();
        if (kt + 2 < NK) {
            load_stage((kt + 2) % NSTAGE, kt + 2);
            CP_COMMIT();
        }

        const uint32_t s = sbase + (kt % NSTAGE) * STG_B;
        #pragma unroll
        for (int ks = 0; ks < 4; ++ks) {
            uint32_t ah[2][4];
            #pragma unroll
            for (int mt = 0; mt < 2; ++mt) {
                uint32_t ro = SWZ128((uint32_t)((a_r + mt * 16) * 128 + ks * 32 + a_c));
                LDM4(ah[mt], s + ro);
            }
            #pragma unroll
            for (int np = 0; np < 4; ++np) {
                uint32_t ro = SWZ128((uint32_t)((b_r + np * 16) * 128 + ks * 32 + b_c));
                uint32_t bq[4];
                LDM4(bq, s + TILE_B + ro);
                MMA16816H(acc[0][2 * np],     ah[0], bq[0], bq[1]);
                MMA16816H(acc[1][2 * np],     ah[1], bq[0], bq[1]);
                MMA16816H(acc[0][2 * np + 1], ah[0], bq[2], bq[3]);
                MMA16816H(acc[1][2 * np + 1], ah[1], bq[2], bq[3]);
            }
        }
    }

    if (Chi != nullptr) {
        #pragma unroll
        for (int mt = 0; mt < 2; ++mt) {
            #pragma unroll
            for (int nt = 0; nt < 8; ++nt) {
                int row = m0 + wm * 32 + mt * 16 + (lane >> 2);
                int col = n0 + wn * 64 + nt * 8 + (lane & 3) * 2;
                uint32_t h0, l0, h1, l1;
                pack2_hilo_h(acc[mt][nt][0], acc[mt][nt][1], h0, l0);
                pack2_hilo_h(acc[mt][nt][2], acc[mt][nt][3], h1, l1);
                *reinterpret_cast<uint32_t*>(&Chi[(size_t)row * N + col])       = h0;
                *reinterpret_cast<uint32_t*>(&Clo[(size_t)row * N + col])       = l0;
                *reinterpret_cast<uint32_t*>(&Chi[(size_t)(row + 8) * N + col]) = h1;
                *reinterpret_cast<uint32_t*>(&Clo[(size_t)(row + 8) * N + col]) = l1;
            }
        }
    } else {
        #pragma unroll
        for (int mt = 0; mt < 2; ++mt) {
            #pragma unroll
            for (int nt = 0; nt < 8; ++nt) {
                int row = m0 + wm * 32 + mt * 16 + (lane >> 2);
                int col = n0 + wn * 64 + nt * 8 + (lane & 3) * 2;
                float2 v0 = make_float2(acc[mt][nt][0], acc[mt][nt][1]);
                float2 v1 = make_float2(acc[mt][nt][2], acc[mt][nt][3]);
                *reinterpret_cast<float2*>(&C[(size_t)row * N + col]) = v0;
                *reinterpret_cast<float2*>(&C[(size_t)(row + 8) * N + col]) = v1;
            }
        }
    }
}

// ---------------------------------------------------------------------------
// Attention (fp16 2-term): S = (Qh+Ql)·Kh^T, O = (Ph+Pl)·Vh.
// Q loaded as fp16 hi/lo; K,V use only the hi stream (single-rounded fp16).
// smem: QH, QL, KH, VH = 4 x 8 KB = 32 KB.
// ---------------------------------------------------------------------------
#define ATT_T 8192

__global__ __launch_bounds__(128, 4)
void attn_tc_kernel(const __half* __restrict__ qh,
                    const __half* __restrict__ ql,
                    __half* __restrict__ out16) {
    extern __shared__ char smb[];
    const uint32_t sb  = smem_u32(smb);
    const uint32_t sQH = sb,             sQL = sb + ATT_T;
    const uint32_t sKH = sb + 2 * ATT_T, sVH = sb + 3 * ATT_T;

    const int tid  = threadIdx.x;
    const int lane = tid & 31;
    const int warp = tid >> 5;
    const int q0 = blockIdx.x * 64;
    const int h  = blockIdx.y;
    const int b  = blockIdx.z;
    const int hoff = h * DH;
    const size_t rbase = (size_t)b * T_SEQ;

    // ---- load Q tile hi+lo ----
    #pragma unroll
    for (int i = 0; i < 4; i++) {
        int cg  = tid + i * 128;
        int row = cg >> 3;
        int ck  = cg & 7;
        uint32_t so = SWZ128((uint32_t)(row * 128 + ck * 16));
        size_t g = (rbase + q0 + row) * N_QKV + hoff + ck * 8;
        CP16(sQH + so, qh + g);
        CP16(sQL + so, ql + g);
    }
    CP_COMMIT();

    float sa[8][4];
    float o[8][4];
    #pragma unroll
    for (int t = 0; t < 8; t++)
        #pragma unroll
        for (int j = 0; j < 4; j++) o[t][j] = 0.f;
    float m0 = -1e20f, m1 = -1e20f, l0 = 0.f, l1 = 0.f;

    const int lane2 = (lane & 3) * 2;
    const int qrow  = warp * 16 + (lane >> 2);
    const int qg0   = q0 + qrow;

    const int a_r = warp * 16 + (lane & 15);
    const int a_c = (lane >> 4) << 4;
    const int b_r = (lane & 7) + ((lane >> 4) << 3);
    const int b_c = ((lane >> 3) & 1) << 4;
    const int v_r = lane & 15;
    const int v_c = (lane >> 4) << 4;

    for (int c = 0; c < 5; c++) {
        const int kb = q0 - WIN + c * 64;
        __syncthreads();
        // ---- cp.async K/V chunk (hi stream only; zero-fill kg<0) ----
        #pragma unroll
        for (int i = 0; i < 4; i++) {
            int cg  = tid + i * 128;
            int row = cg >> 3;
            int ck  = cg & 7;
            int kg  = kb + row;
            uint32_t sz = (kg >= 0) ? 16u : 0u;
            int kgc = kg >= 0 ? kg : 0;
            uint32_t so = SWZ128((uint32_t)(row * 128 + ck * 16));
            size_t gk = (rbase + kgc) * N_QKV + DM + hoff + ck * 8;
            CP16Z(sKH + so, qh + gk, sz);
            CP16Z(sVH + so, qh + gk + DM, sz);
        }
        CP_COMMIT();
        CP_WAIT(0);
        __syncthreads();

        // ---- S = (Qh+Ql) Kh^T (2-term fp16) ----
        #pragma unroll
        for (int t = 0; t < 8; t++)
            #pragma unroll
            for (int j = 0; j < 4; j++) sa[t][j] = 0.f;

        #pragma unroll
        for (int ks = 0; ks < 4; ks++) {
            uint32_t ah[4], al[4];
            uint32_t ao = SWZ128((uint32_t)(a_r * 128 + ks * 32 + a_c));
            LDM4(ah, sQH + ao);
            LDM4(al, sQL + ao);
            #pragma unroll
            for (int np = 0; np < 4; np++) {
                uint32_t bo = SWZ128((uint32_t)((np * 16 + b_r) * 128 + ks * 32 + b_c));
                uint32_t bk[4];
                LDM4(bk, sKH + bo);
                MMA16816H(sa[2 * np],     ah, bk[0], bk[1]);
                MMA16816H(sa[2 * np + 1], ah, bk[2], bk[3]);
                MMA16816H(sa[2 * np],     al, bk[0], bk[1]);
                MMA16816H(sa[2 * np + 1], al, bk[2], bk[3]);
            }
        }

        // ---- mask + online softmax ----
        float mx0 = -1e30f, mx1 = -1e30f;
        #pragma unroll
        for (int t = 0; t < 8; t++) {
            #pragma unroll
            for (int j = 0; j < 4; j++) {
                int col = t * 8 + lane2 + (j & 1);
                int kg  = kb + col;
                int qg  = qg0 + ((j >> 1) << 3);
                bool valid = (kg >= 0) && (kg <= qg) && (kg >= qg - WIN);
                float s = valid ? sa[t][j] * 0.125f : -1e30f;
                sa[t][j] = s;
                if (j < 2) mx0 = fmaxf(mx0, s); else mx1 = fmaxf(mx1, s);
            }
        }
        mx0 = fmaxf(mx0, __shfl_xor_sync(0xffffffffu, mx0, 1));
        mx0 = fmaxf(mx0, __shfl_xor_sync(0xffffffffu, mx0, 2));
        mx1 = fmaxf(mx1, __shfl_xor_sync(0xffffffffu, mx1, 1));
        mx1 = fmaxf(mx1, __shfl_xor_sync(0xffffffffu, mx1, 2));

        const float mn0 = fmaxf(m0, mx0);
        const float mn1 = fmaxf(m1, mx1);
        const float sc0 = __expf(m0 - mn0);
        const float sc1 = __expf(m1 - mn1);
        m0 = mn0; m1 = mn1;

        float ps0 = 0.f, ps1 = 0.f;
        #pragma unroll
        for (int t = 0; t < 8; t++) {
            float p0 = __expf(sa[t][0] - mn0);
            float p1 = __expf(sa[t][1] - mn0);
            float p2 = __expf(sa[t][2] - mn1);
            float p3 = __expf(sa[t][3] - mn1);
            sa[t][0] = p0; sa[t][1] = p1; sa[t][2] = p2; sa[t][3] = p3;
            ps0 += p0 + p1; ps1 += p2 + p3;
        }
        ps0 += __shfl_xor_sync(0xffffffffu, ps0, 1);
        ps0 += __shfl_xor_sync(0xffffffffu, ps0, 2);
        ps1 += __shfl_xor_sync(0xffffffffu, ps1, 1);
        ps1 += __shfl_xor_sync(0xffffffffu, ps1, 2);
        l0 = l0 * sc0 + ps0;
        l1 = l1 * sc1 + ps1;

        #pragma unroll
        for (int t = 0; t < 8; t++) {
            o[t][0] *= sc0; o[t][1] *= sc0;
            o[t][2] *= sc1; o[t][3] *= sc1;
        }

        // ---- O += (Ph+Pl) Vh (2-term fp16) ----
        #pragma unroll
        for (int s = 0; s < 4; s++) {
            uint32_t aph[4], apl[4];
            pack2_hilo_h(sa[2 * s][0],     sa[2 * s][1],     aph[0], apl[0]);
            pack2_hilo_h(sa[2 * s][2],     sa[2 * s][3],     aph[1], apl[1]);
            pack2_hilo_h(sa[2 * s + 1][0], sa[2 * s + 1][1], aph[2], apl[2]);
            pack2_hilo_h(sa[2 * s + 1][2], sa[2 * s + 1][3], aph[3], apl[3]);
            #pragma unroll
            for (int nd = 0; nd < 4; nd++) {
                uint32_t vo = SWZ128((uint32_t)((s * 16 + v_r) * 128 + nd * 32 + v_c));
                uint32_t vv[4];
                LDM4T(vv, sVH + vo);
                MMA16816H(o[2 * nd],     aph, vv[0], vv[1]);
                MMA16816H(o[2 * nd + 1], aph, vv[2], vv[3]);
                MMA16816H(o[2 * nd],     apl, vv[0], vv[1]);
                MMA16816H(o[2 * nd + 1], apl, vv[2], vv[3]);
            }
        }
    }

    // epilogue: normalize, single fp16 store
    const float il0 = 1.f / l0;
    const float il1 = 1.f / l1;
    const size_t row0 = rbase + qg0;
    #pragma unroll
    for (int t = 0; t < 8; t++) {
        int col = hoff + t * 8 + lane2;
        __half2 h0 = __half2(__float2half_rn(o[t][0] * il0), __float2half_rn(o[t][1] * il0));
        __half2 h1 = __half2(__float2half_rn(o[t][2] * il1), __float2half_rn(o[t][3] * il1));
        *reinterpret_cast<__half2*>(&out16[row0 * DM + col])       = h0;
        *reinterpret_cast<__half2*>(&out16[(row0 + 8) * DM + col]) = h1;
    }
}

// ---------------------------------------------------------------------------
extern "C" void kernel_launch(void* const* d_in, const int* in_sizes, int n_in,
                              void* d_out, int out_size) {
    const float* x     = (const float*)d_in[0];
    const float* w_qkv = (const float*)d_in[1];
    const float* w_out = (const float*)d_in[2];
    float* out = (float*)d_out;

    __half *x16, *wq16, *wo16, *at16, *qkv_hi, *qkv_lo;
    cudaGetSymbolAddress((void**)&x16,    g_x16);
    cudaGetSymbolAddress((void**)&wq16,   g_wqkvT16);
    cudaGetSymbolAddress((void**)&wo16,   g_woutT16);
    cudaGetSymbolAddress((void**)&qkv_hi, g_qkv16_hi);
    cudaGetSymbolAddress((void**)&qkv_lo, g_qkv16_lo);
    cudaGetSymbolAddress((void**)&at16,   g_att16);

    cudaFuncSetAttribute(gemm_f16, cudaFuncAttributeMaxDynamicSharedMemorySize, GEMM_SMEM);
    const int ATTN_SMEM = 4 * ATT_T;   // 32 KB
    cudaFuncSetAttribute(attn_tc_kernel, cudaFuncAttributeMaxDynamicSharedMemorySize, ATTN_SMEM);

    // 0) prep: x -> fp16; w_qkv, w_out -> [N][K] fp16
    {
        int n4 = M_ROWS * DM / 4;
        cvt_f16_kernel<<<(n4 + 255) / 256, 256>>>(x, x16, n4);
        dim3 g1(N_QKV / 32, DM / 32);
        transpose_f16_kernel<<<g1, 256>>>(w_qkv, wq16, DM, N_QKV);
        dim3 g2(DM / 32, DM / 32);
        transpose_f16_kernel<<<g2, 256>>>(w_out, wo16, DM, DM);
    }
    // 1) QKV projection (fp16x1, BKK=64) -> fp16 hi/lo splits
    {
        dim3 grid(N_QKV / BN, M_ROWS / BM);
        gemm_f16<<<grid, 256, GEMM_SMEM>>>(x16, wq16, nullptr, qkv_hi, qkv_lo,
                                           M_ROWS, N_QKV, DM);
    }
    // 2) attention (fp16 2-term) -> single fp16
    {
        dim3 grid(T_SEQ / 64, NH, B_SZ);
        attn_tc_kernel<<<grid, 128, ATTN_SMEM>>>(qkv_hi, qkv_lo, at16);
    }
    // 3) output projection (fp16x1, BKK=64) -> fp32
    {
        dim3 grid(DM / BN, M_ROWS / BM);
        gemm_f16<<<grid, 256, GEMM_SMEM>>>(at16, wo16, out, nullptr, nullptr,
                                           M_ROWS, DM, DM);
    }
}

// round 14
// speedup vs baseline: 2.3808x; 1.0337x over previous
#include <cuda_runtime.h>
#include <cuda_bf16.h>
#include <cuda_fp16.h>
#include <math.h>
#include <stdint.h>

// Problem constants
#define B_SZ   4
#define T_SEQ  2048
#define DM     1024
#define NH     16
#define DH     64
#define WIN    256
#define M_ROWS (B_SZ * T_SEQ)        // 8192
#define N_QKV  (3 * DM)              // 3072

// fp16x1 GEMM tiling: 128x128x64 K-tiles, 128B smem rows, 3-stage ring
#define BM 128
#define BN 128
#define BKK 64
#define TILE_B (BM * 128)             // 16384 B per tile
#define NSTAGE 3
#define STG_B (2 * TILE_B)            // 32768 B (A + B)
#define GEMM_SMEM (NSTAGE * STG_B + 128)

// ---------------------------------------------------------------------------
// Device scratch (allocation-free per harness rules)
// ---------------------------------------------------------------------------
__device__ __align__(16) __half g_x16[M_ROWS * (size_t)DM];
__device__ __align__(16) __half g_wqkvT16[N_QKV * (size_t)DM];         // [N][K]
__device__ __align__(16) __half g_woutT16[DM * (size_t)DM];            // [N][K]
__device__ __align__(16) __half g_qkv16_hi[M_ROWS * (size_t)N_QKV];    // fp16 split QKV
__device__ __align__(16) __half g_qkv16_lo[M_ROWS * (size_t)N_QKV];
__device__ __align__(16) __half g_att16[M_ROWS * (size_t)DM];          // attention out

// ---------------------------------------------------------------------------
// Helpers
// ---------------------------------------------------------------------------
__device__ __forceinline__ uint32_t smem_u32(const void* p) {
    return (uint32_t)__cvta_generic_to_shared(p);
}

#define CP16(saddr, gptr) \
    asm volatile("cp.async.cg.shared.global [%0], [%1], 16;" :: "r"(saddr), "l"(gptr))
#define CP16Z(saddr, gptr, sz) \
    asm volatile("cp.async.cg.shared.global [%0], [%1], 16, %2;" \
        :: "r"(saddr), "l"(gptr), "r"(sz))
#define CP_COMMIT() asm volatile("cp.async.commit_group;")
#define CP_WAIT(n)  asm volatile("cp.async.wait_group %0;" :: "n"(n))

#define LDM4(r, addr) \
    asm volatile("ldmatrix.sync.aligned.m8n8.x4.shared.b16 {%0,%1,%2,%3}, [%4];" \
        : "=r"((r)[0]), "=r"((r)[1]), "=r"((r)[2]), "=r"((r)[3]) : "r"(addr))

#define LDM4T(r, addr) \
    asm volatile("ldmatrix.sync.aligned.m8n8.x4.trans.shared.b16 {%0,%1,%2,%3}, [%4];" \
        : "=r"((r)[0]), "=r"((r)[1]), "=r"((r)[2]), "=r"((r)[3]) : "r"(addr))

#define MMA16816H(d, a, b0, b1) \
    asm volatile("mma.sync.aligned.m16n8k16.row.col.f32.f16.f16.f32 " \
        "{%0,%1,%2,%3}, {%4,%5,%6,%7}, {%8,%9}, {%0,%1,%2,%3};" \
        : "+f"((d)[0]), "+f"((d)[1]), "+f"((d)[2]), "+f"((d)[3]) \
        : "r"((a)[0]), "r"((a)[1]), "r"((a)[2]), "r"((a)[3]), "r"(b0), "r"(b1))

// 128B-row swizzle: 16B-chunk index XORed with (row & 7)
#define SWZ128(off) ((off) ^ ((((off) >> 7) & 7u) << 4))

__device__ __forceinline__ void split_f32h(float f, __half& hi, __half& lo) {
    hi = __float2half_rn(f);
    lo = __float2half_rn(f - __half2float(hi));
}
__device__ __forceinline__ void pack2_hilo_h(float x, float y, uint32_t& h, uint32_t& l) {
    __half2 hv, lv;
    split_f32h(x, hv.x, lv.x);
    split_f32h(y, hv.y, lv.y);
    h = *reinterpret_cast<uint32_t*>(&hv);
    l = *reinterpret_cast<uint32_t*>(&lv);
}

// ---------------------------------------------------------------------------
// prep kernels
// ---------------------------------------------------------------------------
__global__ void cvt_f16_kernel(const float* __restrict__ src,
                               __half* __restrict__ dst, int n4) {
    int i = blockIdx.x * blockDim.x + threadIdx.x;
    if (i >= n4) return;
    float4 f = reinterpret_cast<const float4*>(src)[i];
    __half2 a = __half2(__float2half_rn(f.x), __float2half_rn(f.y));
    __half2 b = __half2(__float2half_rn(f.z), __float2half_rn(f.w));
    __half2* dp = reinterpret_cast<__half2*>(dst) + i * 2;
    dp[0] = a; dp[1] = b;
}

__global__ void transpose_f16_kernel(const float* __restrict__ src,
                                     __half* __restrict__ dst, int K, int N) {
    __shared__ float t[32][33];
    const int n0 = blockIdx.x * 32;
    const int k0 = blockIdx.y * 32;
    const int tx = threadIdx.x & 31;
    const int ty = threadIdx.x >> 5;
    #pragma unroll
    for (int i = 0; i < 32; i += 8)
        t[ty + i][tx] = src[(size_t)(k0 + ty + i) * N + n0 + tx];
    __syncthreads();
    #pragma unroll
    for (int i = 0; i < 32; i += 8)
        dst[(size_t)(n0 + ty + i) * K + k0 + tx] = __float2half_rn(t[tx][ty + i]);
}

// ---------------------------------------------------------------------------
// fp16x1 GEMM: C = A16 @ B16^T (Bt is [N][K]).
// 128x128x64 K-tiles, 8 warps (2M x 4N, warp tile 64x32), 3-stage ring.
// Epilogue: Chi!=null -> fp16 hi/lo splits; else fp32 C.
// ---------------------------------------------------------------------------
__global__ __launch_bounds__(256, 2)
void gemm_f16(const __half* __restrict__ A16, const __half* __restrict__ Bq,
              float* __restrict__ C,
              __half* __restrict__ Chi, __half* __restrict__ Clo,
              int M, int N, int K) {
    extern __shared__ char smraw[];
    const uint32_t sbase = (smem_u32(smraw) + 127) & ~127u;

    const int tid  = threadIdx.x;
    const int lane = tid & 31;
    const int warp = tid >> 5;
    const int wm   = warp & 1;        // 0..1: 64 rows each
    const int wn   = warp >> 1;       // 0..3: 32 cols each
    const int m0   = blockIdx.y * BM;
    const int n0   = blockIdx.x * BN;

    float acc[4][4][4];               // [mt 16-row][nt 8-col][frag]
    #pragma unroll
    for (int a = 0; a < 4; a++)
        #pragma unroll
        for (int b = 0; b < 4; b++)
            #pragma unroll
            for (int c = 0; c < 4; c++) acc[a][b][c] = 0.f;

    const int NK = K / BKK;

    auto load_stage = [&](int buf, int kt) {
        const uint32_t s = sbase + buf * STG_B;
        const int kg = kt * BKK;
        #pragma unroll
        for (int i = 0; i < 4; ++i) {
            int cg  = tid + i * 256;
            int row = cg >> 3;
            int ck  = cg & 7;
            uint32_t so = SWZ128((uint32_t)(row * 128 + ck * 16));
            size_t ka = (size_t)kg + ck * 8;
            CP16(s + so,          A16 + (size_t)(m0 + row) * K + ka);
            CP16(s + TILE_B + so, Bq  + (size_t)(n0 + row) * K + ka);
        }
    };

    load_stage(0, 0); CP_COMMIT();
    load_stage(1, 1); CP_COMMIT();

    const int a_r = wm * 64 + (lane & 15);
    const int a_c = (lane >> 4) << 4;
    const int b_r = wn * 32 + (lane & 7) + ((lane >> 4) << 3);
    const int b_c = ((lane >> 3) & 1) << 4;

    for (int kt = 0; kt < NK; ++kt) {
        if (kt + 1 < NK) { CP_WAIT(1); } else { CP_WAIT(0); }
        __syncthreads();
        if (kt + 2 < NK) {
            load_stage((kt + 2) % NSTAGE, kt + 2);
            CP_COMMIT();
        }

        const uint32_t s = sbase + (kt % NSTAGE) * STG_B;
        #pragma unroll
        for (int ks = 0; ks < 4; ++ks) {
            uint32_t ah[4][4];
            #pragma unroll
            for (int mt = 0; mt < 4; ++mt) {
                uint32_t ro = SWZ128((uint32_t)((a_r + mt * 16) * 128 + ks * 32 + a_c));
                LDM4(ah[mt], s + ro);
            }
            #pragma unroll
            for (int np = 0; np < 2; ++np) {
                uint32_t ro = SWZ128((uint32_t)((b_r + np * 16) * 128 + ks * 32 + b_c));
                uint32_t bq[4];
                LDM4(bq, s + TILE_B + ro);
                #pragma unroll
                for (int mt = 0; mt < 4; ++mt) {
                    MMA16816H(acc[mt][2 * np],     ah[mt], bq[0], bq[1]);
                    MMA16816H(acc[mt][2 * np + 1], ah[mt], bq[2], bq[3]);
                }
            }
        }
    }

    if (Chi != nullptr) {
        #pragma unroll
        for (int mt = 0; mt < 4; ++mt) {
            #pragma unroll
            for (int nt = 0; nt < 4; ++nt) {
                int row = m0 + wm * 64 + mt * 16 + (lane >> 2);
                int col = n0 + wn * 32 + nt * 8 + (lane & 3) * 2;
                uint32_t h0, l0, h1, l1;
                pack2_hilo_h(acc[mt][nt][0], acc[mt][nt][1], h0, l0);
                pack2_hilo_h(acc[mt][nt][2], acc[mt][nt][3], h1, l1);
                *reinterpret_cast<uint32_t*>(&Chi[(size_t)row * N + col])       = h0;
                *reinterpret_cast<uint32_t*>(&Clo[(size_t)row * N + col])       = l0;
                *reinterpret_cast<uint32_t*>(&Chi[(size_t)(row + 8) * N + col]) = h1;
                *reinterpret_cast<uint32_t*>(&Clo[(size_t)(row + 8) * N + col]) = l1;
            }
        }
    } else {
        #pragma unroll
        for (int mt = 0; mt < 4; ++mt) {
            #pragma unroll
            for (int nt = 0; nt < 4; ++nt) {
                int row = m0 + wm * 64 + mt * 16 + (lane >> 2);
                int col = n0 + wn * 32 + nt * 8 + (lane & 3) * 2;
                float2 v0 = make_float2(acc[mt][nt][0], acc[mt][nt][1]);
                float2 v1 = make_float2(acc[mt][nt][2], acc[mt][nt][3]);
                *reinterpret_cast<float2*>(&C[(size_t)row * N + col]) = v0;
                *reinterpret_cast<float2*>(&C[(size_t)(row + 8) * N + col]) = v1;
            }
        }
    }
}

// ---------------------------------------------------------------------------
// Attention (fp16): S = (Qh+Ql)·Kh^T (2-term), O = Ph·Vh (1-term).
// smem: QH, QL, KH, VH = 4 x 8 KB = 32 KB.
// ---------------------------------------------------------------------------
#define ATT_T 8192

__global__ __launch_bounds__(128, 4)
void attn_tc_kernel(const __half* __restrict__ qh,
                    const __half* __restrict__ ql,
                    __half* __restrict__ out16) {
    extern __shared__ char smb[];
    const uint32_t sb  = smem_u32(smb);
    const uint32_t sQH = sb,             sQL = sb + ATT_T;
    const uint32_t sKH = sb + 2 * ATT_T, sVH = sb + 3 * ATT_T;

    const int tid  = threadIdx.x;
    const int lane = tid & 31;
    const int warp = tid >> 5;
    const int q0 = blockIdx.x * 64;
    const int h  = blockIdx.y;
    const int b  = blockIdx.z;
    const int hoff = h * DH;
    const size_t rbase = (size_t)b * T_SEQ;

    #pragma unroll
    for (int i = 0; i < 4; i++) {
        int cg  = tid + i * 128;
        int row = cg >> 3;
        int ck  = cg & 7;
        uint32_t so = SWZ128((uint32_t)(row * 128 + ck * 16));
        size_t g = (rbase + q0 + row) * N_QKV + hoff + ck * 8;
        CP16(sQH + so, qh + g);
        CP16(sQL + so, ql + g);
    }
    CP_COMMIT();

    float sa[8][4];
    float o[8][4];
    #pragma unroll
    for (int t = 0; t < 8; t++)
        #pragma unroll
        for (int j = 0; j < 4; j++) o[t][j] = 0.f;
    float m0 = -1e20f, m1 = -1e20f, l0 = 0.f, l1 = 0.f;

    const int lane2 = (lane & 3) * 2;
    const int qrow  = warp * 16 + (lane >> 2);
    const int qg0   = q0 + qrow;

    const int a_r = warp * 16 + (lane & 15);
    const int a_c = (lane >> 4) << 4;
    const int b_r = (lane & 7) + ((lane >> 4) << 3);
    const int b_c = ((lane >> 3) & 1) << 4;
    const int v_r = lane & 15;
    const int v_c = (lane >> 4) << 4;

    for (int c = 0; c < 5; c++) {
        const int kb = q0 - WIN + c * 64;
        __syncthreads();
        #pragma unroll
        for (int i = 0; i < 4; i++) {
            int cg  = tid + i * 128;
            int row = cg >> 3;
            int ck  = cg & 7;
            int kg  = kb + row;
            uint32_t sz = (kg >= 0) ? 16u : 0u;
            int kgc = kg >= 0 ? kg : 0;
            uint32_t so = SWZ128((uint32_t)(row * 128 + ck * 16));
            size_t gk = (rbase + kgc) * N_QKV + DM + hoff + ck * 8;
            CP16Z(sKH + so, qh + gk, sz);
            CP16Z(sVH + so, qh + gk + DM, sz);
        }
        CP_COMMIT();
        CP_WAIT(0);
        __syncthreads();

        // ---- S = (Qh+Ql) Kh^T ----
        #pragma unroll
        for (int t = 0; t < 8; t++)
            #pragma unroll
            for (int j = 0; j < 4; j++) sa[t][j] = 0.f;

        #pragma unroll
        for (int ks = 0; ks < 4; ks++) {
            uint32_t ah[4], al[4];
            uint32_t ao = SWZ128((uint32_t)(a_r * 128 + ks * 32 + a_c));
            LDM4(ah, sQH + ao);
            LDM4(al, sQL + ao);
            #pragma unroll
            for (int np = 0; np < 4; np++) {
                uint32_t bo = SWZ128((uint32_t)((np * 16 + b_r) * 128 + ks * 32 + b_c));
                uint32_t bk[4];
                LDM4(bk, sKH + bo);
                MMA16816H(sa[2 * np],     ah, bk[0], bk[1]);
                MMA16816H(sa[2 * np + 1], ah, bk[2], bk[3]);
                MMA16816H(sa[2 * np],     al, bk[0], bk[1]);
                MMA16816H(sa[2 * np + 1], al, bk[2], bk[3]);
            }
        }

        // ---- mask + online softmax ----
        float mx0 = -1e30f, mx1 = -1e30f;
        #pragma unroll
        for (int t = 0; t < 8; t++) {
            #pragma unroll
            for (int j = 0; j < 4; j++) {
                int col = t * 8 + lane2 + (j & 1);
                int kg  = kb + col;
                int qg  = qg0 + ((j >> 1) << 3);
                bool valid = (kg >= 0) && (kg <= qg) && (kg >= qg - WIN);
                float s = valid ? sa[t][j] * 0.125f : -1e30f;
                sa[t][j] = s;
                if (j < 2) mx0 = fmaxf(mx0, s); else mx1 = fmaxf(mx1, s);
            }
        }
        mx0 = fmaxf(mx0, __shfl_xor_sync(0xffffffffu, mx0, 1));
        mx0 = fmaxf(mx0, __shfl_xor_sync(0xffffffffu, mx0, 2));
        mx1 = fmaxf(mx1, __shfl_xor_sync(0xffffffffu, mx1, 1));
        mx1 = fmaxf(mx1, __shfl_xor_sync(0xffffffffu, mx1, 2));

        const float mn0 = fmaxf(m0, mx0);
        const float mn1 = fmaxf(m1, mx1);
        const float sc0 = __expf(m0 - mn0);
        const float sc1 = __expf(m1 - mn1);
        m0 = mn0; m1 = mn1;

        float ps0 = 0.f, ps1 = 0.f;
        #pragma unroll
        for (int t = 0; t < 8; t++) {
            float p0 = __expf(sa[t][0] - mn0);
            float p1 = __expf(sa[t][1] - mn0);
            float p2 = __expf(sa[t][2] - mn1);
            float p3 = __expf(sa[t][3] - mn1);
            sa[t][0] = p0; sa[t][1] = p1; sa[t][2] = p2; sa[t][3] = p3;
            ps0 += p0 + p1; ps1 += p2 + p3;
        }
        ps0 += __shfl_xor_sync(0xffffffffu, ps0, 1);
        ps0 += __shfl_xor_sync(0xffffffffu, ps0, 2);
        ps1 += __shfl_xor_sync(0xffffffffu, ps1, 1);
        ps1 += __shfl_xor_sync(0xffffffffu, ps1, 2);
        l0 = l0 * sc0 + ps0;
        l1 = l1 * sc1 + ps1;

        #pragma unroll
        for (int t = 0; t < 8; t++) {
            o[t][0] *= sc0; o[t][1] *= sc0;
            o[t][2] *= sc1; o[t][3] *= sc1;
        }

        // ---- O += Ph Vh (single-term) ----
        #pragma unroll
        for (int s = 0; s < 4; s++) {
            uint32_t aph[4];
            __half2 p01 = __half2(__float2half_rn(sa[2 * s][0]),     __float2half_rn(sa[2 * s][1]));
            __half2 p23 = __half2(__float2half_rn(sa[2 * s][2]),     __float2half_rn(sa[2 * s][3]));
            __half2 p45 = __half2(__float2half_rn(sa[2 * s + 1][0]), __float2half_rn(sa[2 * s + 1][1]));
            __half2 p67 = __half2(__float2half_rn(sa[2 * s + 1][2]), __float2half_rn(sa[2 * s + 1][3]));
            aph[0] = *reinterpret_cast<uint32_t*>(&p01);
            aph[1] = *reinterpret_cast<uint32_t*>(&p23);
            aph[2] = *reinterpret_cast<uint32_t*>(&p45);
            aph[3] = *reinterpret_cast<uint32_t*>(&p67);
            #pragma unroll
            for (int nd = 0; nd < 4; nd++) {
                uint32_t vo = SWZ128((uint32_t)((s * 16 + v_r) * 128 + nd * 32 + v_c));
                uint32_t vv[4];
                LDM4T(vv, sVH + vo);
                MMA16816H(o[2 * nd],     aph, vv[0], vv[1]);
                MMA16816H(o[2 * nd + 1], aph, vv[2], vv[3]);
            }
        }
    }

    // epilogue: normalize, single fp16 store
    const float il0 = 1.f / l0;
    const float il1 = 1.f / l1;
    const size_t row0 = rbase + qg0;
    #pragma unroll
    for (int t = 0; t < 8; t++) {
        int col = hoff + t * 8 + lane2;
        __half2 h0 = __half2(__float2half_rn(o[t][0] * il0), __float2half_rn(o[t][1] * il0));
        __half2 h1 = __half2(__float2half_rn(o[t][2] * il1), __float2half_rn(o[t][3] * il1));
        *reinterpret_cast<__half2*>(&out16[row0 * DM + col])       = h0;
        *reinterpret_cast<__half2*>(&out16[(row0 + 8) * DM + col]) = h1;
    }
}

// ---------------------------------------------------------------------------
extern "C" void kernel_launch(void* const* d_in, const int* in_sizes, int n_in,
                              void* d_out, int out_size) {
    const float* x     = (const float*)d_in[0];
    const float* w_qkv = (const float*)d_in[1];
    const float* w_out = (const float*)d_in[2];
    float* out = (float*)d_out;

    __half *x16, *wq16, *wo16, *at16, *qkv_hi, *qkv_lo;
    cudaGetSymbolAddress((void**)&x16,    g_x16);
    cudaGetSymbolAddress((void**)&wq16,   g_wqkvT16);
    cudaGetSymbolAddress((void**)&wo16,   g_woutT16);
    cudaGetSymbolAddress((void**)&qkv_hi, g_qkv16_hi);
    cudaGetSymbolAddress((void**)&qkv_lo, g_qkv16_lo);
    cudaGetSymbolAddress((void**)&at16,   g_att16);

    cudaFuncSetAttribute(gemm_f16, cudaFuncAttributeMaxDynamicSharedMemorySize, GEMM_SMEM);
    const int ATTN_SMEM = 4 * ATT_T;   // 32 KB
    cudaFuncSetAttribute(attn_tc_kernel, cudaFuncAttributeMaxDynamicSharedMemorySize, ATTN_SMEM);

    // 0) prep: x -> fp16; w_qkv, w_out -> [N][K] fp16
    {
        int n4 = M_ROWS * DM / 4;
        cvt_f16_kernel<<<(n4 + 255) / 256, 256>>>(x, x16, n4);
        dim3 g1(N_QKV / 32, DM / 32);
        transpose_f16_kernel<<<g1, 256>>>(w_qkv, wq16, DM, N_QKV);
        dim3 g2(DM / 32, DM / 32);
        transpose_f16_kernel<<<g2, 256>>>(w_out, wo16, DM, DM);
    }
    // 1) QKV projection (fp16x1, BKK=64) -> fp16 hi/lo splits
    {
        dim3 grid(N_QKV / BN, M_ROWS / BM);
        gemm_f16<<<grid, 256, GEMM_SMEM>>>(x16, wq16, nullptr, qkv_hi, qkv_lo,
                                           M_ROWS, N_QKV, DM);
    }
    // 2) attention (2-term S, 1-term PV) -> single fp16
    {
        dim3 grid(T_SEQ / 64, NH, B_SZ);
        attn_tc_kernel<<<grid, 128, ATTN_SMEM>>>(qkv_hi, qkv_lo, at16);
    }
    // 3) output projection (fp16x1, BKK=64) -> fp32
    {
        dim3 grid(DM / BN, M_ROWS / BM);
        gemm_f16<<<grid, 256, GEMM_SMEM>>>(at16, wo16, out, nullptr, nullptr,
                                           M_ROWS, DM, DM);
    }
}

// round 15
// speedup vs baseline: 2.4974x; 1.0490x over previous
#include <cuda_runtime.h>
#include <cuda_bf16.h>
#include <cuda_fp16.h>
#include <math.h>
#include <stdint.h>

// Problem constants
#define B_SZ   4
#define T_SEQ  2048
#define DM     1024
#define NH     16
#define DH     64
#define WIN    256
#define M_ROWS (B_SZ * T_SEQ)        // 8192
#define N_QKV  (3 * DM)              // 3072

// fp16x1 GEMM tiling: 128x128x64 K-tiles, 128B smem rows, 3-stage ring
#define BM 128
#define BN 128
#define BKK 64
#define TILE_B (BM * 128)             // 16384 B per tile
#define NSTAGE 3
#define STG_B (2 * TILE_B)            // 32768 B (A + B)
#define GEMM_SMEM (NSTAGE * STG_B + 128)

// ---------------------------------------------------------------------------
// Device scratch (allocation-free per harness rules)
// ---------------------------------------------------------------------------
__device__ __align__(16) __half g_x16[M_ROWS * (size_t)DM];
__device__ __align__(16) __half g_wqkvT16[N_QKV * (size_t)DM];         // [N][K]
__device__ __align__(16) __half g_woutT16[DM * (size_t)DM];            // [N][K]
__device__ __align__(16) __half g_qkv16_hi[M_ROWS * (size_t)N_QKV];    // fp16 split QKV
__device__ __align__(16) __half g_qkv16_lo[M_ROWS * (size_t)N_QKV];    // lo used for Q cols only
__device__ __align__(16) __half g_att16[M_ROWS * (size_t)DM];          // attention out

// ---------------------------------------------------------------------------
// Helpers
// ---------------------------------------------------------------------------
__device__ __forceinline__ uint32_t smem_u32(const void* p) {
    return (uint32_t)__cvta_generic_to_shared(p);
}

#define CP16(saddr, gptr) \
    asm volatile("cp.async.cg.shared.global [%0], [%1], 16;" :: "r"(saddr), "l"(gptr))
#define CP16Z(saddr, gptr, sz) \
    asm volatile("cp.async.cg.shared.global [%0], [%1], 16, %2;" \
        :: "r"(saddr), "l"(gptr), "r"(sz))
#define CP_COMMIT() asm volatile("cp.async.commit_group;")
#define CP_WAIT(n)  asm volatile("cp.async.wait_group %0;" :: "n"(n))

#define LDM4(r, addr) \
    asm volatile("ldmatrix.sync.aligned.m8n8.x4.shared.b16 {%0,%1,%2,%3}, [%4];" \
        : "=r"((r)[0]), "=r"((r)[1]), "=r"((r)[2]), "=r"((r)[3]) : "r"(addr))

#define LDM4T(r, addr) \
    asm volatile("ldmatrix.sync.aligned.m8n8.x4.trans.shared.b16 {%0,%1,%2,%3}, [%4];" \
        : "=r"((r)[0]), "=r"((r)[1]), "=r"((r)[2]), "=r"((r)[3]) : "r"(addr))

#define MMA16816H(d, a, b0, b1) \
    asm volatile("mma.sync.aligned.m16n8k16.row.col.f32.f16.f16.f32 " \
        "{%0,%1,%2,%3}, {%4,%5,%6,%7}, {%8,%9}, {%0,%1,%2,%3};" \
        : "+f"((d)[0]), "+f"((d)[1]), "+f"((d)[2]), "+f"((d)[3]) \
        : "r"((a)[0]), "r"((a)[1]), "r"((a)[2]), "r"((a)[3]), "r"(b0), "r"(b1))

// 128B-row swizzle: 16B-chunk index XORed with (row & 7)
#define SWZ128(off) ((off) ^ ((((off) >> 7) & 7u) << 4))

__device__ __forceinline__ void split_f32h(float f, __half& hi, __half& lo) {
    hi = __float2half_rn(f);
    lo = __float2half_rn(f - __half2float(hi));
}
__device__ __forceinline__ void pack2_hilo_h(float x, float y, uint32_t& h, uint32_t& l) {
    __half2 hv, lv;
    split_f32h(x, hv.x, lv.x);
    split_f32h(y, hv.y, lv.y);
    h = *reinterpret_cast<uint32_t*>(&hv);
    l = *reinterpret_cast<uint32_t*>(&lv);
}

// ---------------------------------------------------------------------------
// prep kernels
// ---------------------------------------------------------------------------
__global__ void cvt_f16_kernel(const float* __restrict__ src,
                               __half* __restrict__ dst, int n4) {
    int i = blockIdx.x * blockDim.x + threadIdx.x;
    if (i >= n4) return;
    float4 f = reinterpret_cast<const float4*>(src)[i];
    __half2 a = __half2(__float2half_rn(f.x), __float2half_rn(f.y));
    __half2 b = __half2(__float2half_rn(f.z), __float2half_rn(f.w));
    __half2* dp = reinterpret_cast<__half2*>(dst) + i * 2;
    dp[0] = a; dp[1] = b;
}

__global__ void transpose_f16_kernel(const float* __restrict__ src,
                                     __half* __restrict__ dst, int K, int N) {
    __shared__ float t[32][33];
    const int n0 = blockIdx.x * 32;
    const int k0 = blockIdx.y * 32;
    const int tx = threadIdx.x & 31;
    const int ty = threadIdx.x >> 5;
    #pragma unroll
    for (int i = 0; i < 32; i += 8)
        t[ty + i][tx] = src[(size_t)(k0 + ty + i) * N + n0 + tx];
    __syncthreads();
    #pragma unroll
    for (int i = 0; i < 32; i += 8)
        dst[(size_t)(n0 + ty + i) * K + k0 + tx] = __float2half_rn(t[tx][ty + i]);
}

// ---------------------------------------------------------------------------
// fp16x1 GEMM: C = A16 @ B16^T (Bt is [N][K]).
// 128x128x64 K-tiles, 8 warps (2M x 4N), 3-stage ring, one sync/tile.
// Epilogue: Chi!=null -> fp16 hi (+ lo only for n0 < lo_ncols); else fp32 C.
// ---------------------------------------------------------------------------
__global__ __launch_bounds__(256, 2)
void gemm_f16(const __half* __restrict__ A16, const __half* __restrict__ Bq,
              float* __restrict__ C,
              __half* __restrict__ Chi, __half* __restrict__ Clo, int lo_ncols,
              int M, int N, int K) {
    extern __shared__ char smraw[];
    const uint32_t sbase = (smem_u32(smraw) + 127) & ~127u;

    const int tid  = threadIdx.x;
    const int lane = tid & 31;
    const int warp = tid >> 5;
    const int wm   = warp & 1;
    const int wn   = warp >> 1;
    const int m0   = blockIdx.y * BM;
    const int n0   = blockIdx.x * BN;

    float acc[4][4][4];
    #pragma unroll
    for (int a = 0; a < 4; a++)
        #pragma unroll
        for (int b = 0; b < 4; b++)
            #pragma unroll
            for (int c = 0; c < 4; c++) acc[a][b][c] = 0.f;

    const int NK = K / BKK;

    auto load_stage = [&](int buf, int kt) {
        const uint32_t s = sbase + buf * STG_B;
        const int kg = kt * BKK;
        #pragma unroll
        for (int i = 0; i < 4; ++i) {
            int cg  = tid + i * 256;
            int row = cg >> 3;
            int ck  = cg & 7;
            uint32_t so = SWZ128((uint32_t)(row * 128 + ck * 16));
            size_t ka = (size_t)kg + ck * 8;
            CP16(s + so,          A16 + (size_t)(m0 + row) * K + ka);
            CP16(s + TILE_B + so, Bq  + (size_t)(n0 + row) * K + ka);
        }
    };

    load_stage(0, 0); CP_COMMIT();
    load_stage(1, 1); CP_COMMIT();

    const int a_r = wm * 64 + (lane & 15);
    const int a_c = (lane >> 4) << 4;
    const int b_r = wn * 32 + (lane & 7) + ((lane >> 4) << 3);
    const int b_c = ((lane >> 3) & 1) << 4;

    for (int kt = 0; kt < NK; ++kt) {
        if (kt + 1 < NK) { CP_WAIT(1); } else { CP_WAIT(0); }
        __syncthreads();
        if (kt + 2 < NK) {
            load_stage((kt + 2) % NSTAGE, kt + 2);
            CP_COMMIT();
        }

        const uint32_t s = sbase + (kt % NSTAGE) * STG_B;
        #pragma unroll
        for (int ks = 0; ks < 4; ++ks) {
            uint32_t ah[4][4];
            #pragma unroll
            for (int mt = 0; mt < 4; ++mt) {
                uint32_t ro = SWZ128((uint32_t)((a_r + mt * 16) * 128 + ks * 32 + a_c));
                LDM4(ah[mt], s + ro);
            }
            #pragma unroll
            for (int np = 0; np < 2; ++np) {
                uint32_t ro = SWZ128((uint32_t)((b_r + np * 16) * 128 + ks * 32 + b_c));
                uint32_t bq[4];
                LDM4(bq, s + TILE_B + ro);
                #pragma unroll
                for (int mt = 0; mt < 4; ++mt) {
                    MMA16816H(acc[mt][2 * np],     ah[mt], bq[0], bq[1]);
                    MMA16816H(acc[mt][2 * np + 1], ah[mt], bq[2], bq[3]);
                }
            }
        }
    }

    if (Chi != nullptr) {
        const bool wlo = (n0 < lo_ncols);
        #pragma unroll
        for (int mt = 0; mt < 4; ++mt) {
            #pragma unroll
            for (int nt = 0; nt < 4; ++nt) {
                int row = m0 + wm * 64 + mt * 16 + (lane >> 2);
                int col = n0 + wn * 32 + nt * 8 + (lane & 3) * 2;
                uint32_t h0, l0, h1, l1;
                pack2_hilo_h(acc[mt][nt][0], acc[mt][nt][1], h0, l0);
                pack2_hilo_h(acc[mt][nt][2], acc[mt][nt][3], h1, l1);
                *reinterpret_cast<uint32_t*>(&Chi[(size_t)row * N + col])       = h0;
                *reinterpret_cast<uint32_t*>(&Chi[(size_t)(row + 8) * N + col]) = h1;
                if (wlo) {
                    *reinterpret_cast<uint32_t*>(&Clo[(size_t)row * N + col])       = l0;
                    *reinterpret_cast<uint32_t*>(&Clo[(size_t)(row + 8) * N + col]) = l1;
                }
            }
        }
    } else {
        #pragma unroll
        for (int mt = 0; mt < 4; ++mt) {
            #pragma unroll
            for (int nt = 0; nt < 4; ++nt) {
                int row = m0 + wm * 64 + mt * 16 + (lane >> 2);
                int col = n0 + wn * 32 + nt * 8 + (lane & 3) * 2;
                float2 v0 = make_float2(acc[mt][nt][0], acc[mt][nt][1]);
                float2 v1 = make_float2(acc[mt][nt][2], acc[mt][nt][3]);
                *reinterpret_cast<float2*>(&C[(size_t)row * N + col]) = v0;
                *reinterpret_cast<float2*>(&C[(size_t)(row + 8) * N + col]) = v1;
            }
        }
    }
}

// ---------------------------------------------------------------------------
// Attention (fp16): S = (Qh+Ql)·Kh^T (2-term), O = Ph·Vh (1-term).
// K/V chunks double-buffered: chunk c+1 loads during chunk-c compute.
// smem: QH, QL, {KH,VH} x 2 stages = 6 x 8 KB = 48 KB.
// ---------------------------------------------------------------------------
#define ATT_T 8192

__global__ __launch_bounds__(128, 4)
void attn_tc_kernel(const __half* __restrict__ qh,
                    const __half* __restrict__ ql,
                    __half* __restrict__ out16) {
    extern __shared__ char smb[];
    const uint32_t sb  = smem_u32(smb);
    const uint32_t sQH = sb;
    const uint32_t sQL = sb + ATT_T;
    // stage s: K at sb + (2 + 2s)*ATT_T, V at +ATT_T

    const int tid  = threadIdx.x;
    const int lane = tid & 31;
    const int warp = tid >> 5;
    const int q0 = blockIdx.x * 64;
    const int h  = blockIdx.y;
    const int b  = blockIdx.z;
    const int hoff = h * DH;
    const size_t rbase = (size_t)b * T_SEQ;

    // KV chunk loader (hi stream only, zero-fill kg<0)
    auto load_kv = [&](int c) {
        const int kb = q0 - WIN + c * 64;
        const uint32_t sK = sb + (2 + 2 * (c & 1)) * ATT_T;
        const uint32_t sV = sK + ATT_T;
        #pragma unroll
        for (int i = 0; i < 4; i++) {
            int cg  = tid + i * 128;
            int row = cg >> 3;
            int ck  = cg & 7;
            int kg  = kb + row;
            uint32_t sz = (kg >= 0) ? 16u : 0u;
            int kgc = kg >= 0 ? kg : 0;
            uint32_t so = SWZ128((uint32_t)(row * 128 + ck * 16));
            size_t gk = (rbase + kgc) * N_QKV + DM + hoff + ck * 8;
            CP16Z(sK + so, qh + gk, sz);
            CP16Z(sV + so, qh + gk + DM, sz);
        }
    };

    // ---- prologue: Q tile + KV chunk 0 ----
    #pragma unroll
    for (int i = 0; i < 4; i++) {
        int cg  = tid + i * 128;
        int row = cg >> 3;
        int ck  = cg & 7;
        uint32_t so = SWZ128((uint32_t)(row * 128 + ck * 16));
        size_t g = (rbase + q0 + row) * N_QKV + hoff + ck * 8;
        CP16(sQH + so, qh + g);
        CP16(sQL + so, ql + g);
    }
    CP_COMMIT();
    load_kv(0);
    CP_COMMIT();

    float sa[8][4];
    float o[8][4];
    #pragma unroll
    for (int t = 0; t < 8; t++)
        #pragma unroll
        for (int j = 0; j < 4; j++) o[t][j] = 0.f;
    float m0 = -1e20f, m1 = -1e20f, l0 = 0.f, l1 = 0.f;

    const int lane2 = (lane & 3) * 2;
    const int qrow  = warp * 16 + (lane >> 2);
    const int qg0   = q0 + qrow;

    const int a_r = warp * 16 + (lane & 15);
    const int a_c = (lane >> 4) << 4;
    const int b_r = (lane & 7) + ((lane >> 4) << 3);
    const int b_c = ((lane >> 3) & 1) << 4;
    const int v_r = lane & 15;
    const int v_c = (lane >> 4) << 4;

    for (int c = 0; c < 5; c++) {
        const int kb = q0 - WIN + c * 64;
        CP_WAIT(0);          // KV chunk c (and Q on first iter) complete
        __syncthreads();     // all warps done reading buffer (c+1)&1 (chunk c-1)
        if (c + 1 < 5) {     // prefetch next chunk into the freed buffer
            load_kv(c + 1);
            CP_COMMIT();
        }
        const uint32_t sKH = sb + (2 + 2 * (c & 1)) * ATT_T;
        const uint32_t sVH = sKH + ATT_T;

        // ---- S = (Qh+Ql) Kh^T ----
        #pragma unroll
        for (int t = 0; t < 8; t++)
            #pragma unroll
            for (int j = 0; j < 4; j++) sa[t][j] = 0.f;

        #pragma unroll
        for (int ks = 0; ks < 4; ks++) {
            uint32_t ah[4], al[4];
            uint32_t ao = SWZ128((uint32_t)(a_r * 128 + ks * 32 + a_c));
            LDM4(ah, sQH + ao);
            LDM4(al, sQL + ao);
            #pragma unroll
            for (int np = 0; np < 4; np++) {
                uint32_t bo = SWZ128((uint32_t)((np * 16 + b_r) * 128 + ks * 32 + b_c));
                uint32_t bk[4];
                LDM4(bk, sKH + bo);
                MMA16816H(sa[2 * np],     ah, bk[0], bk[1]);
                MMA16816H(sa[2 * np + 1], ah, bk[2], bk[3]);
                MMA16816H(sa[2 * np],     al, bk[0], bk[1]);
                MMA16816H(sa[2 * np + 1], al, bk[2], bk[3]);
            }
        }

        // ---- mask + online softmax ----
        float mx0 = -1e30f, mx1 = -1e30f;
        #pragma unroll
        for (int t = 0; t < 8; t++) {
            #pragma unroll
            for (int j = 0; j < 4; j++) {
                int col = t * 8 + lane2 + (j & 1);
                int kg  = kb + col;
                int qg  = qg0 + ((j >> 1) << 3);
                bool valid = (kg >= 0) && (kg <= qg) && (kg >= qg - WIN);
                float s = valid ? sa[t][j] * 0.125f : -1e30f;
                sa[t][j] = s;
                if (j < 2) mx0 = fmaxf(mx0, s); else mx1 = fmaxf(mx1, s);
            }
        }
        mx0 = fmaxf(mx0, __shfl_xor_sync(0xffffffffu, mx0, 1));
        mx0 = fmaxf(mx0, __shfl_xor_sync(0xffffffffu, mx0, 2));
        mx1 = fmaxf(mx1, __shfl_xor_sync(0xffffffffu, mx1, 1));
        mx1 = fmaxf(mx1, __shfl_xor_sync(0xffffffffu, mx1, 2));

        const float mn0 = fmaxf(m0, mx0);
        const float mn1 = fmaxf(m1, mx1);
        const float sc0 = __expf(m0 - mn0);
        const float sc1 = __expf(m1 - mn1);
        m0 = mn0; m1 = mn1;

        float ps0 = 0.f, ps1 = 0.f;
        #pragma unroll
        for (int t = 0; t < 8; t++) {
            float p0 = __expf(sa[t][0] - mn0);
            float p1 = __expf(sa[t][1] - mn0);
            float p2 = __expf(sa[t][2] - mn1);
            float p3 = __expf(sa[t][3] - mn1);
            sa[t][0] = p0; sa[t][1] = p1; sa[t][2] = p2; sa[t][3] = p3;
            ps0 += p0 + p1; ps1 += p2 + p3;
        }
        ps0 += __shfl_xor_sync(0xffffffffu, ps0, 1);
        ps0 += __shfl_xor_sync(0xffffffffu, ps0, 2);
        ps1 += __shfl_xor_sync(0xffffffffu, ps1, 1);
        ps1 += __shfl_xor_sync(0xffffffffu, ps1, 2);
        l0 = l0 * sc0 + ps0;
        l1 = l1 * sc1 + ps1;

        #pragma unroll
        for (int t = 0; t < 8; t++) {
            o[t][0] *= sc0; o[t][1] *= sc0;
            o[t][2] *= sc1; o[t][3] *= sc1;
        }

        // ---- O += Ph Vh (single-term) ----
        #pragma unroll
        for (int s = 0; s < 4; s++) {
            uint32_t aph[4];
            __half2 p01 = __half2(__float2half_rn(sa[2 * s][0]),     __float2half_rn(sa[2 * s][1]));
            __half2 p23 = __half2(__float2half_rn(sa[2 * s][2]),     __float2half_rn(sa[2 * s][3]));
            __half2 p45 = __half2(__float2half_rn(sa[2 * s + 1][0]), __float2half_rn(sa[2 * s + 1][1]));
            __half2 p67 = __half2(__float2half_rn(sa[2 * s + 1][2]), __float2half_rn(sa[2 * s + 1][3]));
            aph[0] = *reinterpret_cast<uint32_t*>(&p01);
            aph[1] = *reinterpret_cast<uint32_t*>(&p23);
            aph[2] = *reinterpret_cast<uint32_t*>(&p45);
            aph[3] = *reinterpret_cast<uint32_t*>(&p67);
            #pragma unroll
            for (int nd = 0; nd < 4; nd++) {
                uint32_t vo = SWZ128((uint32_t)((s * 16 + v_r) * 128 + nd * 32 + v_c));
                uint32_t vv[4];
                LDM4T(vv, sVH + vo);
                MMA16816H(o[2 * nd],     aph, vv[0], vv[1]);
                MMA16816H(o[2 * nd + 1], aph, vv[2], vv[3]);
            }
        }
    }

    // epilogue: normalize, single fp16 store
    const float il0 = 1.f / l0;
    const float il1 = 1.f / l1;
    const size_t row0 = rbase + qg0;
    #pragma unroll
    for (int t = 0; t < 8; t++) {
        int col = hoff + t * 8 + lane2;
        __half2 h0 = __half2(__float2half_rn(o[t][0] * il0), __float2half_rn(o[t][1] * il0));
        __half2 h1 = __half2(__float2half_rn(o[t][2] * il1), __float2half_rn(o[t][3] * il1));
        *reinterpret_cast<__half2*>(&out16[row0 * DM + col])       = h0;
        *reinterpret_cast<__half2*>(&out16[(row0 + 8) * DM + col]) = h1;
    }
}

// ---------------------------------------------------------------------------
extern "C" void kernel_launch(void* const* d_in, const int* in_sizes, int n_in,
                              void* d_out, int out_size) {
    const float* x     = (const float*)d_in[0];
    const float* w_qkv = (const float*)d_in[1];
    const float* w_out = (const float*)d_in[2];
    float* out = (float*)d_out;

    __half *x16, *wq16, *wo16, *at16, *qkv_hi, *qkv_lo;
    cudaGetSymbolAddress((void**)&x16,    g_x16);
    cudaGetSymbolAddress((void**)&wq16,   g_wqkvT16);
    cudaGetSymbolAddress((void**)&wo16,   g_woutT16);
    cudaGetSymbolAddress((void**)&qkv_hi, g_qkv16_hi);
    cudaGetSymbolAddress((void**)&qkv_lo, g_qkv16_lo);
    cudaGetSymbolAddress((void**)&at16,   g_att16);

    cudaFuncSetAttribute(gemm_f16, cudaFuncAttributeMaxDynamicSharedMemorySize, GEMM_SMEM);
    const int ATTN_SMEM = 6 * ATT_T;   // 48 KB (Q hi/lo + 2-stage K/V)
    cudaFuncSetAttribute(attn_tc_kernel, cudaFuncAttributeMaxDynamicSharedMemorySize, ATTN_SMEM);

    // 0) prep: x -> fp16; w_qkv, w_out -> [N][K] fp16
    {
        int n4 = M_ROWS * DM / 4;
        cvt_f16_kernel<<<(n4 + 255) / 256, 256>>>(x, x16, n4);
        dim3 g1(N_QKV / 32, DM / 32);
        transpose_f16_kernel<<<g1, 256>>>(w_qkv, wq16, DM, N_QKV);
        dim3 g2(DM / 32, DM / 32);
        transpose_f16_kernel<<<g2, 256>>>(w_out, wo16, DM, DM);
    }
    // 1) QKV projection (fp16x1) -> fp16 hi everywhere, lo only for Q columns
    {
        dim3 grid(N_QKV / BN, M_ROWS / BM);
        gemm_f16<<<grid, 256, GEMM_SMEM>>>(x16, wq16, nullptr,
                                           qkv_hi, qkv_lo, DM,
                                           M_ROWS, N_QKV, DM);
    }
    // 2) attention (2-term S, 1-term PV, double-buffered K/V) -> fp16
    {
        dim3 grid(T_SEQ / 64, NH, B_SZ);
        attn_tc_kernel<<<grid, 128, ATTN_SMEM>>>(qkv_hi, qkv_lo, at16);
    }
    // 3) output projection (fp16x1) -> fp32
    {
        dim3 grid(DM / BN, M_ROWS / BM);
        gemm_f16<<<grid, 256, GEMM_SMEM>>>(at16, wo16, out,
                                           nullptr, nullptr, 0,
                                           M_ROWS, DM, DM);
    }
}

// round 16
// speedup vs baseline: 2.6457x; 1.0594x over previous
#include <cuda_runtime.h>
#include <cuda_bf16.h>
#include <cuda_fp16.h>
#include <math.h>
#include <stdint.h>

// Problem constants
#define B_SZ   4
#define T_SEQ  2048
#define DM     1024
#define NH     16
#define DH     64
#define WIN    256
#define M_ROWS (B_SZ * T_SEQ)        // 8192
#define N_QKV  (3 * DM)              // 3072

// fp16x1 GEMM tiling: 128x128x64 K-tiles, 128B smem rows, 3-stage ring
#define BM 128
#define BN 128
#define BKK 64
#define TILE_B (BM * 128)             // 16384 B per tile
#define NSTAGE 3
#define STG_B (2 * TILE_B)            // 32768 B (A + B)
#define GEMM_SMEM (NSTAGE * STG_B + 128)

// ---------------------------------------------------------------------------
// Device scratch (allocation-free per harness rules)
// ---------------------------------------------------------------------------
__device__ __align__(16) __half g_x16[M_ROWS * (size_t)DM];
__device__ __align__(16) __half g_wqkvT16[N_QKV * (size_t)DM];      // [N][K]
__device__ __align__(16) __half g_woutT16[DM * (size_t)DM];         // [N][K]
__device__ __align__(16) __half g_qkv16[M_ROWS * (size_t)N_QKV];    // fp16 QKV
__device__ __align__(16) __half g_att16[M_ROWS * (size_t)DM];       // attention out

// ---------------------------------------------------------------------------
// Helpers
// ---------------------------------------------------------------------------
__device__ __forceinline__ uint32_t smem_u32(const void* p) {
    return (uint32_t)__cvta_generic_to_shared(p);
}

#define CP16(saddr, gptr) \
    asm volatile("cp.async.cg.shared.global [%0], [%1], 16;" :: "r"(saddr), "l"(gptr))
#define CP16Z(saddr, gptr, sz) \
    asm volatile("cp.async.cg.shared.global [%0], [%1], 16, %2;" \
        :: "r"(saddr), "l"(gptr), "r"(sz))
#define CP_COMMIT() asm volatile("cp.async.commit_group;")
#define CP_WAIT(n)  asm volatile("cp.async.wait_group %0;" :: "n"(n))

#define LDM4(r, addr) \
    asm volatile("ldmatrix.sync.aligned.m8n8.x4.shared.b16 {%0,%1,%2,%3}, [%4];" \
        : "=r"((r)[0]), "=r"((r)[1]), "=r"((r)[2]), "=r"((r)[3]) : "r"(addr))

#define LDM4T(r, addr) \
    asm volatile("ldmatrix.sync.aligned.m8n8.x4.trans.shared.b16 {%0,%1,%2,%3}, [%4];" \
        : "=r"((r)[0]), "=r"((r)[1]), "=r"((r)[2]), "=r"((r)[3]) : "r"(addr))

#define MMA16816H(d, a, b0, b1) \
    asm volatile("mma.sync.aligned.m16n8k16.row.col.f32.f16.f16.f32 " \
        "{%0,%1,%2,%3}, {%4,%5,%6,%7}, {%8,%9}, {%0,%1,%2,%3};" \
        : "+f"((d)[0]), "+f"((d)[1]), "+f"((d)[2]), "+f"((d)[3]) \
        : "r"((a)[0]), "r"((a)[1]), "r"((a)[2]), "r"((a)[3]), "r"(b0), "r"(b1))

// 128B-row swizzle: 16B-chunk index XORed with (row & 7)
#define SWZ128(off) ((off) ^ ((((off) >> 7) & 7u) << 4))

// ---------------------------------------------------------------------------
// prep kernels
// ---------------------------------------------------------------------------
__global__ void cvt_f16_kernel(const float* __restrict__ src,
                               __half* __restrict__ dst, int n4) {
    int i = blockIdx.x * blockDim.x + threadIdx.x;
    if (i >= n4) return;
    float4 f = reinterpret_cast<const float4*>(src)[i];
    __half2 a = __half2(__float2half_rn(f.x), __float2half_rn(f.y));
    __half2 b = __half2(__float2half_rn(f.z), __float2half_rn(f.w));
    __half2* dp = reinterpret_cast<__half2*>(dst) + i * 2;
    dp[0] = a; dp[1] = b;
}

__global__ void transpose_f16_kernel(const float* __restrict__ src,
                                     __half* __restrict__ dst, int K, int N) {
    __shared__ float t[32][33];
    const int n0 = blockIdx.x * 32;
    const int k0 = blockIdx.y * 32;
    const int tx = threadIdx.x & 31;
    const int ty = threadIdx.x >> 5;
    #pragma unroll
    for (int i = 0; i < 32; i += 8)
        t[ty + i][tx] = src[(size_t)(k0 + ty + i) * N + n0 + tx];
    __syncthreads();
    #pragma unroll
    for (int i = 0; i < 32; i += 8)
        dst[(size_t)(n0 + ty + i) * K + k0 + tx] = __float2half_rn(t[tx][ty + i]);
}

// ---------------------------------------------------------------------------
// fp16x1 GEMM: C = A16 @ B16^T (Bt is [N][K]).
// 128x128x64 K-tiles, 8 warps (2M x 4N), 3-stage ring, one sync/tile.
// Epilogue: C16!=null -> single fp16; else fp32 C.
// ---------------------------------------------------------------------------
__global__ __launch_bounds__(256, 2)
void gemm_f16(const __half* __restrict__ A16, const __half* __restrict__ Bq,
              float* __restrict__ C, __half* __restrict__ C16,
              int M, int N, int K) {
    extern __shared__ char smraw[];
    const uint32_t sbase = (smem_u32(smraw) + 127) & ~127u;

    const int tid  = threadIdx.x;
    const int lane = tid & 31;
    const int warp = tid >> 5;
    const int wm   = warp & 1;
    const int wn   = warp >> 1;
    const int m0   = blockIdx.y * BM;
    const int n0   = blockIdx.x * BN;

    float acc[4][4][4];
    #pragma unroll
    for (int a = 0; a < 4; a++)
        #pragma unroll
        for (int b = 0; b < 4; b++)
            #pragma unroll
            for (int c = 0; c < 4; c++) acc[a][b][c] = 0.f;

    const int NK = K / BKK;

    auto load_stage = [&](int buf, int kt) {
        const uint32_t s = sbase + buf * STG_B;
        const int kg = kt * BKK;
        #pragma unroll
        for (int i = 0; i < 4; ++i) {
            int cg  = tid + i * 256;
            int row = cg >> 3;
            int ck  = cg & 7;
            uint32_t so = SWZ128((uint32_t)(row * 128 + ck * 16));
            size_t ka = (size_t)kg + ck * 8;
            CP16(s + so,          A16 + (size_t)(m0 + row) * K + ka);
            CP16(s + TILE_B + so, Bq  + (size_t)(n0 + row) * K + ka);
        }
    };

    load_stage(0, 0); CP_COMMIT();
    load_stage(1, 1); CP_COMMIT();

    const int a_r = wm * 64 + (lane & 15);
    const int a_c = (lane >> 4) << 4;
    const int b_r = wn * 32 + (lane & 7) + ((lane >> 4) << 3);
    const int b_c = ((lane >> 3) & 1) << 4;

    for (int kt = 0; kt < NK; ++kt) {
        if (kt + 1 < NK) { CP_WAIT(1); } else { CP_WAIT(0); }
        __syncthreads();
        if (kt + 2 < NK) {
            load_stage((kt + 2) % NSTAGE, kt + 2);
            CP_COMMIT();
        }

        const uint32_t s = sbase + (kt % NSTAGE) * STG_B;
        #pragma unroll
        for (int ks = 0; ks < 4; ++ks) {
            uint32_t ah[4][4];
            #pragma unroll
            for (int mt = 0; mt < 4; ++mt) {
                uint32_t ro = SWZ128((uint32_t)((a_r + mt * 16) * 128 + ks * 32 + a_c));
                LDM4(ah[mt], s + ro);
            }
            #pragma unroll
            for (int np = 0; np < 2; ++np) {
                uint32_t ro = SWZ128((uint32_t)((b_r + np * 16) * 128 + ks * 32 + b_c));
                uint32_t bq[4];
                LDM4(bq, s + TILE_B + ro);
                #pragma unroll
                for (int mt = 0; mt < 4; ++mt) {
                    MMA16816H(acc[mt][2 * np],     ah[mt], bq[0], bq[1]);
                    MMA16816H(acc[mt][2 * np + 1], ah[mt], bq[2], bq[3]);
                }
            }
        }
    }

    if (C16 != nullptr) {
        #pragma unroll
        for (int mt = 0; mt < 4; ++mt) {
            #pragma unroll
            for (int nt = 0; nt < 4; ++nt) {
                int row = m0 + wm * 64 + mt * 16 + (lane >> 2);
                int col = n0 + wn * 32 + nt * 8 + (lane & 3) * 2;
                __half2 h0 = __half2(__float2half_rn(acc[mt][nt][0]),
                                     __float2half_rn(acc[mt][nt][1]));
                __half2 h1 = __half2(__float2half_rn(acc[mt][nt][2]),
                                     __float2half_rn(acc[mt][nt][3]));
                *reinterpret_cast<__half2*>(&C16[(size_t)row * N + col])       = h0;
                *reinterpret_cast<__half2*>(&C16[(size_t)(row + 8) * N + col]) = h1;
            }
        }
    } else {
        #pragma unroll
        for (int mt = 0; mt < 4; ++mt) {
            #pragma unroll
            for (int nt = 0; nt < 4; ++nt) {
                int row = m0 + wm * 64 + mt * 16 + (lane >> 2);
                int col = n0 + wn * 32 + nt * 8 + (lane & 3) * 2;
                float2 v0 = make_float2(acc[mt][nt][0], acc[mt][nt][1]);
                float2 v1 = make_float2(acc[mt][nt][2], acc[mt][nt][3]);
                *reinterpret_cast<float2*>(&C[(size_t)row * N + col]) = v0;
                *reinterpret_cast<float2*>(&C[(size_t)(row + 8) * N + col]) = v1;
            }
        }
    }
}

// ---------------------------------------------------------------------------
// Attention (all single-term fp16): S = Q·K^T, O = P·V.
// K/V double-buffered; leading fully-masked chunks skipped (c0).
// smem: Q + {K,V} x 2 stages = 5 x 8 KB = 40 KB.
// ---------------------------------------------------------------------------
#define ATT_T 8192

__global__ __launch_bounds__(128, 4)
void attn_tc_kernel(const __half* __restrict__ qkv,
                    __half* __restrict__ out16) {
    extern __shared__ char smb[];
    const uint32_t sb = smem_u32(smb);
    const uint32_t sQ = sb;
    // stage s: K at sb + (1 + 2s)*ATT_T, V at +ATT_T

    const int tid  = threadIdx.x;
    const int lane = tid & 31;
    const int warp = tid >> 5;
    const int q0 = blockIdx.x * 64;
    const int h  = blockIdx.y;
    const int b  = blockIdx.z;
    const int hoff = h * DH;
    const size_t rbase = (size_t)b * T_SEQ;

    // first chunk with any in-range key: kb+63 >= 0  =>  c >= (193-q0)/64
    const int c0 = (q0 >= 193) ? 0 : ((193 - q0 + 63) >> 6);

    auto load_kv = [&](int c) {
        const int kb = q0 - WIN + c * 64;
        const uint32_t sK = sb + (1 + 2 * (c & 1)) * ATT_T;
        const uint32_t sV = sK + ATT_T;
        #pragma unroll
        for (int i = 0; i < 4; i++) {
            int cg  = tid + i * 128;
            int row = cg >> 3;
            int ck  = cg & 7;
            int kg  = kb + row;
            uint32_t sz = (kg >= 0) ? 16u : 0u;
            int kgc = kg >= 0 ? kg : 0;
            uint32_t so = SWZ128((uint32_t)(row * 128 + ck * 16));
            size_t gk = (rbase + kgc) * N_QKV + DM + hoff + ck * 8;
            CP16Z(sK + so, qkv + gk, sz);
            CP16Z(sV + so, qkv + gk + DM, sz);
        }
    };

    // ---- prologue: Q tile + first KV chunk ----
    #pragma unroll
    for (int i = 0; i < 4; i++) {
        int cg  = tid + i * 128;
        int row = cg >> 3;
        int ck  = cg & 7;
        uint32_t so = SWZ128((uint32_t)(row * 128 + ck * 16));
        size_t g = (rbase + q0 + row) * N_QKV + hoff + ck * 8;
        CP16(sQ + so, qkv + g);
    }
    CP_COMMIT();
    load_kv(c0);
    CP_COMMIT();

    float sa[8][4];
    float o[8][4];
    #pragma unroll
    for (int t = 0; t < 8; t++)
        #pragma unroll
        for (int j = 0; j < 4; j++) o[t][j] = 0.f;
    float m0 = -1e20f, m1 = -1e20f, l0 = 0.f, l1 = 0.f;

    const int lane2 = (lane & 3) * 2;
    const int qrow  = warp * 16 + (lane >> 2);
    const int qg0   = q0 + qrow;

    const int a_r = warp * 16 + (lane & 15);
    const int a_c = (lane >> 4) << 4;
    const int b_r = (lane & 7) + ((lane >> 4) << 3);
    const int b_c = ((lane >> 3) & 1) << 4;
    const int v_r = lane & 15;
    const int v_c = (lane >> 4) << 4;

    for (int c = c0; c < 5; c++) {
        const int kb = q0 - WIN + c * 64;
        CP_WAIT(0);
        __syncthreads();
        if (c + 1 < 5) {
            load_kv(c + 1);
            CP_COMMIT();
        }
        const uint32_t sKH = sb + (1 + 2 * (c & 1)) * ATT_T;
        const uint32_t sVH = sKH + ATT_T;

        // ---- S = Q K^T (single-term) ----
        #pragma unroll
        for (int t = 0; t < 8; t++)
            #pragma unroll
            for (int j = 0; j < 4; j++) sa[t][j] = 0.f;

        #pragma unroll
        for (int ks = 0; ks < 4; ks++) {
            uint32_t ah[4];
            uint32_t ao = SWZ128((uint32_t)(a_r * 128 + ks * 32 + a_c));
            LDM4(ah, sQ + ao);
            #pragma unroll
            for (int np = 0; np < 4; np++) {
                uint32_t bo = SWZ128((uint32_t)((np * 16 + b_r) * 128 + ks * 32 + b_c));
                uint32_t bk[4];
                LDM4(bk, sKH + bo);
                MMA16816H(sa[2 * np],     ah, bk[0], bk[1]);
                MMA16816H(sa[2 * np + 1], ah, bk[2], bk[3]);
            }
        }

        // ---- mask + online softmax ----
        float mx0 = -1e30f, mx1 = -1e30f;
        #pragma unroll
        for (int t = 0; t < 8; t++) {
            #pragma unroll
            for (int j = 0; j < 4; j++) {
                int col = t * 8 + lane2 + (j & 1);
                int kg  = kb + col;
                int qg  = qg0 + ((j >> 1) << 3);
                bool valid = (kg >= 0) && (kg <= qg) && (kg >= qg - WIN);
                float s = valid ? sa[t][j] * 0.125f : -1e30f;
                sa[t][j] = s;
                if (j < 2) mx0 = fmaxf(mx0, s); else mx1 = fmaxf(mx1, s);
            }
        }
        mx0 = fmaxf(mx0, __shfl_xor_sync(0xffffffffu, mx0, 1));
        mx0 = fmaxf(mx0, __shfl_xor_sync(0xffffffffu, mx0, 2));
        mx1 = fmaxf(mx1, __shfl_xor_sync(0xffffffffu, mx1, 1));
        mx1 = fmaxf(mx1, __shfl_xor_sync(0xffffffffu, mx1, 2));

        const float mn0 = fmaxf(m0, mx0);
        const float mn1 = fmaxf(m1, mx1);
        const float sc0 = __expf(m0 - mn0);
        const float sc1 = __expf(m1 - mn1);
        m0 = mn0; m1 = mn1;

        float ps0 = 0.f, ps1 = 0.f;
        #pragma unroll
        for (int t = 0; t < 8; t++) {
            float p0 = __expf(sa[t][0] - mn0);
            float p1 = __expf(sa[t][1] - mn0);
            float p2 = __expf(sa[t][2] - mn1);
            float p3 = __expf(sa[t][3] - mn1);
            sa[t][0] = p0; sa[t][1] = p1; sa[t][2] = p2; sa[t][3] = p3;
            ps0 += p0 + p1; ps1 += p2 + p3;
        }
        ps0 += __shfl_xor_sync(0xffffffffu, ps0, 1);
        ps0 += __shfl_xor_sync(0xffffffffu, ps0, 2);
        ps1 += __shfl_xor_sync(0xffffffffu, ps1, 1);
        ps1 += __shfl_xor_sync(0xffffffffu, ps1, 2);
        l0 = l0 * sc0 + ps0;
        l1 = l1 * sc1 + ps1;

        #pragma unroll
        for (int t = 0; t < 8; t++) {
            o[t][0] *= sc0; o[t][1] *= sc0;
            o[t][2] *= sc1; o[t][3] *= sc1;
        }

        // ---- O += P V (single-term) ----
        #pragma unroll
        for (int s = 0; s < 4; s++) {
            uint32_t aph[4];
            __half2 p01 = __half2(__float2half_rn(sa[2 * s][0]),     __float2half_rn(sa[2 * s][1]));
            __half2 p23 = __half2(__float2half_rn(sa[2 * s][2]),     __float2half_rn(sa[2 * s][3]));
            __half2 p45 = __half2(__float2half_rn(sa[2 * s + 1][0]), __float2half_rn(sa[2 * s + 1][1]));
            __half2 p67 = __half2(__float2half_rn(sa[2 * s + 1][2]), __float2half_rn(sa[2 * s + 1][3]));
            aph[0] = *reinterpret_cast<uint32_t*>(&p01);
            aph[1] = *reinterpret_cast<uint32_t*>(&p23);
            aph[2] = *reinterpret_cast<uint32_t*>(&p45);
            aph[3] = *reinterpret_cast<uint32_t*>(&p67);
            #pragma unroll
            for (int nd = 0; nd < 4; nd++) {
                uint32_t vo = SWZ128((uint32_t)((s * 16 + v_r) * 128 + nd * 32 + v_c));
                uint32_t vv[4];
                LDM4T(vv, sVH + vo);
                MMA16816H(o[2 * nd],     aph, vv[0], vv[1]);
                MMA16816H(o[2 * nd + 1], aph, vv[2], vv[3]);
            }
        }
    }

    // epilogue: normalize, single fp16 store
    const float il0 = 1.f / l0;
    const float il1 = 1.f / l1;
    const size_t row0 = rbase + qg0;
    #pragma unroll
    for (int t = 0; t < 8; t++) {
        int col = hoff + t * 8 + lane2;
        __half2 h0 = __half2(__float2half_rn(o[t][0] * il0), __float2half_rn(o[t][1] * il0));
        __half2 h1 = __half2(__float2half_rn(o[t][2] * il1), __float2half_rn(o[t][3] * il1));
        *reinterpret_cast<__half2*>(&out16[row0 * DM + col])       = h0;
        *reinterpret_cast<__half2*>(&out16[(row0 + 8) * DM + col]) = h1;
    }
}

// ---------------------------------------------------------------------------
extern "C" void kernel_launch(void* const* d_in, const int* in_sizes, int n_in,
                              void* d_out, int out_size) {
    const float* x     = (const float*)d_in[0];
    const float* w_qkv = (const float*)d_in[1];
    const float* w_out = (const float*)d_in[2];
    float* out = (float*)d_out;

    __half *x16, *wq16, *wo16, *at16, *qkv16;
    cudaGetSymbolAddress((void**)&x16,   g_x16);
    cudaGetSymbolAddress((void**)&wq16,  g_wqkvT16);
    cudaGetSymbolAddress((void**)&wo16,  g_woutT16);
    cudaGetSymbolAddress((void**)&qkv16, g_qkv16);
    cudaGetSymbolAddress((void**)&at16,  g_att16);

    cudaFuncSetAttribute(gemm_f16, cudaFuncAttributeMaxDynamicSharedMemorySize, GEMM_SMEM);
    const int ATTN_SMEM = 5 * ATT_T;   // 40 KB (Q + 2-stage K/V)
    cudaFuncSetAttribute(attn_tc_kernel, cudaFuncAttributeMaxDynamicSharedMemorySize, ATTN_SMEM);

    // 0) prep: x -> fp16; w_qkv, w_out -> [N][K] fp16
    {
        int n4 = M_ROWS * DM / 4;
        cvt_f16_kernel<<<(n4 + 255) / 256, 256>>>(x, x16, n4);
        dim3 g1(N_QKV / 32, DM / 32);
        transpose_f16_kernel<<<g1, 256>>>(w_qkv, wq16, DM, N_QKV);
        dim3 g2(DM / 32, DM / 32);
        transpose_f16_kernel<<<g2, 256>>>(w_out, wo16, DM, DM);
    }
    // 1) QKV projection (fp16x1) -> single fp16
    {
        dim3 grid(N_QKV / BN, M_ROWS / BM);
        gemm_f16<<<grid, 256, GEMM_SMEM>>>(x16, wq16, nullptr, qkv16,
                                           M_ROWS, N_QKV, DM);
    }
    // 2) attention (1-term S, 1-term PV, double-buffered, chunk-skipped)
    {
        dim3 grid(T_SEQ / 64, NH, B_SZ);
        attn_tc_kernel<<<grid, 128, ATTN_SMEM>>>(qkv16, at16);
    }
    // 3) output projection (fp16x1) -> fp32
    {
        dim3 grid(DM / BN, M_ROWS / BM);
        gemm_f16<<<grid, 256, GEMM_SMEM>>>(at16, wo16, out, nullptr,
                                           M_ROWS, DM, DM);
    }
}